// round 1
// baseline (speedup 1.0000x reference)
#include <cuda_runtime.h>
#include <mma.h>
#include <math.h>

using namespace nvcuda;

#define LATENT 256
#define HID    1024
#define NOUT   128
#define SEQL   96
#define NBATCH 512

#define BK 32
// pool must hold: stage (128*32 A + 128*32 B = 8192 floats) OR epilogue patches
// (8 warps * 16 * 132 = 16896 floats) OR P4 scratch (~2304 floats)
#define POOL_FLOATS (8 * 16 * 132)
#define SMEM_BYTES  (POOL_FLOATS * 4)

// ---------------- device scratch (no cudaMalloc allowed) ----------------
__device__ float g_u[NBATCH * 2 * HID];      // init projection output (512 x 2048)
__device__ float g_t[NBATCH * HID];          // p1 projection output
__device__ float g_h1[2][NBATCH * HID];      // ping-pong LSTM states
__device__ float g_c1[2][NBATCH * HID];
__device__ float g_h2[2][NBATCH * HID];
__device__ float g_c2[2][NBATCH * HID];
__device__ float g_x[NBATCH * NOUT];         // per-step input / previous y
__device__ unsigned g_cnt;
__device__ volatile unsigned g_gen;

typedef wmma::fragment<wmma::accumulator, 16, 16, 8, float> AccFrag;
typedef wmma::fragment<wmma::matrix_a, 16, 16, 8, wmma::precision::tf32, wmma::row_major> AFrag;
typedef wmma::fragment<wmma::matrix_b, 16, 16, 8, wmma::precision::tf32, wmma::col_major> BFrag;

// ---------------- grid-wide barrier (persistent kernel) ----------------
__device__ __forceinline__ void gridbar() {
    __threadfence();           // every thread flushes its own global writes
    __syncthreads();
    if (threadIdx.x == 0) {
        unsigned gen = g_gen;  // read BEFORE arriving
        if (atomicAdd(&g_cnt, 1u) == gridDim.x - 1) {
            g_cnt = 0;
            __threadfence();
            g_gen = gen + 1;
        } else {
            while (g_gen == gen) { __nanosleep(64); }
        }
    }
    __syncthreads();
}

__device__ __forceinline__ float block_sum(float v, float* red) {
    #pragma unroll
    for (int o = 16; o > 0; o >>= 1) v += __shfl_down_sync(0xffffffffu, v, o);
    int warp = threadIdx.x >> 5, lane = threadIdx.x & 31;
    if (lane == 0) red[warp] = v;
    __syncthreads();
    if (threadIdx.x < 32) {
        v = (lane < 8) ? red[lane] : 0.f;
        #pragma unroll
        for (int o = 4; o > 0; o >>= 1) v += __shfl_down_sync(0xffffffffu, v, o);
        if (lane == 0) red[0] = v;
    }
    __syncthreads();
    v = red[0];
    __syncthreads();
    return v;
}

__device__ __forceinline__ float sigm(float x) { return 1.f / (1.f + expf(-x)); }

// ---------------- block GEMM: acc += act[mbase:+128, :K] @ W^T tile ----------------
// Uses tf32x3 split (hi/lo) -> effectively fp32 precision.
// gated=1: tile columns n map to W rows (n>>5)*HID + nrow0 + (n&31)  (4 LSTM gates x 32)
// gated=0: tile columns n map to W rows nrow0 + n
template <int NFRAGS>
__device__ __forceinline__ void gemm_accum(
    AccFrag (&acc)[NFRAGS], float* pool,
    const float* __restrict__ act, int K, int mbase,
    const float* __restrict__ W, int gated, int nrow0)
{
    constexpr int BN = NFRAGS * 16;
    float* As = pool;              // [128][BK]
    float* Bs = pool + 128 * BK;   // [BN][BK]
    const int tid = threadIdx.x;
    const int warp = tid >> 5;

    for (int kb = 0; kb < K; kb += BK) {
        // stage A (mutable activations -> L2-coherent loads)
        for (int i = tid; i < 128 * (BK / 4); i += 256) {
            int r = i >> 3, kq = (i & 7) << 2;
            float4 v = __ldcg((const float4*)(act + (size_t)(mbase + r) * K + kb + kq));
            *(float4*)(As + r * BK + kq) = v;
        }
        // stage B (read-only weights)
        for (int i = tid; i < BN * (BK / 4); i += 256) {
            int n = i >> 3, kq = (i & 7) << 2;
            int row = gated ? (((n >> 5) * HID) + nrow0 + (n & 31)) : (nrow0 + n);
            float4 v = *(const float4*)(W + (size_t)row * K + kb + kq);
            *(float4*)(Bs + n * BK + kq) = v;
        }
        __syncthreads();

        #pragma unroll
        for (int kk = 0; kk < BK / 8; kk++) {
            AFrag ah, al;
            wmma::load_matrix_sync(ah, As + warp * 16 * BK + kk * 8, BK);
            #pragma unroll
            for (int i = 0; i < ah.num_elements; i++) {
                float v = ah.x[i];
                float h = wmma::__float_to_tf32(v);
                ah.x[i] = h;
                al.x[i] = wmma::__float_to_tf32(v - h);
            }
            #pragma unroll
            for (int nf = 0; nf < NFRAGS; nf++) {
                BFrag bh, bl;
                wmma::load_matrix_sync(bh, Bs + nf * 16 * BK + kk * 8, BK);
                #pragma unroll
                for (int i = 0; i < bh.num_elements; i++) {
                    float v = bh.x[i];
                    float h = wmma::__float_to_tf32(v);
                    bh.x[i] = h;
                    bl.x[i] = wmma::__float_to_tf32(v - h);
                }
                wmma::mma_sync(acc[nf], al, bh, acc[nf]);
                wmma::mma_sync(acc[nf], ah, bl, acc[nf]);
                wmma::mma_sync(acc[nf], ah, bh, acc[nf]);
            }
        }
        __syncthreads();
    }
}

// ---------------- epilogues ----------------
// fused LSTM gate epilogue: tile cols = [i(32) | f(32) | g(32) | o(32)] for hidden jbase..jbase+31
__device__ __forceinline__ void lstm_epilogue(
    AccFrag (&acc)[8], float* pool,
    const float* __restrict__ bias,
    const float* __restrict__ c_in, float* __restrict__ c_out, float* __restrict__ h_out,
    int mbase, int jbase)
{
    const int tid = threadIdx.x, warp = tid >> 5, lane = tid & 31;
    float* my = pool + warp * 16 * 132;     // per-warp [16][132] patch
    #pragma unroll
    for (int nf = 0; nf < 8; nf++)
        wmma::store_matrix_sync(my + nf * 16, acc[nf], 132, wmma::mem_row_major);
    __syncwarp();
    for (int e = lane; e < 16 * 32; e += 32) {
        int r = e >> 5, j = e & 31;
        int row = mbase + warp * 16 + r;
        int col = jbase + j;
        float iv = my[r * 132 + j]        + __ldg(bias + col);
        float fv = my[r * 132 + 32 + j]   + __ldg(bias + HID + col);
        float gv = my[r * 132 + 64 + j]   + __ldg(bias + 2 * HID + col);
        float ov = my[r * 132 + 96 + j]   + __ldg(bias + 3 * HID + col);
        float cold = __ldcg(c_in + (size_t)row * HID + col);
        float cn = sigm(fv) * cold + sigm(iv) * tanhf(gv);
        float hn = sigm(ov) * tanhf(cn);
        c_out[(size_t)row * HID + col] = cn;
        h_out[(size_t)row * HID + col] = hn;
    }
}

template <int NFRAGS>
__device__ __forceinline__ void store_epilogue_bias(
    AccFrag (&acc)[NFRAGS], float* pool, const float* __restrict__ bias,
    float* __restrict__ dst, int dstride, int mbase, int nbase)
{
    constexpr int BN = NFRAGS * 16, PS = BN + 4;
    const int tid = threadIdx.x, warp = tid >> 5, lane = tid & 31;
    float* my = pool + warp * 16 * PS;
    #pragma unroll
    for (int nf = 0; nf < NFRAGS; nf++)
        wmma::store_matrix_sync(my + nf * 16, acc[nf], PS, wmma::mem_row_major);
    __syncwarp();
    for (int e = lane; e < 16 * BN; e += 32) {
        int r = e / BN, cc = e % BN;
        int row = mbase + warp * 16 + r;
        dst[(size_t)row * dstride + nbase + cc] = my[r * PS + cc] + __ldg(bias + nbase + cc);
    }
}

// ---------------- the persistent decoder kernel ----------------
__global__ void __launch_bounds__(256, 1) dec_kernel(
    const float* __restrict__ z,     const float* __restrict__ lin1_w, const float* __restrict__ lin1_b,
    const float* __restrict__ ln1_w, const float* __restrict__ ln1_b,
    const float* __restrict__ w_ih0, const float* __restrict__ w_hh0,  const float* __restrict__ b0,
    const float* __restrict__ w_ih1, const float* __restrict__ w_hh1,  const float* __restrict__ b1,
    const float* __restrict__ p1_w,  const float* __restrict__ p1_b,
    const float* __restrict__ pln_w, const float* __restrict__ pln_b,
    const float* __restrict__ p2_w,  const float* __restrict__ p2_b,
    float* __restrict__ out)
{
    extern __shared__ float pool[];
    __shared__ float redA[8], redB[8];
    const int bid = blockIdx.x, nb = gridDim.x, tid = threadIdx.x;

    // ---- S1: u = z @ lin1_w^T + lin1_b   (512 x 2048, K=256)
    for (int t = bid; t < 64; t += nb) {
        int mbase = (t >> 4) << 7;
        int nbase = (t & 15) << 7;
        AccFrag acc[8];
        #pragma unroll
        for (int i = 0; i < 8; i++) wmma::fill_fragment(acc[i], 0.f);
        gemm_accum<8>(acc, pool, z, LATENT, mbase, lin1_w, 0, nbase);
        store_epilogue_bias<8>(acc, pool, lin1_b, g_u, 2 * HID, mbase, nbase);
        __syncthreads();
    }
    gridbar();

    // ---- S2: LayerNorm(2048) + gelu, split into h0/c0 (both cells); zero x
    for (int grp = bid; grp < 128; grp += nb) {
        for (int rr = 0; rr < 4; rr++) {
            int row = (grp << 2) + rr;
            float ls = 0.f, lq = 0.f;
            for (int i = tid; i < 2 * HID; i += 256) {
                float v = __ldcg(g_u + (size_t)row * 2 * HID + i);
                pool[i] = v; ls += v; lq += v * v;
            }
            __syncthreads();
            float S = block_sum(ls, redA);
            float Q = block_sum(lq, redB);
            float mu = S * (1.f / 2048.f);
            float rstd = rsqrtf(Q * (1.f / 2048.f) - mu * mu + 1e-5f);
            for (int i = tid; i < 2 * HID; i += 256) {
                float v = (pool[i] - mu) * rstd * __ldg(ln1_w + i) + __ldg(ln1_b + i);
                float ge = v * normcdff(v);
                if (i < HID) {
                    g_h1[0][(size_t)row * HID + i] = ge;
                    g_h2[0][(size_t)row * HID + i] = ge;
                } else {
                    g_c1[0][(size_t)row * HID + i - HID] = ge;
                    g_c2[0][(size_t)row * HID + i - HID] = ge;
                }
            }
            __syncthreads();
        }
        for (int i = tid; i < 4 * NOUT; i += 256) g_x[(size_t)(grp << 2) * NOUT + i] = 0.f;
    }
    gridbar();

    // ---- main sequential loop
    for (int s = 0; s < SEQL; s++) {
        const int pi = s & 1, po = pi ^ 1;

        // P1: (h1,c1) = lstm0(x, h1, c1)   fused gates (4x32 cols gathered) + activations
        for (int t = bid; t < 128; t += nb) {
            int mbase = (t >> 5) << 7;
            int jbase = (t & 31) << 5;
            AccFrag acc[8];
            #pragma unroll
            for (int i = 0; i < 8; i++) wmma::fill_fragment(acc[i], 0.f);
            gemm_accum<8>(acc, pool, g_x, NOUT, mbase, w_ih0, 1, jbase);
            gemm_accum<8>(acc, pool, g_h1[pi], HID, mbase, w_hh0, 1, jbase);
            lstm_epilogue(acc, pool, b0, g_c1[pi], g_c1[po], g_h1[po], mbase, jbase);
            __syncthreads();
        }
        gridbar();

        // P2: (h2,c2) = lstm1(h1_new, h2, c2)
        for (int t = bid; t < 128; t += nb) {
            int mbase = (t >> 5) << 7;
            int jbase = (t & 31) << 5;
            AccFrag acc[8];
            #pragma unroll
            for (int i = 0; i < 8; i++) wmma::fill_fragment(acc[i], 0.f);
            gemm_accum<8>(acc, pool, g_h1[po], HID, mbase, w_ih1, 1, jbase);
            gemm_accum<8>(acc, pool, g_h2[pi], HID, mbase, w_hh1, 1, jbase);
            lstm_epilogue(acc, pool, b1, g_c2[pi], g_c2[po], g_h2[po], mbase, jbase);
            __syncthreads();
        }
        gridbar();

        // P3: t = h2_new @ p1_w^T + p1_b   (512 x 1024, tiles 128x64 for balance)
        for (int t = bid; t < 64; t += nb) {
            int mbase = (t >> 4) << 7;
            int nbase = (t & 15) << 6;
            AccFrag acc[4];
            #pragma unroll
            for (int i = 0; i < 4; i++) wmma::fill_fragment(acc[i], 0.f);
            gemm_accum<4>(acc, pool, g_h2[po], HID, mbase, p1_w, 0, nbase);
            store_epilogue_bias<4>(acc, pool, p1_b, g_t, HID, mbase, nbase);
            __syncthreads();
        }
        gridbar();

        // P4: per-row LayerNorm + gelu + y = g @ p2_w^T + p2_b ; y -> out and next x
        for (int grp = bid; grp < 128; grp += nb) {
            for (int rr = 0; rr < 4; rr++) {
                int row = (grp << 2) + rr;
                float ls = 0.f, lq = 0.f;
                for (int i = tid; i < HID; i += 256) {
                    float v = __ldcg(g_t + (size_t)row * HID + i);
                    pool[i] = v; ls += v; lq += v * v;
                }
                __syncthreads();
                float S = block_sum(ls, redA);
                float Q = block_sum(lq, redB);
                float mu = S * (1.f / 1024.f);
                float rstd = rsqrtf(Q * (1.f / 1024.f) - mu * mu + 1e-5f);
                for (int i = tid; i < HID; i += 256) {
                    float v = (pool[i] - mu) * rstd * __ldg(pln_w + i) + __ldg(pln_b + i);
                    pool[HID + i] = v * normcdff(v);
                }
                __syncthreads();
                // y GEMM: 2 threads per output column, 512-long partial dots
                int o = tid & 127, half = tid >> 7;
                const float* wrow = p2_w + (size_t)o * HID + half * 512;
                const float* gv = pool + HID + half * 512;
                float a = 0.f;
                #pragma unroll 4
                for (int k = 0; k < 512; k += 4) {
                    float4 w4 = *(const float4*)(wrow + k);
                    float4 g4 = *(const float4*)(gv + k);
                    a += g4.x * w4.x + g4.y * w4.y + g4.z * w4.z + g4.w * w4.w;
                }
                pool[2 * HID + tid] = a;
                __syncthreads();
                if (half == 0) {
                    float y = pool[2 * HID + o] + pool[2 * HID + 128 + o] + __ldg(p2_b + o);
                    g_x[(size_t)row * NOUT + o] = y;
                    out[(size_t)row * SEQL * NOUT + s * NOUT + o] = y;
                }
                __syncthreads();
            }
        }
        gridbar();
    }
}

// ---------------- launch ----------------
extern "C" void kernel_launch(void* const* d_in, const int* in_sizes, int n_in,
                              void* d_out, int out_size) {
    (void)in_sizes; (void)n_in; (void)out_size;
    int nsm = 0;
    cudaDeviceGetAttribute(&nsm, cudaDevAttrMultiProcessorCount, 0);
    if (nsm <= 0) nsm = 148;
    cudaFuncSetAttribute(dec_kernel, cudaFuncAttributeMaxDynamicSharedMemorySize, SMEM_BYTES);

    const float* z      = (const float*)d_in[0];
    const float* lin1_w = (const float*)d_in[1];
    const float* lin1_b = (const float*)d_in[2];
    const float* ln1_w  = (const float*)d_in[3];
    const float* ln1_b  = (const float*)d_in[4];
    const float* w_ih0  = (const float*)d_in[5];
    const float* w_hh0  = (const float*)d_in[6];
    const float* b0     = (const float*)d_in[7];
    const float* w_ih1  = (const float*)d_in[8];
    const float* w_hh1  = (const float*)d_in[9];
    const float* b1     = (const float*)d_in[10];
    const float* p1_w   = (const float*)d_in[11];
    const float* p1_b   = (const float*)d_in[12];
    const float* pln_w  = (const float*)d_in[13];
    const float* pln_b  = (const float*)d_in[14];
    const float* p2_w   = (const float*)d_in[15];
    const float* p2_b   = (const float*)d_in[16];

    dec_kernel<<<nsm, 256, SMEM_BYTES>>>(
        z, lin1_w, lin1_b, ln1_w, ln1_b,
        w_ih0, w_hh0, b0, w_ih1, w_hh1, b1,
        p1_w, p1_b, pln_w, pln_b, p2_w, p2_b,
        (float*)d_out);
}

// round 2
// speedup vs baseline: 2.5377x; 2.5377x over previous
#include <cuda_runtime.h>
#include <cuda_bf16.h>
#include <mma.h>
#include <math.h>

using namespace nvcuda;
using bf16 = __nv_bfloat16;

#define LATENT 256
#define HID    1024
#define NOUT   128
#define SEQL   96
#define NBATCH 512

#define LDA 72                      // padded smem leading dim (bf16 elems)
#define SMEM_BYTES (512 * LDA * 2)  // 4 planes x (128 or BN) rows x LDA bf16 = 73728

// ---------------- device scratch (no cudaMalloc allowed) ----------------
// weight / input bf16 hi-lo planes (written once in S0)
__device__ bf16 g_lin1_hi[2048 * 256],  g_lin1_lo[2048 * 256];
__device__ bf16 g_wih0_hi[4096 * 128],  g_wih0_lo[4096 * 128];
__device__ bf16 g_whh0_hi[4096 * 1024], g_whh0_lo[4096 * 1024];
__device__ bf16 g_wih1_hi[4096 * 1024], g_wih1_lo[4096 * 1024];
__device__ bf16 g_whh1_hi[4096 * 1024], g_whh1_lo[4096 * 1024];
__device__ bf16 g_p1_hi[1024 * 1024],   g_p1_lo[1024 * 1024];
__device__ bf16 g_z_hi[512 * 256],      g_z_lo[512 * 256];
// activations
__device__ bf16  g_h1h[2][NBATCH * HID], g_h1l[2][NBATCH * HID];
__device__ bf16  g_h2h[2][NBATCH * HID], g_h2l[2][NBATCH * HID];
__device__ float g_c1[2][NBATCH * HID];
__device__ float g_c2[2][NBATCH * HID];
__device__ bf16  g_xh[NBATCH * NOUT],    g_xl[NBATCH * NOUT];
__device__ float g_u[NBATCH * 2 * HID];
__device__ float g_t[NBATCH * HID];
// barrier state
__device__ volatile unsigned g_arrive[256];
__device__ volatile unsigned g_release;

typedef wmma::fragment<wmma::accumulator, 16, 16, 16, float> CFrag;
typedef wmma::fragment<wmma::matrix_a, 16, 16, 16, bf16, wmma::row_major> AFrag;
typedef wmma::fragment<wmma::matrix_b, 16, 16, 16, bf16, wmma::col_major> BFrag;

// ---------------- grid barrier: distributed flags ----------------
__device__ __forceinline__ void gridbar(unsigned& epoch) {
    epoch++;
    __threadfence();
    __syncthreads();
    if (blockIdx.x == 0) {
        if (threadIdx.x == 0) g_arrive[0] = epoch;
        for (int b = threadIdx.x; b < (int)gridDim.x; b += blockDim.x) {
            while (g_arrive[b] < epoch) { __nanosleep(32); }
        }
        __syncthreads();
        if (threadIdx.x == 0) { __threadfence(); g_release = epoch; }
    } else {
        if (threadIdx.x == 0) {
            g_arrive[blockIdx.x] = epoch;
            while (g_release < epoch) { __nanosleep(32); }
        }
    }
    __syncthreads();
}

__device__ __forceinline__ float block_sum(float v, float* red) {
    #pragma unroll
    for (int o = 16; o > 0; o >>= 1) v += __shfl_down_sync(0xffffffffu, v, o);
    int warp = threadIdx.x >> 5, lane = threadIdx.x & 31;
    if (lane == 0) red[warp] = v;
    __syncthreads();
    if (threadIdx.x < 32) {
        v = (lane < 8) ? red[lane] : 0.f;
        #pragma unroll
        for (int o = 4; o > 0; o >>= 1) v += __shfl_down_sync(0xffffffffu, v, o);
        if (lane == 0) red[0] = v;
    }
    __syncthreads();
    v = red[0];
    __syncthreads();
    return v;
}

__device__ __forceinline__ float sigm(float x) { return 1.f / (1.f + expf(-x)); }

__device__ __forceinline__ void split1(float v, bf16& h, bf16& l) {
    h = __float2bfloat16_rn(v);
    l = __float2bfloat16_rn(v - __bfloat162float(h));
}

// S0 helper: split a fp32 array into bf16 hi/lo planes (vectorized)
__device__ __forceinline__ void split_arr(const float* __restrict__ src,
                                          bf16* __restrict__ hi, bf16* __restrict__ lo,
                                          int n, int gt, int gs) {
    for (int i = gt; i < (n >> 2); i += gs) {
        float4 v = *(const float4*)(src + 4 * i);
        bf16 h[4], l[4];
        split1(v.x, h[0], l[0]); split1(v.y, h[1], l[1]);
        split1(v.z, h[2], l[2]); split1(v.w, h[3], l[3]);
        *(uint2*)(hi + 4 * i) = *(uint2*)h;
        *(uint2*)(lo + 4 * i) = *(uint2*)l;
    }
}

// ---------------- block GEMM: acc += A[mbase:+128, :K] @ W^T tile (bf16 hi/lo x3) ----------------
// NF: 16-col fragments per warp (warp tile 32 x 16*NF; block tile 128 x 32*NF)
// GATED: tile col n maps to W row (n>>5)*HID + nrow0 + (n&31), else nrow0 + n
template <int NF, bool GATED>
__device__ __forceinline__ void gemm_bf16(
    CFrag (&acc)[2][NF], char* pool,
    const bf16* __restrict__ Ahi, const bf16* __restrict__ Alo, int K, int mbase,
    const bf16* __restrict__ Whi, const bf16* __restrict__ Wlo, int nrow0)
{
    constexpr int BN = 32 * NF;
    bf16* sAh = (bf16*)pool;
    bf16* sAl = sAh + 128 * LDA;
    bf16* sBh = sAl + 128 * LDA;
    bf16* sBl = sBh + BN * LDA;
    const int tid = threadIdx.x;
    const int warp = tid >> 5;
    const int wm = warp >> 1, wn = warp & 1;

    for (int kb = 0; kb < K; kb += 64) {
        // stage A (mutable activations -> L2 loads)
        for (int i = tid; i < 128 * 8; i += 256) {
            int r = i >> 3, q = (i & 7) << 3;
            size_t off = (size_t)(mbase + r) * K + kb + q;
            *(uint4*)(sAh + r * LDA + q) = __ldcg((const uint4*)(Ahi + off));
            *(uint4*)(sAl + r * LDA + q) = __ldcg((const uint4*)(Alo + off));
        }
        // stage B (weight planes, L1-cacheable)
        for (int i = tid; i < BN * 8; i += 256) {
            int n = i >> 3, q = (i & 7) << 3;
            int row = GATED ? (((n >> 5) * HID) + nrow0 + (n & 31)) : (nrow0 + n);
            size_t off = (size_t)row * K + kb + q;
            *(uint4*)(sBh + n * LDA + q) = *(const uint4*)(Whi + off);
            *(uint4*)(sBl + n * LDA + q) = *(const uint4*)(Wlo + off);
        }
        __syncthreads();

        #pragma unroll
        for (int kk = 0; kk < 4; kk++) {
            AFrag ah0, ah1, al0, al1;
            wmma::load_matrix_sync(ah0, sAh + (wm * 32 + 0)  * LDA + kk * 16, LDA);
            wmma::load_matrix_sync(ah1, sAh + (wm * 32 + 16) * LDA + kk * 16, LDA);
            wmma::load_matrix_sync(al0, sAl + (wm * 32 + 0)  * LDA + kk * 16, LDA);
            wmma::load_matrix_sync(al1, sAl + (wm * 32 + 16) * LDA + kk * 16, LDA);
            #pragma unroll
            for (int nf = 0; nf < NF; nf++) {
                BFrag bh, bl;
                int cb = wn * (16 * NF) + nf * 16;
                wmma::load_matrix_sync(bh, sBh + cb * LDA + kk * 16, LDA);
                wmma::load_matrix_sync(bl, sBl + cb * LDA + kk * 16, LDA);
                wmma::mma_sync(acc[0][nf], ah0, bl, acc[0][nf]);
                wmma::mma_sync(acc[1][nf], ah1, bl, acc[1][nf]);
                wmma::mma_sync(acc[0][nf], al0, bh, acc[0][nf]);
                wmma::mma_sync(acc[1][nf], al1, bh, acc[1][nf]);
                wmma::mma_sync(acc[0][nf], ah0, bh, acc[0][nf]);
                wmma::mma_sync(acc[1][nf], ah1, bh, acc[1][nf]);
            }
        }
        __syncthreads();
    }
}

// ---------------- epilogues ----------------
__device__ __forceinline__ void lstm_epilogue(
    CFrag (&acc)[2][4], char* pool,
    const float* __restrict__ bias,
    const float* __restrict__ c_in, float* __restrict__ c_out,
    bf16* __restrict__ h_hi, bf16* __restrict__ h_lo,
    int mbase, int jbase)
{
    float* pf = (float*)pool;                 // patch [128][132]
    const int tid = threadIdx.x, warp = tid >> 5;
    const int wm = warp >> 1, wn = warp & 1;
    #pragma unroll
    for (int i = 0; i < 2; i++)
        #pragma unroll
        for (int nf = 0; nf < 4; nf++)
            wmma::store_matrix_sync(pf + (wm * 32 + i * 16) * 132 + wn * 64 + nf * 16,
                                    acc[i][nf], 132, wmma::mem_row_major);
    __syncthreads();
    for (int e = tid; e < 128 * 32; e += 256) {
        int r = e >> 5, j = e & 31;
        int row = mbase + r, col = jbase + j;
        float iv = pf[r * 132 + j]      + __ldg(bias + col);
        float fv = pf[r * 132 + 32 + j] + __ldg(bias + HID + col);
        float gv = pf[r * 132 + 64 + j] + __ldg(bias + 2 * HID + col);
        float ov = pf[r * 132 + 96 + j] + __ldg(bias + 3 * HID + col);
        float cold = __ldcg(c_in + (size_t)row * HID + col);
        float cn = sigm(fv) * cold + sigm(iv) * tanhf(gv);
        float hn = sigm(ov) * tanhf(cn);
        c_out[(size_t)row * HID + col] = cn;
        bf16 hh, hl; split1(hn, hh, hl);
        h_hi[(size_t)row * HID + col] = hh;
        h_lo[(size_t)row * HID + col] = hl;
    }
    __syncthreads();
}

template <int NF>
__device__ __forceinline__ void store_epilogue_bias(
    CFrag (&acc)[2][NF], char* pool, const float* __restrict__ bias,
    float* __restrict__ dst, int dstride, int mbase, int nbase)
{
    constexpr int BN = 32 * NF, PS = BN + 4;
    float* pf = (float*)pool;
    const int tid = threadIdx.x, warp = tid >> 5;
    const int wm = warp >> 1, wn = warp & 1;
    #pragma unroll
    for (int i = 0; i < 2; i++)
        #pragma unroll
        for (int nf = 0; nf < NF; nf++)
            wmma::store_matrix_sync(pf + (wm * 32 + i * 16) * PS + wn * (16 * NF) + nf * 16,
                                    acc[i][nf], PS, wmma::mem_row_major);
    __syncthreads();
    for (int e = tid; e < 128 * BN; e += 256) {
        int r = e / BN, c = e % BN;
        dst[(size_t)(mbase + r) * dstride + nbase + c] = pf[r * PS + c] + __ldg(bias + nbase + c);
    }
    __syncthreads();
}

// ---------------- the persistent decoder kernel ----------------
__global__ void __launch_bounds__(256, 1) dec_kernel(
    const float* __restrict__ z,     const float* __restrict__ lin1_w, const float* __restrict__ lin1_b,
    const float* __restrict__ ln1_w, const float* __restrict__ ln1_b,
    const float* __restrict__ w_ih0, const float* __restrict__ w_hh0,  const float* __restrict__ b0,
    const float* __restrict__ w_ih1, const float* __restrict__ w_hh1,  const float* __restrict__ b1,
    const float* __restrict__ p1_w,  const float* __restrict__ p1_b,
    const float* __restrict__ pln_w, const float* __restrict__ pln_b,
    const float* __restrict__ p2_w,  const float* __restrict__ p2_b,
    float* __restrict__ out)
{
    extern __shared__ char pool[];
    __shared__ float redA[8], redB[8];
    const int bid = blockIdx.x, nb = gridDim.x, tid = threadIdx.x;
    unsigned epoch = g_release;   // continue epoch across graph replays

    // ---- S0: split weights + z into bf16 hi/lo planes
    {
        int gt = bid * 256 + tid, gs = nb * 256;
        split_arr(lin1_w, g_lin1_hi, g_lin1_lo, 2048 * 256, gt, gs);
        split_arr(w_ih0,  g_wih0_hi, g_wih0_lo, 4096 * 128, gt, gs);
        split_arr(w_hh0,  g_whh0_hi, g_whh0_lo, 4096 * 1024, gt, gs);
        split_arr(w_ih1,  g_wih1_hi, g_wih1_lo, 4096 * 1024, gt, gs);
        split_arr(w_hh1,  g_whh1_hi, g_whh1_lo, 4096 * 1024, gt, gs);
        split_arr(p1_w,   g_p1_hi,   g_p1_lo,   1024 * 1024, gt, gs);
        split_arr(z,      g_z_hi,    g_z_lo,    512 * 256,   gt, gs);
    }
    gridbar(epoch);

    // ---- S1: u = z @ lin1_w^T + lin1_b   (512 x 2048, K=256)
    for (int t = bid; t < 64; t += nb) {
        int mbase = (t >> 4) << 7;
        int nbase = (t & 15) << 7;
        CFrag acc[2][4];
        #pragma unroll
        for (int i = 0; i < 2; i++)
            #pragma unroll
            for (int j = 0; j < 4; j++) wmma::fill_fragment(acc[i][j], 0.f);
        gemm_bf16<4, false>(acc, pool, g_z_hi, g_z_lo, LATENT, mbase, g_lin1_hi, g_lin1_lo, nbase);
        store_epilogue_bias<4>(acc, pool, lin1_b, g_u, 2 * HID, mbase, nbase);
    }
    gridbar(epoch);

    // ---- S2: LayerNorm(2048) + gelu -> h0/c0 (both cells); zero x
    {
        float* pf = (float*)pool;
        for (int grp = bid; grp < 128; grp += nb) {
            for (int rr = 0; rr < 4; rr++) {
                int row = (grp << 2) + rr;
                float ls = 0.f, lq = 0.f;
                for (int i = tid; i < 2 * HID; i += 256) {
                    float v = __ldcg(g_u + (size_t)row * 2 * HID + i);
                    pf[i] = v; ls += v; lq += v * v;
                }
                __syncthreads();
                float S = block_sum(ls, redA);
                float Q = block_sum(lq, redB);
                float mu = S * (1.f / 2048.f);
                float rstd = rsqrtf(Q * (1.f / 2048.f) - mu * mu + 1e-5f);
                for (int i = tid; i < 2 * HID; i += 256) {
                    float v = (pf[i] - mu) * rstd * __ldg(ln1_w + i) + __ldg(ln1_b + i);
                    float ge = v * normcdff(v);
                    if (i < HID) {
                        bf16 hh, hl; split1(ge, hh, hl);
                        g_h1h[0][(size_t)row * HID + i] = hh;
                        g_h1l[0][(size_t)row * HID + i] = hl;
                        g_h2h[0][(size_t)row * HID + i] = hh;
                        g_h2l[0][(size_t)row * HID + i] = hl;
                    } else {
                        g_c1[0][(size_t)row * HID + i - HID] = ge;
                        g_c2[0][(size_t)row * HID + i - HID] = ge;
                    }
                }
                __syncthreads();
            }
            for (int i = tid; i < 4 * NOUT; i += 256) {
                g_xh[(size_t)(grp << 2) * NOUT + i] = __float2bfloat16_rn(0.f);
                g_xl[(size_t)(grp << 2) * NOUT + i] = __float2bfloat16_rn(0.f);
            }
        }
    }
    gridbar(epoch);

    // ---- main sequential loop
    for (int s = 0; s < SEQL; s++) {
        const int pi = s & 1, po = pi ^ 1;

        // P1: (h1,c1) = lstm0(x, h1, c1)
        for (int t = bid; t < 128; t += nb) {
            int mbase = (t >> 5) << 7;
            int jbase = (t & 31) << 5;
            CFrag acc[2][4];
            #pragma unroll
            for (int i = 0; i < 2; i++)
                #pragma unroll
                for (int j = 0; j < 4; j++) wmma::fill_fragment(acc[i][j], 0.f);
            gemm_bf16<4, true>(acc, pool, g_xh, g_xl, NOUT, mbase, g_wih0_hi, g_wih0_lo, jbase);
            gemm_bf16<4, true>(acc, pool, g_h1h[pi], g_h1l[pi], HID, mbase, g_whh0_hi, g_whh0_lo, jbase);
            lstm_epilogue(acc, pool, b0, g_c1[pi], g_c1[po], g_h1h[po], g_h1l[po], mbase, jbase);
        }
        gridbar(epoch);

        // P2: (h2,c2) = lstm1(h1_new, h2, c2)
        for (int t = bid; t < 128; t += nb) {
            int mbase = (t >> 5) << 7;
            int jbase = (t & 31) << 5;
            CFrag acc[2][4];
            #pragma unroll
            for (int i = 0; i < 2; i++)
                #pragma unroll
                for (int j = 0; j < 4; j++) wmma::fill_fragment(acc[i][j], 0.f);
            gemm_bf16<4, true>(acc, pool, g_h1h[po], g_h1l[po], HID, mbase, g_wih1_hi, g_wih1_lo, jbase);
            gemm_bf16<4, true>(acc, pool, g_h2h[pi], g_h2l[pi], HID, mbase, g_whh1_hi, g_whh1_lo, jbase);
            lstm_epilogue(acc, pool, b1, g_c2[pi], g_c2[po], g_h2h[po], g_h2l[po], mbase, jbase);
        }
        gridbar(epoch);

        // P3: t = h2_new @ p1_w^T + p1_b   (512 x 1024, 128x64 tiles -> 64 tiles)
        for (int t = bid; t < 64; t += nb) {
            int mbase = (t >> 4) << 7;
            int nbase = (t & 15) << 6;
            CFrag acc[2][2];
            #pragma unroll
            for (int i = 0; i < 2; i++)
                #pragma unroll
                for (int j = 0; j < 2; j++) wmma::fill_fragment(acc[i][j], 0.f);
            gemm_bf16<2, false>(acc, pool, g_h2h[po], g_h2l[po], HID, mbase, g_p1_hi, g_p1_lo, nbase);
            store_epilogue_bias<2>(acc, pool, p1_b, g_t, HID, mbase, nbase);
        }
        gridbar(epoch);

        // P4: per-row LayerNorm + gelu + y = g @ p2_w^T + p2_b ; y -> out and next x
        {
            float* pf = (float*)pool;
            for (int grp = bid; grp < 128; grp += nb) {
                for (int rr = 0; rr < 4; rr++) {
                    int row = (grp << 2) + rr;
                    float ls = 0.f, lq = 0.f;
                    for (int i = tid; i < HID; i += 256) {
                        float v = __ldcg(g_t + (size_t)row * HID + i);
                        pf[i] = v; ls += v; lq += v * v;
                    }
                    __syncthreads();
                    float S = block_sum(ls, redA);
                    float Q = block_sum(lq, redB);
                    float mu = S * (1.f / 1024.f);
                    float rstd = rsqrtf(Q * (1.f / 1024.f) - mu * mu + 1e-5f);
                    for (int i = tid; i < HID; i += 256) {
                        float v = (pf[i] - mu) * rstd * __ldg(pln_w + i) + __ldg(pln_b + i);
                        pf[HID + i] = v * normcdff(v);
                    }
                    __syncthreads();
                    int o = tid & 127, half = tid >> 7;
                    const float* wrow = p2_w + (size_t)o * HID + half * 512;
                    const float* gv = pf + HID + half * 512;
                    float a = 0.f;
                    #pragma unroll 4
                    for (int k = 0; k < 512; k += 4) {
                        float4 w4 = *(const float4*)(wrow + k);
                        float4 g4 = *(const float4*)(gv + k);
                        a += g4.x * w4.x + g4.y * w4.y + g4.z * w4.z + g4.w * w4.w;
                    }
                    pf[2 * HID + tid] = a;
                    __syncthreads();
                    if (half == 0) {
                        float y = pf[2 * HID + o] + pf[2 * HID + 128 + o] + __ldg(p2_b + o);
                        bf16 xh, xl; split1(y, xh, xl);
                        g_xh[(size_t)row * NOUT + o] = xh;
                        g_xl[(size_t)row * NOUT + o] = xl;
                        out[(size_t)row * SEQL * NOUT + s * NOUT + o] = y;
                    }
                    __syncthreads();
                }
            }
        }
        gridbar(epoch);
    }
}

// ---------------- launch ----------------
extern "C" void kernel_launch(void* const* d_in, const int* in_sizes, int n_in,
                              void* d_out, int out_size) {
    (void)in_sizes; (void)n_in; (void)out_size;
    int nsm = 0;
    cudaDeviceGetAttribute(&nsm, cudaDevAttrMultiProcessorCount, 0);
    if (nsm <= 0) nsm = 148;
    if (nsm > 256) nsm = 256;
    cudaFuncSetAttribute(dec_kernel, cudaFuncAttributeMaxDynamicSharedMemorySize, SMEM_BYTES);

    const float* z      = (const float*)d_in[0];
    const float* lin1_w = (const float*)d_in[1];
    const float* lin1_b = (const float*)d_in[2];
    const float* ln1_w  = (const float*)d_in[3];
    const float* ln1_b  = (const float*)d_in[4];
    const float* w_ih0  = (const float*)d_in[5];
    const float* w_hh0  = (const float*)d_in[6];
    const float* b0     = (const float*)d_in[7];
    const float* w_ih1  = (const float*)d_in[8];
    const float* w_hh1  = (const float*)d_in[9];
    const float* b1     = (const float*)d_in[10];
    const float* p1_w   = (const float*)d_in[11];
    const float* p1_b   = (const float*)d_in[12];
    const float* pln_w  = (const float*)d_in[13];
    const float* pln_b  = (const float*)d_in[14];
    const float* p2_w   = (const float*)d_in[15];
    const float* p2_b   = (const float*)d_in[16];

    dec_kernel<<<nsm, 256, SMEM_BYTES>>>(
        z, lin1_w, lin1_b, ln1_w, ln1_b,
        w_ih0, w_hh0, b0, w_ih1, w_hh1, b1,
        p1_w, p1_b, pln_w, pln_b, p2_w, p2_b,
        (float*)d_out);
}

// round 4
// speedup vs baseline: 4.2402x; 1.6709x over previous
#include <cuda_runtime.h>
#include <cuda_bf16.h>
#include <mma.h>
#include <math.h>
#include <stdint.h>

using namespace nvcuda;
using bf16 = __nv_bfloat16;

#define LATENT 256
#define HID    1024
#define NOUT   128
#define SEQL   96
#define NBATCH 512

#define NTHREADS 512
#define LDA 72                       // padded smem leading dim (bf16 elems) = 144 bytes/row

// stage buffer: A hi/lo (128 x 72 x 2B x 2) + B hi/lo (128 x 72 x 2B x 2) = 73728 B
#define ASZ   (128 * 144)
#define BSZمم 0
#define STG_MAX (2 * ASZ + 2 * (128 * 144))
#define SMEM_BYTES (1024 + 2 * STG_MAX)

// ---------------- device scratch (no cudaMalloc allowed) ----------------
__device__ bf16 g_lin1_hi[2048 * 256],  g_lin1_lo[2048 * 256];
__device__ bf16 g_wih0_hi[4096 * 128],  g_wih0_lo[4096 * 128];
__device__ bf16 g_whh0_hi[4096 * 1024], g_whh0_lo[4096 * 1024];
__device__ bf16 g_wih1_hi[4096 * 1024], g_wih1_lo[4096 * 1024];
__device__ bf16 g_whh1_hi[4096 * 1024], g_whh1_lo[4096 * 1024];
__device__ bf16 g_p1_hi[1024 * 1024],   g_p1_lo[1024 * 1024];
__device__ bf16 g_z_hi[512 * 256],      g_z_lo[512 * 256];
__device__ bf16  g_h1h[2][NBATCH * HID], g_h1l[2][NBATCH * HID];
__device__ bf16  g_h2h[2][NBATCH * HID], g_h2l[2][NBATCH * HID];
__device__ float g_c1[2][NBATCH * HID];
__device__ float g_c2[2][NBATCH * HID];
__device__ bf16  g_xh[NBATCH * NOUT],    g_xl[NBATCH * NOUT];
__device__ float g_u[NBATCH * 2 * HID];
__device__ float g_t[NBATCH * HID];
__device__ volatile unsigned g_arrive[256];
__device__ volatile unsigned g_release;

typedef wmma::fragment<wmma::accumulator, 16, 16, 16, float> CFrag;
typedef wmma::fragment<wmma::matrix_a, 16, 16, 16, bf16, wmma::row_major> AFrag;
typedef wmma::fragment<wmma::matrix_b, 16, 16, 16, bf16, wmma::col_major> BFrag;

// ---------------- cp.async helpers ----------------
__device__ __forceinline__ uint32_t smem_u32(const void* p) {
    uint32_t a;
    asm("{ .reg .u64 t; cvta.to.shared.u64 t, %1; cvt.u32.u64 %0, t; }" : "=r"(a) : "l"(p));
    return a;
}
#define CP_CG(dst, src) \
    asm volatile("cp.async.cg.shared.global [%0], [%1], 16;" :: "r"(dst), "l"(src) : "memory")
#define CP_CA(dst, src) \
    asm volatile("cp.async.ca.shared.global [%0], [%1], 16;" :: "r"(dst), "l"(src) : "memory")
#define CP_COMMIT() asm volatile("cp.async.commit_group;" ::: "memory")
#define CP_WAIT1()  asm volatile("cp.async.wait_group 1;" ::: "memory")
#define CP_WAIT0()  asm volatile("cp.async.wait_group 0;" ::: "memory")

// ---------------- grid barrier ----------------
__device__ __forceinline__ void gridbar(unsigned& epoch) {
    epoch++;
    __threadfence();
    __syncthreads();
    if (blockIdx.x == 0) {
        if (threadIdx.x == 0) g_arrive[0] = epoch;
        for (int b = threadIdx.x; b < (int)gridDim.x; b += blockDim.x) {
            while (g_arrive[b] < epoch) { __nanosleep(32); }
        }
        __syncthreads();
        if (threadIdx.x == 0) { __threadfence(); g_release = epoch; }
    } else {
        if (threadIdx.x == 0) {
            g_arrive[blockIdx.x] = epoch;
            while (g_release < epoch) { __nanosleep(32); }
        }
    }
    __syncthreads();
}

__device__ __forceinline__ float block_sum(float v, float* red) {
    #pragma unroll
    for (int o = 16; o > 0; o >>= 1) v += __shfl_down_sync(0xffffffffu, v, o);
    int warp = threadIdx.x >> 5, lane = threadIdx.x & 31;
    if (lane == 0) red[warp] = v;
    __syncthreads();
    if (threadIdx.x < 32) {
        v = (lane < 16) ? red[lane] : 0.f;
        #pragma unroll
        for (int o = 8; o > 0; o >>= 1) v += __shfl_down_sync(0xffffffffu, v, o);
        if (lane == 0) red[0] = v;
    }
    __syncthreads();
    v = red[0];
    __syncthreads();
    return v;
}

__device__ __forceinline__ float sigm(float x) { return 1.f / (1.f + expf(-x)); }
__device__ __forceinline__ void split1(float v, bf16& h, bf16& l) {
    h = __float2bfloat16_rn(v);
    l = __float2bfloat16_rn(v - __bfloat162float(h));
}
__device__ __forceinline__ void split_arr(const float* __restrict__ src,
                                          bf16* __restrict__ hi, bf16* __restrict__ lo,
                                          int n, int gt, int gs) {
    for (int i = gt; i < (n >> 2); i += gs) {
        float4 v = *(const float4*)(src + 4 * i);
        bf16 h[4], l[4];
        split1(v.x, h[0], l[0]); split1(v.y, h[1], l[1]);
        split1(v.z, h[2], l[2]); split1(v.w, h[3], l[3]);
        *(uint2*)(hi + 4 * i) = *(uint2*)h;
        *(uint2*)(lo + 4 * i) = *(uint2*)l;
    }
}

// ---------------- pipelined wmma GEMM ----------------
// acc[2][NF] per warp: warp tile 32 rows x 16*NF cols. 16 warps: wm=warp>>2 (4x32 rows),
// wn=warp&3 (4 x 16NF cols). Block tile 128 x 64*NF.
// 3-term bf16 split: Ah*Bh + Ah*Bl + Al*Bh, fp32 accum.
template <int NF, bool GATED>
__device__ void gemm_bf16(
    CFrag (&acc)[2][NF], char* P, uint32_t sbase,
    const bf16* __restrict__ Ahi, const bf16* __restrict__ Alo, int K, int mbase,
    const bf16* __restrict__ Whi, const bf16* __restrict__ Wlo, int nrow0)
{
    constexpr int BN  = 64 * NF;
    constexpr int BSZ = BN * 144;
    constexpr int STG = 2 * ASZ + 2 * BSZ;
    const int tid = threadIdx.x;
    const int warp = tid >> 5;
    const int wm = warp >> 2, wn = warp & 3;
    const int nt = K >> 6;

    auto stage = [&](int b, int ci) {
        const int kb = ci << 6;
        const uint32_t s0 = sbase + b * STG;
        for (int i = tid; i < 128 * 8; i += NTHREADS) {
            int r = i >> 3, u = i & 7;
            size_t g = (size_t)(mbase + r) * K + kb + u * 8;
            uint32_t d = s0 + r * 144 + u * 16;
            CP_CG(d,       Ahi + g);
            CP_CG(d + ASZ, Alo + g);
        }
        for (int i = tid; i < BN * 8; i += NTHREADS) {
            int n = i >> 3, u = i & 7;
            int row = GATED ? ((n >> 5) * HID + nrow0 + (n & 31)) : (nrow0 + n);
            size_t g = (size_t)row * K + kb + u * 8;
            uint32_t d = s0 + 2 * ASZ + n * 144 + u * 16;
            CP_CA(d,       Whi + g);
            CP_CA(d + BSZ, Wlo + g);
        }
        CP_COMMIT();
    };

    stage(0, 0);
    for (int i = 0; i < nt; i++) {
        const int b = i & 1;
        if (i + 1 < nt) { stage(b ^ 1, i + 1); CP_WAIT1(); }
        else            { CP_WAIT0(); }
        __syncthreads();

        const bf16* Ah = (const bf16*)(P + b * STG);
        const bf16* Al = (const bf16*)(P + b * STG + ASZ);
        const bf16* Bh = (const bf16*)(P + b * STG + 2 * ASZ);
        const bf16* Bl = (const bf16*)(P + b * STG + 2 * ASZ + BSZ);
        #pragma unroll
        for (int kk = 0; kk < 4; kk++) {
            AFrag ah0, ah1, al0, al1;
            wmma::load_matrix_sync(ah0, Ah + (wm * 32 + 0)  * LDA + kk * 16, LDA);
            wmma::load_matrix_sync(ah1, Ah + (wm * 32 + 16) * LDA + kk * 16, LDA);
            wmma::load_matrix_sync(al0, Al + (wm * 32 + 0)  * LDA + kk * 16, LDA);
            wmma::load_matrix_sync(al1, Al + (wm * 32 + 16) * LDA + kk * 16, LDA);
            #pragma unroll
            for (int nf = 0; nf < NF; nf++) {
                BFrag bh, bl;
                int cb = wn * (16 * NF) + nf * 16;
                wmma::load_matrix_sync(bh, Bh + cb * LDA + kk * 16, LDA);
                wmma::load_matrix_sync(bl, Bl + cb * LDA + kk * 16, LDA);
                wmma::mma_sync(acc[0][nf], ah0, bl, acc[0][nf]);
                wmma::mma_sync(acc[1][nf], ah1, bl, acc[1][nf]);
                wmma::mma_sync(acc[0][nf], al0, bh, acc[0][nf]);
                wmma::mma_sync(acc[1][nf], al1, bh, acc[1][nf]);
                wmma::mma_sync(acc[0][nf], ah0, bh, acc[0][nf]);
                wmma::mma_sync(acc[1][nf], ah1, bh, acc[1][nf]);
            }
        }
        __syncthreads();
    }
}

// ---------------- epilogues ----------------
__device__ void lstm_epi(CFrag (&acc)[2][2], char* P, const float* __restrict__ bias,
                         const float* __restrict__ c_in, float* __restrict__ c_out,
                         bf16* __restrict__ h_hi, bf16* __restrict__ h_lo,
                         int mbase, int jbase)
{
    float* pf = (float*)P;   // patch [128][132]
    const int tid = threadIdx.x, warp = tid >> 5;
    const int wm = warp >> 2, wn = warp & 3;
    #pragma unroll
    for (int i = 0; i < 2; i++)
        #pragma unroll
        for (int nf = 0; nf < 2; nf++)
            wmma::store_matrix_sync(pf + (wm * 32 + i * 16) * 132 + wn * 32 + nf * 16,
                                    acc[i][nf], 132, wmma::mem_row_major);
    __syncthreads();
    for (int e = tid; e < 128 * 32; e += NTHREADS) {
        int r = e >> 5, j = e & 31;
        int row = mbase + r, col = jbase + j;
        float iv = pf[r * 132 + j]      + __ldg(bias + col);
        float fv = pf[r * 132 + 32 + j] + __ldg(bias + HID + col);
        float gv = pf[r * 132 + 64 + j] + __ldg(bias + 2 * HID + col);
        float ov = pf[r * 132 + 96 + j] + __ldg(bias + 3 * HID + col);
        float cold = __ldcg(c_in + (size_t)row * HID + col);
        float cn = sigm(fv) * cold + sigm(iv) * tanhf(gv);
        float hn = sigm(ov) * tanhf(cn);
        c_out[(size_t)row * HID + col] = cn;
        bf16 hh, hl; split1(hn, hh, hl);
        h_hi[(size_t)row * HID + col] = hh;
        h_lo[(size_t)row * HID + col] = hl;
    }
    __syncthreads();
}

template <int NF>
__device__ void store_epi(CFrag (&acc)[2][NF], char* P, const float* __restrict__ bias,
                          float* __restrict__ dst, int stride, int mbase, int nbase)
{
    constexpr int BN = 64 * NF, PS = BN + 4;
    float* pf = (float*)P;
    const int tid = threadIdx.x, warp = tid >> 5;
    const int wm = warp >> 2, wn = warp & 3;
    #pragma unroll
    for (int i = 0; i < 2; i++)
        #pragma unroll
        for (int nf = 0; nf < NF; nf++)
            wmma::store_matrix_sync(pf + (wm * 32 + i * 16) * PS + wn * (16 * NF) + nf * 16,
                                    acc[i][nf], PS, wmma::mem_row_major);
    __syncthreads();
    for (int e = tid; e < 128 * BN; e += NTHREADS) {
        int r = e / BN, c = e % BN;
        dst[(size_t)(mbase + r) * stride + nbase + c] = pf[r * PS + c] + __ldg(bias + nbase + c);
    }
    __syncthreads();
}

// ---------------- the persistent decoder kernel ----------------
__global__ void __launch_bounds__(NTHREADS, 1) dec_kernel(
    const float* __restrict__ z,     const float* __restrict__ lin1_w, const float* __restrict__ lin1_b,
    const float* __restrict__ ln1_w, const float* __restrict__ ln1_b,
    const float* __restrict__ w_ih0, const float* __restrict__ w_hh0,  const float* __restrict__ b0,
    const float* __restrict__ w_ih1, const float* __restrict__ w_hh1,  const float* __restrict__ b1,
    const float* __restrict__ p1_w,  const float* __restrict__ p1_b,
    const float* __restrict__ pln_w, const float* __restrict__ pln_b,
    const float* __restrict__ p2_w,  const float* __restrict__ p2_b,
    float* __restrict__ out)
{
    extern __shared__ char pool[];
    __shared__ float redA[16], redB[16];
    const int bid = blockIdx.x, nb = gridDim.x, tid = threadIdx.x;
    uint32_t raw = smem_u32(pool);
    uint32_t pbase = (raw + 1023) & ~1023u;
    char* P = pool + (pbase - raw);
    unsigned epoch = g_release;

    // ---- S0: split weights + z into bf16 hi/lo planes
    {
        int gt = bid * NTHREADS + tid, gs = nb * NTHREADS;
        split_arr(lin1_w, g_lin1_hi, g_lin1_lo, 2048 * 256, gt, gs);
        split_arr(w_ih0,  g_wih0_hi, g_wih0_lo, 4096 * 128, gt, gs);
        split_arr(w_hh0,  g_whh0_hi, g_whh0_lo, 4096 * 1024, gt, gs);
        split_arr(w_ih1,  g_wih1_hi, g_wih1_lo, 4096 * 1024, gt, gs);
        split_arr(w_hh1,  g_whh1_hi, g_whh1_lo, 4096 * 1024, gt, gs);
        split_arr(p1_w,   g_p1_hi,   g_p1_lo,   1024 * 1024, gt, gs);
        split_arr(z,      g_z_hi,    g_z_lo,    512 * 256,   gt, gs);
    }
    gridbar(epoch);

    // ---- S1: u = z @ lin1_w^T + lin1_b  (512 x 2048, K=256): 128 tiles of 128x64
    for (int t = bid; t < 128; t += nb) {
        int mbase = (t >> 5) << 7;
        int nbase = (t & 31) << 6;
        CFrag acc[2][1];
        wmma::fill_fragment(acc[0][0], 0.f);
        wmma::fill_fragment(acc[1][0], 0.f);
        gemm_bf16<1, false>(acc, P, pbase, g_z_hi, g_z_lo, LATENT, mbase, g_lin1_hi, g_lin1_lo, nbase);
        store_epi<1>(acc, P, lin1_b, g_u, 2 * HID, mbase, nbase);
    }
    gridbar(epoch);

    // ---- S2: LayerNorm(2048) + gelu -> h0/c0 (both cells); zero x
    {
        float* pf = (float*)P;
        for (int grp = bid; grp < 128; grp += nb) {
            for (int rr = 0; rr < 4; rr++) {
                int row = (grp << 2) + rr;
                float ls = 0.f, lq = 0.f;
                for (int i = tid; i < 2 * HID; i += NTHREADS) {
                    float v = __ldcg(g_u + (size_t)row * 2 * HID + i);
                    pf[i] = v; ls += v; lq += v * v;
                }
                __syncthreads();
                float S = block_sum(ls, redA);
                float Q = block_sum(lq, redB);
                float mu = S * (1.f / 2048.f);
                float rstd = rsqrtf(Q * (1.f / 2048.f) - mu * mu + 1e-5f);
                for (int i = tid; i < 2 * HID; i += NTHREADS) {
                    float v = (pf[i] - mu) * rstd * __ldg(ln1_w + i) + __ldg(ln1_b + i);
                    float ge = v * normcdff(v);
                    if (i < HID) {
                        bf16 hh, hl; split1(ge, hh, hl);
                        g_h1h[0][(size_t)row * HID + i] = hh;
                        g_h1l[0][(size_t)row * HID + i] = hl;
                        g_h2h[0][(size_t)row * HID + i] = hh;
                        g_h2l[0][(size_t)row * HID + i] = hl;
                    } else {
                        g_c1[0][(size_t)row * HID + i - HID] = ge;
                        g_c2[0][(size_t)row * HID + i - HID] = ge;
                    }
                }
                __syncthreads();
            }
            for (int i = tid; i < 4 * NOUT; i += NTHREADS) {
                g_xh[(size_t)(grp << 2) * NOUT + i] = __float2bfloat16_rn(0.f);
                g_xl[(size_t)(grp << 2) * NOUT + i] = __float2bfloat16_rn(0.f);
            }
        }
    }
    gridbar(epoch);

    // ---- main sequential loop
    for (int s = 0; s < SEQL; s++) {
        const int pi = s & 1, po = pi ^ 1;

        // P1: (h1,c1) = lstm0(x, h1, c1) : K = 128 + 1024, 128 tiles of 128x128
        for (int t = bid; t < 128; t += nb) {
            int mbase = (t >> 5) << 7;
            int jbase = (t & 31) << 5;
            CFrag acc[2][2];
            #pragma unroll
            for (int i = 0; i < 2; i++) { wmma::fill_fragment(acc[i][0], 0.f); wmma::fill_fragment(acc[i][1], 0.f); }
            gemm_bf16<2, true>(acc, P, pbase, g_xh, g_xl, NOUT, mbase, g_wih0_hi, g_wih0_lo, jbase);
            gemm_bf16<2, true>(acc, P, pbase, g_h1h[pi], g_h1l[pi], HID, mbase, g_whh0_hi, g_whh0_lo, jbase);
            lstm_epi(acc, P, b0, g_c1[pi], g_c1[po], g_h1h[po], g_h1l[po], mbase, jbase);
        }
        gridbar(epoch);

        // P2: (h2,c2) = lstm1(h1_new, h2, c2) : K = 1024 + 1024
        for (int t = bid; t < 128; t += nb) {
            int mbase = (t >> 5) << 7;
            int jbase = (t & 31) << 5;
            CFrag acc[2][2];
            #pragma unroll
            for (int i = 0; i < 2; i++) { wmma::fill_fragment(acc[i][0], 0.f); wmma::fill_fragment(acc[i][1], 0.f); }
            gemm_bf16<2, true>(acc, P, pbase, g_h1h[po], g_h1l[po], HID, mbase, g_wih1_hi, g_wih1_lo, jbase);
            gemm_bf16<2, true>(acc, P, pbase, g_h2h[pi], g_h2l[pi], HID, mbase, g_whh1_hi, g_whh1_lo, jbase);
            lstm_epi(acc, P, b1, g_c2[pi], g_c2[po], g_h2h[po], g_h2l[po], mbase, jbase);
        }
        gridbar(epoch);

        // P3: t = h2_new @ p1_w^T + p1_b : 64 tiles of 128x64
        for (int t = bid; t < 64; t += nb) {
            int mbase = (t >> 4) << 7;
            int nbase = (t & 15) << 6;
            CFrag acc[2][1];
            wmma::fill_fragment(acc[0][0], 0.f);
            wmma::fill_fragment(acc[1][0], 0.f);
            gemm_bf16<1, false>(acc, P, pbase, g_h2h[po], g_h2l[po], HID, mbase, g_p1_hi, g_p1_lo, nbase);
            store_epi<1>(acc, P, p1_b, g_t, HID, mbase, nbase);
        }
        gridbar(epoch);

        // P4: per-row LayerNorm + gelu + y = g @ p2_w^T + p2_b ; y -> out and next x
        {
            float* pf = (float*)P;
            for (int grp = bid; grp < 128; grp += nb) {
                for (int rr = 0; rr < 4; rr++) {
                    int row = (grp << 2) + rr;
                    float ls = 0.f, lq = 0.f;
                    for (int i = tid; i < HID; i += NTHREADS) {
                        float v = __ldcg(g_t + (size_t)row * HID + i);
                        pf[i] = v; ls += v; lq += v * v;
                    }
                    __syncthreads();
                    float S = block_sum(ls, redA);
                    float Q = block_sum(lq, redB);
                    float mu = S * (1.f / 1024.f);
                    float rstd = rsqrtf(Q * (1.f / 1024.f) - mu * mu + 1e-5f);
                    for (int i = tid; i < HID; i += NTHREADS) {
                        float v = (pf[i] - mu) * rstd * __ldg(pln_w + i) + __ldg(pln_b + i);
                        pf[HID + i] = v * normcdff(v);
                    }
                    __syncthreads();
                    int o = tid & 127, q = tid >> 7;   // 4 partials per column
                    const float* wrow = p2_w + (size_t)o * HID + q * 256;
                    const float* gv = pf + HID + q * 256;
                    float a = 0.f;
                    #pragma unroll 4
                    for (int k = 0; k < 256; k += 4) {
                        float4 w4 = *(const float4*)(wrow + k);
                        float4 g4 = *(const float4*)(gv + k);
                        a += g4.x * w4.x + g4.y * w4.y + g4.z * w4.z + g4.w * w4.w;
                    }
                    pf[2 * HID + tid] = a;
                    __syncthreads();
                    if (q == 0) {
                        float y = pf[2 * HID + o] + pf[2 * HID + 128 + o]
                                + pf[2 * HID + 256 + o] + pf[2 * HID + 384 + o] + __ldg(p2_b + o);
                        bf16 xh, xl; split1(y, xh, xl);
                        g_xh[(size_t)row * NOUT + o] = xh;
                        g_xl[(size_t)row * NOUT + o] = xl;
                        out[(size_t)row * SEQL * NOUT + s * NOUT + o] = y;
                    }
                    __syncthreads();
                }
            }
        }
        gridbar(epoch);
    }
}

// ---------------- launch ----------------
extern "C" void kernel_launch(void* const* d_in, const int* in_sizes, int n_in,
                              void* d_out, int out_size) {
    (void)in_sizes; (void)n_in; (void)out_size;
    int nsm = 0;
    cudaDeviceGetAttribute(&nsm, cudaDevAttrMultiProcessorCount, 0);
    if (nsm <= 0) nsm = 148;
    if (nsm > 256) nsm = 256;
    cudaFuncSetAttribute(dec_kernel, cudaFuncAttributeMaxDynamicSharedMemorySize, SMEM_BYTES);

    const float* z      = (const float*)d_in[0];
    const float* lin1_w = (const float*)d_in[1];
    const float* lin1_b = (const float*)d_in[2];
    const float* ln1_w  = (const float*)d_in[3];
    const float* ln1_b  = (const float*)d_in[4];
    const float* w_ih0  = (const float*)d_in[5];
    const float* w_hh0  = (const float*)d_in[6];
    const float* b0     = (const float*)d_in[7];
    const float* w_ih1  = (const float*)d_in[8];
    const float* w_hh1  = (const float*)d_in[9];
    const float* b1     = (const float*)d_in[10];
    const float* p1_w   = (const float*)d_in[11];
    const float* p1_b   = (const float*)d_in[12];
    const float* pln_w  = (const float*)d_in[13];
    const float* pln_b  = (const float*)d_in[14];
    const float* p2_w   = (const float*)d_in[15];
    const float* p2_b   = (const float*)d_in[16];

    dec_kernel<<<nsm, NTHREADS, SMEM_BYTES>>>(
        z, lin1_w, lin1_b, ln1_w, ln1_b,
        w_ih0, w_hh0, b0, w_ih1, w_hh1, b1,
        p1_w, p1_b, pln_w, pln_b, p2_w, p2_b,
        (float*)d_out);
}

// round 5
// speedup vs baseline: 4.6921x; 1.1066x over previous
#include <cuda_runtime.h>
#include <cuda_bf16.h>
#include <mma.h>
#include <math.h>
#include <stdint.h>

using namespace nvcuda;
using bf16 = __nv_bfloat16;

#define LATENT 256
#define HID    1024
#define NOUT   128
#define SEQL   96

#define NTHREADS 512
#define LDA   72
#define ABLK  9216          // elems per 128x72 block
#define ABLKB 18432         // bytes per 128x72 bf16 block

// smem: 1024 align slack + 1024 hdr (mbars) + 2 x 72KB stage buffers
#define SMEM_BYTES (1024 + 1024 + 2 * 73728)

// ---------------- device scratch (packed layouts) ----------------
// weights packed as [plane][ntile][kchunk][BN x 72]
__device__ __align__(16) bf16 g_lin1p[2][32 * 4 * 4608];     // BN=64, K=256
__device__ __align__(16) bf16 g_wih0p[2][32 * 2 * 9216];     // BN=128 gated, K=128
__device__ __align__(16) bf16 g_whh0p[2][32 * 16 * 9216];    // BN=128 gated, K=1024
__device__ __align__(16) bf16 g_wih1p[2][32 * 16 * 9216];
__device__ __align__(16) bf16 g_whh1p[2][32 * 16 * 9216];
__device__ __align__(16) bf16 g_p1p[2][16 * 16 * 4608];      // BN=64, K=1024
// activations packed as [plane][kchunk][mgroup][128 x 72]
__device__ __align__(16) bf16 g_zp[2][4 * 4 * 9216];
__device__ __align__(16) bf16 g_xp[2][2 * 4 * 9216];
__device__ __align__(16) bf16 g_h1p[2][2][16 * 4 * 9216];    // [pingpong][plane]
__device__ __align__(16) bf16 g_h2p[2][2][16 * 4 * 9216];
__device__ float g_c1[2][512 * HID];
__device__ float g_c2[2][512 * HID];
__device__ float g_u[512 * 2 * HID];
__device__ float g_t[512 * HID];
__device__ volatile unsigned g_arrive[256];
__device__ volatile unsigned g_release;

typedef wmma::fragment<wmma::accumulator, 16, 16, 16, float> CFrag;
typedef wmma::fragment<wmma::matrix_a, 16, 16, 16, bf16, wmma::row_major> AFrag;
typedef wmma::fragment<wmma::matrix_b, 16, 16, 16, bf16, wmma::col_major> BFrag;

// ---------------- PTX helpers ----------------
__device__ __forceinline__ uint32_t smem_u32(const void* p) {
    uint32_t a;
    asm("{ .reg .u64 t; cvta.to.shared.u64 t, %1; cvt.u32.u64 %0, t; }" : "=r"(a) : "l"(p));
    return a;
}
#define MBAR_INIT(a, c) \
    asm volatile("mbarrier.init.shared.b64 [%0], %1;" :: "r"(a), "r"((uint32_t)(c)) : "memory")
#define MBAR_EXPECT(a, n) \
    asm volatile("mbarrier.arrive.expect_tx.shared.b64 _, [%0], %1;" :: "r"(a), "r"((uint32_t)(n)) : "memory")
#define MBAR_WAIT(a, par) do { \
    uint32_t _m = (a), _p = (par), _d; \
    asm volatile("{\n\t.reg .pred p;\n\t" \
        "mbarrier.try_wait.parity.acquire.cta.shared::cta.b64 p, [%1], %2;\n\t" \
        "selp.b32 %0, 1, 0, p;\n\t}" : "=r"(_d) : "r"(_m), "r"(_p) : "memory"); \
    if (!_d) { \
        asm volatile("{\n\t.reg .pred P1;\n\tWL_%=:\n\t" \
            "mbarrier.try_wait.parity.acquire.cta.shared::cta.b64 P1, [%0], %1, 0x989680;\n\t" \
            "@P1 bra.uni WD_%=;\n\tbra.uni WL_%=;\n\tWD_%=:\n\t}" \
            :: "r"(_m), "r"(_p) : "memory"); \
    } } while (0)
#define BULK_G2S(dst, src, sz, mbar) \
    asm volatile("cp.async.bulk.shared::cluster.global.mbarrier::complete_tx::bytes [%0], [%1], %2, [%3];" \
        :: "r"((uint32_t)(dst)), "l"(src), "r"((uint32_t)(sz)), "r"((uint32_t)(mbar)) : "memory")

// ---------------- grid barrier ----------------
__device__ __forceinline__ void gridbar(unsigned& epoch) {
    epoch++;
    __threadfence();
    __syncthreads();
    if (blockIdx.x == 0) {
        if (threadIdx.x == 0) g_arrive[0] = epoch;
        for (int b = threadIdx.x; b < (int)gridDim.x; b += blockDim.x) {
            while (g_arrive[b] < epoch) { __nanosleep(32); }
        }
        __syncthreads();
        if (threadIdx.x == 0) { __threadfence(); g_release = epoch; }
    } else {
        if (threadIdx.x == 0) {
            g_arrive[blockIdx.x] = epoch;
            while (g_release < epoch) { __nanosleep(32); }
        }
    }
    __syncthreads();
}

__device__ __forceinline__ float block_sum(float v, float* red) {
    #pragma unroll
    for (int o = 16; o > 0; o >>= 1) v += __shfl_down_sync(0xffffffffu, v, o);
    int warp = threadIdx.x >> 5, lane = threadIdx.x & 31;
    if (lane == 0) red[warp] = v;
    __syncthreads();
    if (threadIdx.x < 32) {
        v = (lane < 16) ? red[lane] : 0.f;
        #pragma unroll
        for (int o = 8; o > 0; o >>= 1) v += __shfl_down_sync(0xffffffffu, v, o);
        if (lane == 0) red[0] = v;
    }
    __syncthreads();
    v = red[0];
    __syncthreads();
    return v;
}

__device__ __forceinline__ float sigm(float x) { return 1.f / (1.f + expf(-x)); }
__device__ __forceinline__ void split1(float v, bf16& h, bf16& l) {
    h = __float2bfloat16_rn(v);
    l = __float2bfloat16_rn(v - __bfloat162float(h));
}

// pack activation offset: (row 0..511, col) -> packed elem index
__device__ __forceinline__ size_t pk_off(int row, int col) {
    return ((size_t)((col >> 6) * 4 + (row >> 7))) * ABLK + (size_t)(row & 127) * LDA + (col & 63);
}

// ---------------- S0 weight packer ----------------
__device__ void pack_w(const float* __restrict__ W, bf16* __restrict__ hi, bf16* __restrict__ lo,
                       int K, int BN, int ntiles, int gated, int gt, int gs)
{
    const int nch = K >> 6;
    const int tot = ntiles * nch * BN * 16;   // float4 units
    for (int i = gt; i < tot; i += gs) {
        int k4 = i & 15;
        int rest = i >> 4;
        int n = rest % BN; rest /= BN;
        int c = rest % nch;
        int nt = rest / nch;
        int row = gated ? ((n >> 5) * HID + nt * 32 + (n & 31)) : (nt * BN + n);
        float4 v = *(const float4*)(W + (size_t)row * K + c * 64 + k4 * 4);
        bf16 h[4], l[4];
        split1(v.x, h[0], l[0]); split1(v.y, h[1], l[1]);
        split1(v.z, h[2], l[2]); split1(v.w, h[3], l[3]);
        size_t d = ((size_t)(nt * nch + c) * BN + n) * LDA + k4 * 4;
        *(uint2*)(hi + d) = *(uint2*)h;
        *(uint2*)(lo + d) = *(uint2*)l;
    }
}

// ---------------- bulk-pipelined wmma GEMM ----------------
// acc[2][NF]: 16 warps, warp tile 32 x 16*NF; block tile 128 x 64*NF.
// A/B pre-packed padded blocks; staging via cp.async.bulk into double buffers.
template <int NF>
__device__ void gemm_pk(CFrag (&acc)[2][NF], char* P, uint32_t pbase,
                        const bf16* __restrict__ Ah, const bf16* __restrict__ Al,
                        int nch, size_t astr,
                        const bf16* __restrict__ Bh, const bf16* __restrict__ Bl,
                        size_t bstr, int* ph)
{
    constexpr int BB  = NF * 64 * 144;            // B plane bytes
    constexpr int STG = 2 * ABLKB + 2 * BB;
    constexpr uint32_t TX = (uint32_t)STG;
    const int tid = threadIdx.x;
    const int warp = tid >> 5;
    const int wm = warp >> 2, wn = warp & 3;
    const uint32_t sbuf = pbase + 1024;

    auto fill = [&](int b, int c) {
        if (tid == 0) {
            uint32_t d = sbuf + b * STG;
            uint32_t mb = pbase + (b << 3);
            MBAR_EXPECT(mb, TX);
            BULK_G2S(d,                 (const char*)(Ah + (size_t)c * astr), ABLKB, mb);
            BULK_G2S(d + ABLKB,         (const char*)(Al + (size_t)c * astr), ABLKB, mb);
            BULK_G2S(d + 2 * ABLKB,     (const char*)(Bh + (size_t)c * bstr), BB, mb);
            BULK_G2S(d + 2 * ABLKB + BB,(const char*)(Bl + (size_t)c * bstr), BB, mb);
        }
    };

    fill(0, 0);
    for (int i = 0; i < nch; i++) {
        const int b = i & 1;
        if (i + 1 < nch) fill(b ^ 1, i + 1);
        MBAR_WAIT(pbase + (b << 3), (uint32_t)(ph[b] & 1));
        ph[b]++;

        const bf16* sAh = (const bf16*)(P + 1024 + b * STG);
        const bf16* sAl = sAh + ABLK;
        const bf16* sBh = sAl + ABLK;
        const bf16* sBl = sBh + NF * 64 * LDA;
        #pragma unroll
        for (int kk = 0; kk < 4; kk++) {
            AFrag ah0, ah1, al0, al1;
            wmma::load_matrix_sync(ah0, sAh + (wm * 32 + 0)  * LDA + kk * 16, LDA);
            wmma::load_matrix_sync(ah1, sAh + (wm * 32 + 16) * LDA + kk * 16, LDA);
            wmma::load_matrix_sync(al0, sAl + (wm * 32 + 0)  * LDA + kk * 16, LDA);
            wmma::load_matrix_sync(al1, sAl + (wm * 32 + 16) * LDA + kk * 16, LDA);
            #pragma unroll
            for (int nf = 0; nf < NF; nf++) {
                BFrag bh, bl;
                int cb = wn * (16 * NF) + nf * 16;
                wmma::load_matrix_sync(bh, sBh + cb * LDA + kk * 16, LDA);
                wmma::load_matrix_sync(bl, sBl + cb * LDA + kk * 16, LDA);
                wmma::mma_sync(acc[0][nf], ah0, bl, acc[0][nf]);
                wmma::mma_sync(acc[1][nf], ah1, bl, acc[1][nf]);
                wmma::mma_sync(acc[0][nf], al0, bh, acc[0][nf]);
                wmma::mma_sync(acc[1][nf], al1, bh, acc[1][nf]);
                wmma::mma_sync(acc[0][nf], ah0, bh, acc[0][nf]);
                wmma::mma_sync(acc[1][nf], ah1, bh, acc[1][nf]);
            }
        }
        __syncthreads();
    }
}

// ---------------- epilogues ----------------
__device__ void lstm_epi(CFrag (&acc)[2][2], char* P, const float* __restrict__ bias,
                         const float* __restrict__ c_in, float* __restrict__ c_out,
                         bf16* __restrict__ hp_hi, bf16* __restrict__ hp_lo,
                         int mbase, int jbase)
{
    float* pf = (float*)(P + 1024);   // patch [128][132]
    const int tid = threadIdx.x, warp = tid >> 5;
    const int wm = warp >> 2, wn = warp & 3;
    #pragma unroll
    for (int i = 0; i < 2; i++)
        #pragma unroll
        for (int nf = 0; nf < 2; nf++)
            wmma::store_matrix_sync(pf + (wm * 32 + i * 16) * 132 + wn * 32 + nf * 16,
                                    acc[i][nf], 132, wmma::mem_row_major);
    __syncthreads();
    for (int e = tid; e < 128 * 32; e += NTHREADS) {
        int r = e >> 5, j = e & 31;
        int row = mbase + r, col = jbase + j;
        float iv = pf[r * 132 + j]      + __ldg(bias + col);
        float fv = pf[r * 132 + 32 + j] + __ldg(bias + HID + col);
        float gv = pf[r * 132 + 64 + j] + __ldg(bias + 2 * HID + col);
        float ov = pf[r * 132 + 96 + j] + __ldg(bias + 3 * HID + col);
        float cold = __ldcg(c_in + (size_t)row * HID + col);
        float cn = sigm(fv) * cold + sigm(iv) * tanhf(gv);
        float hn = sigm(ov) * tanhf(cn);
        c_out[(size_t)row * HID + col] = cn;
        bf16 hh, hl; split1(hn, hh, hl);
        size_t off = pk_off(row, col);
        hp_hi[off] = hh;
        hp_lo[off] = hl;
    }
    __syncthreads();
}

template <int NF>
__device__ void store_epi(CFrag (&acc)[2][NF], char* P, const float* __restrict__ bias,
                          float* __restrict__ dst, int stride, int mbase, int nbase)
{
    constexpr int BN = 64 * NF, PS = BN + 4;
    float* pf = (float*)(P + 1024);
    const int tid = threadIdx.x, warp = tid >> 5;
    const int wm = warp >> 2, wn = warp & 3;
    #pragma unroll
    for (int i = 0; i < 2; i++)
        #pragma unroll
        for (int nf = 0; nf < NF; nf++)
            wmma::store_matrix_sync(pf + (wm * 32 + i * 16) * PS + wn * (16 * NF) + nf * 16,
                                    acc[i][nf], PS, wmma::mem_row_major);
    __syncthreads();
    for (int e = tid; e < 128 * BN; e += NTHREADS) {
        int r = e / BN, c = e % BN;
        dst[(size_t)(mbase + r) * stride + nbase + c] = pf[r * PS + c] + __ldg(bias + nbase + c);
    }
    __syncthreads();
}

// ---------------- the persistent decoder kernel ----------------
__global__ void __launch_bounds__(NTHREADS, 1) dec_kernel(
    const float* __restrict__ z,     const float* __restrict__ lin1_w, const float* __restrict__ lin1_b,
    const float* __restrict__ ln1_w, const float* __restrict__ ln1_b,
    const float* __restrict__ w_ih0, const float* __restrict__ w_hh0,  const float* __restrict__ b0,
    const float* __restrict__ w_ih1, const float* __restrict__ w_hh1,  const float* __restrict__ b1,
    const float* __restrict__ p1_w,  const float* __restrict__ p1_b,
    const float* __restrict__ pln_w, const float* __restrict__ pln_b,
    const float* __restrict__ p2_w,  const float* __restrict__ p2_b,
    float* __restrict__ out)
{
    extern __shared__ char pool[];
    __shared__ float redA[16], redB[16];
    const int bid = blockIdx.x, nb = gridDim.x, tid = threadIdx.x;
    uint32_t raw = smem_u32(pool);
    uint32_t pbase = (raw + 1023) & ~1023u;
    char* P = pool + (pbase - raw);
    unsigned epoch = g_release;
    int ph[2] = {0, 0};

    if (tid == 0) { MBAR_INIT(pbase, 1); MBAR_INIT(pbase + 8, 1); }
    __syncthreads();

    // ---- S0: pack weights into blocked bf16 hi/lo layouts; pack z; zero x
    {
        int gt = bid * NTHREADS + tid, gs = nb * NTHREADS;
        pack_w(lin1_w, g_lin1p[0], g_lin1p[1], LATENT, 64, 32, 0, gt, gs);
        pack_w(w_ih0,  g_wih0p[0], g_wih0p[1], NOUT, 128, 32, 1, gt, gs);
        pack_w(w_hh0,  g_whh0p[0], g_whh0p[1], HID, 128, 32, 1, gt, gs);
        pack_w(w_ih1,  g_wih1p[0], g_wih1p[1], HID, 128, 32, 1, gt, gs);
        pack_w(w_hh1,  g_whh1p[0], g_whh1p[1], HID, 128, 32, 1, gt, gs);
        pack_w(p1_w,   g_p1p[0],   g_p1p[1],   HID, 64, 16, 0, gt, gs);
        // z: (ch4, mg4, r128, k64)
        for (int i = gt; i < 4 * 4 * 128 * 16; i += gs) {
            int k4 = i & 15, r = (i >> 4) & 127, mg = (i >> 11) & 3, c = i >> 13;
            float4 v = *(const float4*)(z + (size_t)(mg * 128 + r) * LATENT + c * 64 + k4 * 4);
            bf16 h[4], l[4];
            split1(v.x, h[0], l[0]); split1(v.y, h[1], l[1]);
            split1(v.z, h[2], l[2]); split1(v.w, h[3], l[3]);
            size_t d = (size_t)(c * 4 + mg) * ABLK + (size_t)r * LDA + k4 * 4;
            *(uint2*)(g_zp[0] + d) = *(uint2*)h;
            *(uint2*)(g_zp[1] + d) = *(uint2*)l;
        }
        // zero x (re-zero each launch for graph replays)
        for (int i = gt; i < 2 * 4 * ABLK; i += gs) {
            g_xp[0][i] = __float2bfloat16_rn(0.f);
            g_xp[1][i] = __float2bfloat16_rn(0.f);
        }
    }
    gridbar(epoch);

    // ---- S1: u = z @ lin1_w^T + lin1_b  (512 x 2048): 128 tiles of 128x64
    for (int t = bid; t < 128; t += nb) {
        int mg = t >> 5, nt = t & 31;
        CFrag acc[2][1];
        wmma::fill_fragment(acc[0][0], 0.f);
        wmma::fill_fragment(acc[1][0], 0.f);
        gemm_pk<1>(acc, P, pbase,
                   g_zp[0] + (size_t)mg * ABLK, g_zp[1] + (size_t)mg * ABLK, 4, 4 * ABLK,
                   g_lin1p[0] + (size_t)nt * 4 * 4608, g_lin1p[1] + (size_t)nt * 4 * 4608, 4608, ph);
        store_epi<1>(acc, P, lin1_b, g_u, 2 * HID, mg << 7, nt << 6);
    }
    gridbar(epoch);

    // ---- S2: LayerNorm(2048) + gelu -> h0/c0 (both cells)
    {
        float* pf = (float*)(P + 1024);
        for (int grp = bid; grp < 128; grp += nb) {
            for (int rr = 0; rr < 4; rr++) {
                int row = (grp << 2) + rr;
                float ls = 0.f, lq = 0.f;
                for (int i = tid; i < 2 * HID; i += NTHREADS) {
                    float v = __ldcg(g_u + (size_t)row * 2 * HID + i);
                    pf[i] = v; ls += v; lq += v * v;
                }
                __syncthreads();
                float S = block_sum(ls, redA);
                float Q = block_sum(lq, redB);
                float mu = S * (1.f / 2048.f);
                float rstd = rsqrtf(Q * (1.f / 2048.f) - mu * mu + 1e-5f);
                for (int i = tid; i < 2 * HID; i += NTHREADS) {
                    float v = (pf[i] - mu) * rstd * __ldg(ln1_w + i) + __ldg(ln1_b + i);
                    float ge = v * normcdff(v);
                    if (i < HID) {
                        bf16 hh, hl; split1(ge, hh, hl);
                        size_t off = pk_off(row, i);
                        g_h1p[0][0][off] = hh; g_h1p[0][1][off] = hl;
                        g_h2p[0][0][off] = hh; g_h2p[0][1][off] = hl;
                    } else {
                        g_c1[0][(size_t)row * HID + i - HID] = ge;
                        g_c2[0][(size_t)row * HID + i - HID] = ge;
                    }
                }
                __syncthreads();
            }
        }
    }
    gridbar(epoch);

    // ---- main sequential loop
    for (int s = 0; s < SEQL; s++) {
        const int pi = s & 1, po = pi ^ 1;

        // P1: (h1,c1) = lstm0(x, h1, c1) : K = 128 + 1024
        for (int t = bid; t < 128; t += nb) {
            int mg = t >> 5, nt = t & 31;
            CFrag acc[2][2];
            #pragma unroll
            for (int i = 0; i < 2; i++) { wmma::fill_fragment(acc[i][0], 0.f); wmma::fill_fragment(acc[i][1], 0.f); }
            gemm_pk<2>(acc, P, pbase,
                       g_xp[0] + (size_t)mg * ABLK, g_xp[1] + (size_t)mg * ABLK, 2, 4 * ABLK,
                       g_wih0p[0] + (size_t)nt * 2 * 9216, g_wih0p[1] + (size_t)nt * 2 * 9216, 9216, ph);
            gemm_pk<2>(acc, P, pbase,
                       g_h1p[pi][0] + (size_t)mg * ABLK, g_h1p[pi][1] + (size_t)mg * ABLK, 16, 4 * ABLK,
                       g_whh0p[0] + (size_t)nt * 16 * 9216, g_whh0p[1] + (size_t)nt * 16 * 9216, 9216, ph);
            lstm_epi(acc, P, b0, g_c1[pi], g_c1[po], g_h1p[po][0], g_h1p[po][1], mg << 7, nt << 5);
        }
        gridbar(epoch);

        // P2: (h2,c2) = lstm1(h1_new, h2, c2) : K = 1024 + 1024
        for (int t = bid; t < 128; t += nb) {
            int mg = t >> 5, nt = t & 31;
            CFrag acc[2][2];
            #pragma unroll
            for (int i = 0; i < 2; i++) { wmma::fill_fragment(acc[i][0], 0.f); wmma::fill_fragment(acc[i][1], 0.f); }
            gemm_pk<2>(acc, P, pbase,
                       g_h1p[po][0] + (size_t)mg * ABLK, g_h1p[po][1] + (size_t)mg * ABLK, 16, 4 * ABLK,
                       g_wih1p[0] + (size_t)nt * 16 * 9216, g_wih1p[1] + (size_t)nt * 16 * 9216, 9216, ph);
            gemm_pk<2>(acc, P, pbase,
                       g_h2p[pi][0] + (size_t)mg * ABLK, g_h2p[pi][1] + (size_t)mg * ABLK, 16, 4 * ABLK,
                       g_whh1p[0] + (size_t)nt * 16 * 9216, g_whh1p[1] + (size_t)nt * 16 * 9216, 9216, ph);
            lstm_epi(acc, P, b1, g_c2[pi], g_c2[po], g_h2p[po][0], g_h2p[po][1], mg << 7, nt << 5);
        }
        gridbar(epoch);

        // P3: t = h2_new @ p1_w^T + p1_b : 64 tiles of 128x64
        for (int t = bid; t < 64; t += nb) {
            int mg = t >> 4, nt = t & 15;
            CFrag acc[2][1];
            wmma::fill_fragment(acc[0][0], 0.f);
            wmma::fill_fragment(acc[1][0], 0.f);
            gemm_pk<1>(acc, P, pbase,
                       g_h2p[po][0] + (size_t)mg * ABLK, g_h2p[po][1] + (size_t)mg * ABLK, 16, 4 * ABLK,
                       g_p1p[0] + (size_t)nt * 16 * 4608, g_p1p[1] + (size_t)nt * 16 * 4608, 4608, ph);
            store_epi<1>(acc, P, p1_b, g_t, HID, mg << 7, nt << 6);
        }
        gridbar(epoch);

        // P4: 4 rows in parallel: LayerNorm + gelu + y = g @ p2_w^T + p2_b
        {
            float* pf = (float*)(P + 1024);   // 4 groups x 1024 floats
            const int g = tid >> 7, lt = tid & 127, w4 = (tid >> 5) & 3, lane = tid & 31;
            for (int grp = bid; grp < 128; grp += nb) {
                int row = (grp << 2) + g;
                const float* trow = g_t + (size_t)row * HID;
                float vb[8]; float ls = 0.f, lq = 0.f;
                #pragma unroll
                for (int u = 0; u < 8; u++) {
                    float v = __ldcg(trow + u * 128 + lt);
                    vb[u] = v; ls += v; lq += v * v;
                }
                #pragma unroll
                for (int o = 16; o > 0; o >>= 1) {
                    ls += __shfl_down_sync(0xffffffffu, ls, o);
                    lq += __shfl_down_sync(0xffffffffu, lq, o);
                }
                if (lane == 0) { redA[g * 4 + w4] = ls; redB[g * 4 + w4] = lq; }
                __syncthreads();
                float S = redA[g * 4] + redA[g * 4 + 1] + redA[g * 4 + 2] + redA[g * 4 + 3];
                float Q = redB[g * 4] + redB[g * 4 + 1] + redB[g * 4 + 2] + redB[g * 4 + 3];
                float mu = S * (1.f / 1024.f);
                float rstd = rsqrtf(Q * (1.f / 1024.f) - mu * mu + 1e-5f);
                #pragma unroll
                for (int u = 0; u < 8; u++) {
                    int i = u * 128 + lt;
                    float v = (vb[u] - mu) * rstd * __ldg(pln_w + i) + __ldg(pln_b + i);
                    pf[g * 1024 + i] = v * normcdff(v);
                }
                __syncthreads();
                const float* wrow = p2_w + (size_t)lt * HID;
                const float* gv = pf + g * 1024;
                float a = 0.f;
                #pragma unroll 4
                for (int k = 0; k < 1024; k += 4) {
                    float4 wv = *(const float4*)(wrow + k);
                    float4 g4 = *(const float4*)(gv + k);
                    a += g4.x * wv.x + g4.y * wv.y + g4.z * wv.z + g4.w * wv.w;
                }
                float y = a + __ldg(p2_b + lt);
                bf16 xh, xl; split1(y, xh, xl);
                size_t off = pk_off(row, lt);
                g_xp[0][off] = xh;
                g_xp[1][off] = xl;
                out[(size_t)row * SEQL * NOUT + s * NOUT + lt] = y;
                __syncthreads();
            }
        }
        gridbar(epoch);
    }
}

// ---------------- launch ----------------
extern "C" void kernel_launch(void* const* d_in, const int* in_sizes, int n_in,
                              void* d_out, int out_size) {
    (void)in_sizes; (void)n_in; (void)out_size;
    int nsm = 0;
    cudaDeviceGetAttribute(&nsm, cudaDevAttrMultiProcessorCount, 0);
    if (nsm <= 0) nsm = 148;
    if (nsm > 256) nsm = 256;
    cudaFuncSetAttribute(dec_kernel, cudaFuncAttributeMaxDynamicSharedMemorySize, SMEM_BYTES);

    const float* z      = (const float*)d_in[0];
    const float* lin1_w = (const float*)d_in[1];
    const float* lin1_b = (const float*)d_in[2];
    const float* ln1_w  = (const float*)d_in[3];
    const float* ln1_b  = (const float*)d_in[4];
    const float* w_ih0  = (const float*)d_in[5];
    const float* w_hh0  = (const float*)d_in[6];
    const float* b0     = (const float*)d_in[7];
    const float* w_ih1  = (const float*)d_in[8];
    const float* w_hh1  = (const float*)d_in[9];
    const float* b1     = (const float*)d_in[10];
    const float* p1_w   = (const float*)d_in[11];
    const float* p1_b   = (const float*)d_in[12];
    const float* pln_w  = (const float*)d_in[13];
    const float* pln_b  = (const float*)d_in[14];
    const float* p2_w   = (const float*)d_in[15];
    const float* p2_b   = (const float*)d_in[16];

    dec_kernel<<<nsm, NTHREADS, SMEM_BYTES>>>(
        z, lin1_w, lin1_b, ln1_w, ln1_b,
        w_ih0, w_hh0, b0, w_ih1, w_hh1, b1,
        p1_w, p1_b, pln_w, pln_b, p2_w, p2_b,
        (float*)d_out);
}

// round 6
// speedup vs baseline: 4.6991x; 1.0015x over previous
#include <cuda_runtime.h>
#include <cuda_bf16.h>
#include <mma.h>
#include <math.h>
#include <stdint.h>

using namespace nvcuda;
using bf16 = __nv_bfloat16;

#define LATENT 256
#define HID    1024
#define NOUT   128
#define SEQL   96

#define NTHREADS 512
#define LDA    72
#define ABLK   9216          // elems per 128x72 block
#define ABLKB  18432         // bytes per 128x72 bf16 block
#define NSTAGE 3
#define STGMAX 73728         // bytes per stage buffer (max: NF=2)

// smem: 1024 align slack + 1024 hdr (mbars) + 3 stage buffers
#define SMEM_BYTES (1024 + 1024 + NSTAGE * STGMAX)

// ---------------- device scratch (packed layouts) ----------------
__device__ __align__(16) bf16 g_lin1p[2][32 * 4 * 4608];     // BN=64, K=256
__device__ __align__(16) bf16 g_wih0p[2][32 * 2 * 9216];     // BN=128 gated, K=128
__device__ __align__(16) bf16 g_whh0p[2][32 * 16 * 9216];    // BN=128 gated, K=1024
__device__ __align__(16) bf16 g_wih1p[2][32 * 16 * 9216];
__device__ __align__(16) bf16 g_whh1p[2][32 * 16 * 9216];
__device__ __align__(16) bf16 g_p1p[2][16 * 16 * 4608];      // BN=64, K=1024
// activations packed as [plane][kchunk][mgroup][128 x 72]
__device__ __align__(16) bf16 g_zp[2][4 * 4 * 9216];
__device__ __align__(16) bf16 g_xp[2][2 * 4 * 9216];
__device__ __align__(16) bf16 g_h1p[2][2][16 * 4 * 9216];    // [pingpong][plane]
__device__ __align__(16) bf16 g_h2p[2][2][16 * 4 * 9216];
__device__ float g_c1[2][512 * HID];
__device__ float g_c2[2][512 * HID];
__device__ float g_u[512 * 2 * HID];
__device__ float g_t[512 * HID];
__device__ volatile unsigned g_arrive[256];
__device__ volatile unsigned g_release;

typedef wmma::fragment<wmma::accumulator, 16, 16, 16, float> CFrag;
typedef wmma::fragment<wmma::matrix_a, 16, 16, 16, bf16, wmma::row_major> AFrag;
typedef wmma::fragment<wmma::matrix_b, 16, 16, 16, bf16, wmma::col_major> BFrag;

// ---------------- PTX helpers ----------------
__device__ __forceinline__ uint32_t smem_u32(const void* p) {
    uint32_t a;
    asm("{ .reg .u64 t; cvta.to.shared.u64 t, %1; cvt.u32.u64 %0, t; }" : "=r"(a) : "l"(p));
    return a;
}
#define MBAR_INIT(a, c) \
    asm volatile("mbarrier.init.shared.b64 [%0], %1;" :: "r"(a), "r"((uint32_t)(c)) : "memory")
#define MBAR_EXPECT(a, n) \
    asm volatile("mbarrier.arrive.expect_tx.shared.b64 _, [%0], %1;" :: "r"(a), "r"((uint32_t)(n)) : "memory")
#define MBAR_ARRIVE(a) \
    asm volatile("mbarrier.arrive.shared.b64 _, [%0];" :: "r"((uint32_t)(a)) : "memory")
#define MBAR_WAIT(a, par) do { \
    uint32_t _m = (a), _p = (par), _d; \
    asm volatile("{\n\t.reg .pred p;\n\t" \
        "mbarrier.try_wait.parity.acquire.cta.shared::cta.b64 p, [%1], %2;\n\t" \
        "selp.b32 %0, 1, 0, p;\n\t}" : "=r"(_d) : "r"(_m), "r"(_p) : "memory"); \
    if (!_d) { \
        asm volatile("{\n\t.reg .pred P1;\n\tWL_%=:\n\t" \
            "mbarrier.try_wait.parity.acquire.cta.shared::cta.b64 P1, [%0], %1, 0x989680;\n\t" \
            "@P1 bra.uni WD_%=;\n\tbra.uni WL_%=;\n\tWD_%=:\n\t}" \
            :: "r"(_m), "r"(_p) : "memory"); \
    } } while (0)
#define BULK_G2S(dst, src, sz, mbar) \
    asm volatile("cp.async.bulk.shared::cluster.global.mbarrier::complete_tx::bytes [%0], [%1], %2, [%3];" \
        :: "r"((uint32_t)(dst)), "l"(src), "r"((uint32_t)(sz)), "r"((uint32_t)(mbar)) : "memory")

// ---------------- grid barrier ----------------
__device__ __forceinline__ void gridbar(unsigned& epoch) {
    epoch++;
    __threadfence();
    __syncthreads();
    if (blockIdx.x == 0) {
        if (threadIdx.x == 0) g_arrive[0] = epoch;
        for (int b = threadIdx.x; b < (int)gridDim.x; b += blockDim.x) {
            while (g_arrive[b] < epoch) { __nanosleep(32); }
        }
        __syncthreads();
        if (threadIdx.x == 0) { __threadfence(); g_release = epoch; }
    } else {
        if (threadIdx.x == 0) {
            g_arrive[blockIdx.x] = epoch;
            while (g_release < epoch) { __nanosleep(32); }
        }
    }
    __syncthreads();
}

__device__ __forceinline__ float sigm(float x) { return 1.f / (1.f + expf(-x)); }
__device__ __forceinline__ void split1(float v, bf16& h, bf16& l) {
    h = __float2bfloat16_rn(v);
    l = __float2bfloat16_rn(v - __bfloat162float(h));
}

// pack activation offset: (row 0..511, col) -> packed elem index
__device__ __forceinline__ size_t pk_off(int row, int col) {
    return ((size_t)((col >> 6) * 4 + (row >> 7))) * ABLK + (size_t)(row & 127) * LDA + (col & 63);
}

// ---------------- S0 weight packer ----------------
__device__ void pack_w(const float* __restrict__ W, bf16* __restrict__ hi, bf16* __restrict__ lo,
                       int K, int BN, int ntiles, int gated, int gt, int gs)
{
    const int nch = K >> 6;
    const int tot = ntiles * nch * BN * 16;   // float4 units
    for (int i = gt; i < tot; i += gs) {
        int k4 = i & 15;
        int rest = i >> 4;
        int n = rest % BN; rest /= BN;
        int c = rest % nch;
        int nt = rest / nch;
        int row = gated ? ((n >> 5) * HID + nt * 32 + (n & 31)) : (nt * BN + n);
        float4 v = *(const float4*)(W + (size_t)row * K + c * 64 + k4 * 4);
        bf16 h[4], l[4];
        split1(v.x, h[0], l[0]); split1(v.y, h[1], l[1]);
        split1(v.z, h[2], l[2]); split1(v.w, h[3], l[3]);
        size_t d = ((size_t)(nt * nch + c) * BN + n) * LDA + k4 * 4;
        *(uint2*)(hi + d) = *(uint2*)h;
        *(uint2*)(lo + d) = *(uint2*)l;
    }
}

// ---------------- pipeline state ----------------
struct Pipe {
    int fullph[NSTAGE];
    int emptyph[NSTAGE];
    int pcnt, ccnt;
};
struct Seg { const bf16 *ah, *al, *bh, *bl; int nch, astr, bstr; };

// ---------------- 3-stage mbar-pipelined wmma GEMM ----------------
// Block tile 128 x 64*NF, 16 warps (wm 0..3 rows x wn 0..3 cols), warp tile 32 x 16*NF.
// No __syncthreads in the loop: full/empty mbarriers pace warps independently.
template <int NF>
__device__ void gemm_pk(CFrag (&acc)[2][NF], char* P, uint32_t pbase,
                        const Seg* segs, int nseg, Pipe& pp)
{
    constexpr int BB = NF * 64 * 144;                 // B plane bytes
    constexpr uint32_t TX = 2 * ABLKB + 2 * BB;
    const int tid = threadIdx.x;
    const int warp = tid >> 5, lane = tid & 31;
    const int wm = warp >> 2, wn = warp & 3;

    int nt = 0;
    for (int s = 0; s < nseg; s++) nt += segs[s].nch;

    auto do_fill = [&](int gidx) {
        int c = gidx, si = 0;
        while (c >= segs[si].nch) { c -= segs[si].nch; si++; }
        const Seg& S = segs[si];
        int st = pp.pcnt % NSTAGE;
        if (tid == 0) {
            MBAR_WAIT(pbase + 24 + (st << 3), (uint32_t)(pp.emptyph[st] & 1));
            uint32_t d = pbase + 1024 + st * STGMAX;
            uint32_t mb = pbase + (st << 3);
            MBAR_EXPECT(mb, TX);
            BULK_G2S(d,                  (const char*)(S.ah + (size_t)c * S.astr), ABLKB, mb);
            BULK_G2S(d + ABLKB,          (const char*)(S.al + (size_t)c * S.astr), ABLKB, mb);
            BULK_G2S(d + 2 * ABLKB,      (const char*)(S.bh + (size_t)c * S.bstr), BB, mb);
            BULK_G2S(d + 2 * ABLKB + BB, (const char*)(S.bl + (size_t)c * S.bstr), BB, mb);
        }
        pp.emptyph[st]++;
        pp.pcnt++;
    };

    const int pre = nt < 2 ? nt : 2;
    for (int g = 0; g < pre; g++) do_fill(g);

    for (int i = 0; i < nt; i++) {
        if (i + 2 < nt) do_fill(i + 2);
        const int st = pp.ccnt % NSTAGE;
        MBAR_WAIT(pbase + (st << 3), (uint32_t)(pp.fullph[st] & 1));
        pp.fullph[st]++;
        pp.ccnt++;

        const bf16* sAh = (const bf16*)(P + 1024 + st * STGMAX);
        const bf16* sAl = sAh + ABLK;
        const bf16* sBh = sAl + ABLK;
        const bf16* sBl = sBh + NF * 64 * LDA;
        #pragma unroll
        for (int kk = 0; kk < 4; kk++) {
            AFrag ah0, ah1, al0, al1;
            wmma::load_matrix_sync(ah0, sAh + (wm * 32 + 0)  * LDA + kk * 16, LDA);
            wmma::load_matrix_sync(ah1, sAh + (wm * 32 + 16) * LDA + kk * 16, LDA);
            wmma::load_matrix_sync(al0, sAl + (wm * 32 + 0)  * LDA + kk * 16, LDA);
            wmma::load_matrix_sync(al1, sAl + (wm * 32 + 16) * LDA + kk * 16, LDA);
            #pragma unroll
            for (int nf = 0; nf < NF; nf++) {
                BFrag bh, bl;
                int cb = wn * (16 * NF) + nf * 16;
                wmma::load_matrix_sync(bh, sBh + cb * LDA + kk * 16, LDA);
                wmma::load_matrix_sync(bl, sBl + cb * LDA + kk * 16, LDA);
                wmma::mma_sync(acc[0][nf], ah0, bl, acc[0][nf]);
                wmma::mma_sync(acc[1][nf], ah1, bl, acc[1][nf]);
                wmma::mma_sync(acc[0][nf], al0, bh, acc[0][nf]);
                wmma::mma_sync(acc[1][nf], al1, bh, acc[1][nf]);
                wmma::mma_sync(acc[0][nf], ah0, bh, acc[0][nf]);
                wmma::mma_sync(acc[1][nf], ah1, bh, acc[1][nf]);
            }
        }
        if (lane == 0) MBAR_ARRIVE(pbase + 24 + (st << 3));
    }
}

// ---------------- epilogues (syncthreads at entry: patch aliases stage smem) ----------------
__device__ void lstm_epi(CFrag (&acc)[2][2], char* P, const float* __restrict__ bias,
                         const float* __restrict__ c_in, float* __restrict__ c_out,
                         bf16* __restrict__ hp_hi, bf16* __restrict__ hp_lo,
                         int mbase, int jbase)
{
    __syncthreads();                      // lagging warps may still read stage 0
    float* pf = (float*)(P + 1024);       // patch [128][132]
    const int tid = threadIdx.x, warp = tid >> 5;
    const int wm = warp >> 2, wn = warp & 3;
    #pragma unroll
    for (int i = 0; i < 2; i++)
        #pragma unroll
        for (int nf = 0; nf < 2; nf++)
            wmma::store_matrix_sync(pf + (wm * 32 + i * 16) * 132 + wn * 32 + nf * 16,
                                    acc[i][nf], 132, wmma::mem_row_major);
    __syncthreads();
    for (int e = tid; e < 128 * 32; e += NTHREADS) {
        int r = e >> 5, j = e & 31;
        int row = mbase + r, col = jbase + j;
        float iv = pf[r * 132 + j]      + __ldg(bias + col);
        float fv = pf[r * 132 + 32 + j] + __ldg(bias + HID + col);
        float gv = pf[r * 132 + 64 + j] + __ldg(bias + 2 * HID + col);
        float ov = pf[r * 132 + 96 + j] + __ldg(bias + 3 * HID + col);
        float cold = __ldcg(c_in + (size_t)row * HID + col);
        float cn = sigm(fv) * cold + sigm(iv) * tanhf(gv);
        float hn = sigm(ov) * tanhf(cn);
        c_out[(size_t)row * HID + col] = cn;
        bf16 hh, hl; split1(hn, hh, hl);
        size_t off = pk_off(row, col);
        hp_hi[off] = hh;
        hp_lo[off] = hl;
    }
    __syncthreads();
}

template <int NF>
__device__ void store_epi(CFrag (&acc)[2][NF], char* P, const float* __restrict__ bias,
                          float* __restrict__ dst, int stride, int mbase, int nbase)
{
    __syncthreads();
    constexpr int BN = 64 * NF, PS = BN + 4;
    float* pf = (float*)(P + 1024);
    const int tid = threadIdx.x, warp = tid >> 5;
    const int wm = warp >> 2, wn = warp & 3;
    #pragma unroll
    for (int i = 0; i < 2; i++)
        #pragma unroll
        for (int nf = 0; nf < NF; nf++)
            wmma::store_matrix_sync(pf + (wm * 32 + i * 16) * PS + wn * (16 * NF) + nf * 16,
                                    acc[i][nf], PS, wmma::mem_row_major);
    __syncthreads();
    for (int e = tid; e < 128 * BN; e += NTHREADS) {
        int r = e / BN, c = e % BN;
        dst[(size_t)(mbase + r) * stride + nbase + c] = pf[r * PS + c] + __ldg(bias + nbase + c);
    }
    __syncthreads();
}

// ---------------- the persistent decoder kernel ----------------
__global__ void __launch_bounds__(NTHREADS, 1) dec_kernel(
    const float* __restrict__ z,     const float* __restrict__ lin1_w, const float* __restrict__ lin1_b,
    const float* __restrict__ ln1_w, const float* __restrict__ ln1_b,
    const float* __restrict__ w_ih0, const float* __restrict__ w_hh0,  const float* __restrict__ b0,
    const float* __restrict__ w_ih1, const float* __restrict__ w_hh1,  const float* __restrict__ b1,
    const float* __restrict__ p1_w,  const float* __restrict__ p1_b,
    const float* __restrict__ pln_w, const float* __restrict__ pln_b,
    const float* __restrict__ p2_w,  const float* __restrict__ p2_b,
    float* __restrict__ out)
{
    extern __shared__ char pool[];
    __shared__ float redA[16], redB[16];
    const int bid = blockIdx.x, nb = gridDim.x, tid = threadIdx.x;
    const int lane = tid & 31;
    uint32_t raw = smem_u32(pool);
    uint32_t pbase = (raw + 1023) & ~1023u;
    char* P = pool + (pbase - raw);
    unsigned epoch = g_release;
    Pipe pp;
    #pragma unroll
    for (int s = 0; s < NSTAGE; s++) { pp.fullph[s] = 0; pp.emptyph[s] = 0; }
    pp.pcnt = 0; pp.ccnt = 0;

    if (tid == 0) {
        #pragma unroll
        for (int s = 0; s < NSTAGE; s++) {
            MBAR_INIT(pbase + (s << 3), 1);        // full: tx-based
            MBAR_INIT(pbase + 24 + (s << 3), 16);  // empty: one arrive per warp
        }
    }
    __syncthreads();
    if (lane == 0) {   // arm all empties (16 warps x lane0 = 16 arrivals each)
        MBAR_ARRIVE(pbase + 24);
        MBAR_ARRIVE(pbase + 32);
        MBAR_ARRIVE(pbase + 40);
    }
    __syncthreads();

    // ---- S0: pack weights; pack z; zero x
    {
        int gt = bid * NTHREADS + tid, gs = nb * NTHREADS;
        pack_w(lin1_w, g_lin1p[0], g_lin1p[1], LATENT, 64, 32, 0, gt, gs);
        pack_w(w_ih0,  g_wih0p[0], g_wih0p[1], NOUT, 128, 32, 1, gt, gs);
        pack_w(w_hh0,  g_whh0p[0], g_whh0p[1], HID, 128, 32, 1, gt, gs);
        pack_w(w_ih1,  g_wih1p[0], g_wih1p[1], HID, 128, 32, 1, gt, gs);
        pack_w(w_hh1,  g_whh1p[0], g_whh1p[1], HID, 128, 32, 1, gt, gs);
        pack_w(p1_w,   g_p1p[0],   g_p1p[1],   HID, 64, 16, 0, gt, gs);
        for (int i = gt; i < 4 * 4 * 128 * 16; i += gs) {
            int k4 = i & 15, r = (i >> 4) & 127, mg = (i >> 11) & 3, c = i >> 13;
            float4 v = *(const float4*)(z + (size_t)(mg * 128 + r) * LATENT + c * 64 + k4 * 4);
            bf16 h[4], l[4];
            split1(v.x, h[0], l[0]); split1(v.y, h[1], l[1]);
            split1(v.z, h[2], l[2]); split1(v.w, h[3], l[3]);
            size_t d = (size_t)(c * 4 + mg) * ABLK + (size_t)r * LDA + k4 * 4;
            *(uint2*)(g_zp[0] + d) = *(uint2*)h;
            *(uint2*)(g_zp[1] + d) = *(uint2*)l;
        }
        for (int i = gt; i < 2 * 4 * ABLK; i += gs) {
            g_xp[0][i] = __float2bfloat16_rn(0.f);
            g_xp[1][i] = __float2bfloat16_rn(0.f);
        }
    }
    gridbar(epoch);

    // ---- S1: u = z @ lin1_w^T + lin1_b  (512 x 2048): 128 tiles of 128x64
    if (bid < 128) {
        int mg = bid >> 5, nt = bid & 31;
        CFrag acc[2][1];
        wmma::fill_fragment(acc[0][0], 0.f);
        wmma::fill_fragment(acc[1][0], 0.f);
        Seg sg[1] = {{g_zp[0] + (size_t)mg * ABLK, g_zp[1] + (size_t)mg * ABLK,
                      g_lin1p[0] + (size_t)nt * 4 * 4608, g_lin1p[1] + (size_t)nt * 4 * 4608,
                      4, 4 * ABLK, 4608}};
        gemm_pk<1>(acc, P, pbase, sg, 1, pp);
        store_epi<1>(acc, P, lin1_b, g_u, 2 * HID, mg << 7, nt << 6);
    }
    gridbar(epoch);

    // ---- S2: LayerNorm(2048) + gelu -> h0/c0 (both cells)
    {
        float* pf = (float*)(P + 1024);
        const int g = tid >> 7, lt = tid & 127, w4 = (tid >> 5) & 3;
        for (int grp = bid; grp < 128; grp += nb) {
            int row = (grp << 2) + g;
            const float* urow = g_u + (size_t)row * 2 * HID;
            float ls = 0.f, lq = 0.f;
            #pragma unroll
            for (int u = 0; u < 16; u++) {
                float v = __ldcg(urow + u * 128 + lt);
                pf[g * 2048 + u * 128 + lt] = v;
                ls += v; lq += v * v;
            }
            #pragma unroll
            for (int o = 16; o > 0; o >>= 1) {
                ls += __shfl_down_sync(0xffffffffu, ls, o);
                lq += __shfl_down_sync(0xffffffffu, lq, o);
            }
            if (lane == 0) { redA[g * 4 + w4] = ls; redB[g * 4 + w4] = lq; }
            __syncthreads();
            float S = redA[g * 4] + redA[g * 4 + 1] + redA[g * 4 + 2] + redA[g * 4 + 3];
            float Q = redB[g * 4] + redB[g * 4 + 1] + redB[g * 4 + 2] + redB[g * 4 + 3];
            float mu = S * (1.f / 2048.f);
            float rstd = rsqrtf(Q * (1.f / 2048.f) - mu * mu + 1e-5f);
            #pragma unroll
            for (int u = 0; u < 16; u++) {
                int i = u * 128 + lt;
                float v = (pf[g * 2048 + i] - mu) * rstd * __ldg(ln1_w + i) + __ldg(ln1_b + i);
                float ge = v * normcdff(v);
                if (i < HID) {
                    bf16 hh, hl; split1(ge, hh, hl);
                    size_t off = pk_off(row, i);
                    g_h1p[0][0][off] = hh; g_h1p[0][1][off] = hl;
                    g_h2p[0][0][off] = hh; g_h2p[0][1][off] = hl;
                } else {
                    g_c1[0][(size_t)row * HID + i - HID] = ge;
                    g_c2[0][(size_t)row * HID + i - HID] = ge;
                }
            }
            __syncthreads();
        }
    }
    gridbar(epoch);

    // ---- main sequential loop
    for (int s = 0; s < SEQL; s++) {
        const int pi = s & 1, po = pi ^ 1;
        const int mg = (bid >> 5) & 3, ntl = bid & 31;

        // P1: (h1,c1) = lstm0(x, h1, c1) : K = 128 + 1024 (18 chunks streamed)
        if (bid < 128) {
            CFrag acc[2][2];
            #pragma unroll
            for (int i = 0; i < 2; i++) { wmma::fill_fragment(acc[i][0], 0.f); wmma::fill_fragment(acc[i][1], 0.f); }
            Seg sg[2] = {
                {g_xp[0] + (size_t)mg * ABLK, g_xp[1] + (size_t)mg * ABLK,
                 g_wih0p[0] + (size_t)ntl * 2 * 9216, g_wih0p[1] + (size_t)ntl * 2 * 9216,
                 2, 4 * ABLK, 9216},
                {g_h1p[pi][0] + (size_t)mg * ABLK, g_h1p[pi][1] + (size_t)mg * ABLK,
                 g_whh0p[0] + (size_t)ntl * 16 * 9216, g_whh0p[1] + (size_t)ntl * 16 * 9216,
                 16, 4 * ABLK, 9216}};
            gemm_pk<2>(acc, P, pbase, sg, 2, pp);
            lstm_epi(acc, P, b0, g_c1[pi], g_c1[po], g_h1p[po][0], g_h1p[po][1], mg << 7, ntl << 5);
        }
        gridbar(epoch);

        // P2: (h2,c2) = lstm1(h1_new, h2, c2) : K = 1024 + 1024 (32 chunks)
        if (bid < 128) {
            CFrag acc[2][2];
            #pragma unroll
            for (int i = 0; i < 2; i++) { wmma::fill_fragment(acc[i][0], 0.f); wmma::fill_fragment(acc[i][1], 0.f); }
            Seg sg[2] = {
                {g_h1p[po][0] + (size_t)mg * ABLK, g_h1p[po][1] + (size_t)mg * ABLK,
                 g_wih1p[0] + (size_t)ntl * 16 * 9216, g_wih1p[1] + (size_t)ntl * 16 * 9216,
                 16, 4 * ABLK, 9216},
                {g_h2p[pi][0] + (size_t)mg * ABLK, g_h2p[pi][1] + (size_t)mg * ABLK,
                 g_whh1p[0] + (size_t)ntl * 16 * 9216, g_whh1p[1] + (size_t)ntl * 16 * 9216,
                 16, 4 * ABLK, 9216}};
            gemm_pk<2>(acc, P, pbase, sg, 2, pp);
            lstm_epi(acc, P, b1, g_c2[pi], g_c2[po], g_h2p[po][0], g_h2p[po][1], mg << 7, ntl << 5);
        }
        gridbar(epoch);

        // P3: t = h2_new @ p1_w^T + p1_b : 64 tiles of 128x64
        if (bid < 64) {
            int mg3 = bid >> 4, nt3 = bid & 15;
            CFrag acc[2][1];
            wmma::fill_fragment(acc[0][0], 0.f);
            wmma::fill_fragment(acc[1][0], 0.f);
            Seg sg[1] = {{g_h2p[po][0] + (size_t)mg3 * ABLK, g_h2p[po][1] + (size_t)mg3 * ABLK,
                          g_p1p[0] + (size_t)nt3 * 16 * 4608, g_p1p[1] + (size_t)nt3 * 16 * 4608,
                          16, 4 * ABLK, 4608}};
            gemm_pk<1>(acc, P, pbase, sg, 1, pp);
            store_epi<1>(acc, P, p1_b, g_t, HID, mg3 << 7, nt3 << 6);
        }
        gridbar(epoch);

        // P4: 4 rows in parallel: LayerNorm + gelu + y = g @ p2_w^T + p2_b
        {
            float* pf = (float*)(P + 1024);   // 4 groups x 1024 floats
            const int g = tid >> 7, lt = tid & 127, w4 = (tid >> 5) & 3;
            for (int grp = bid; grp < 128; grp += nb) {
                int row = (grp << 2) + g;
                const float* trow = g_t + (size_t)row * HID;
                float vb[8]; float ls = 0.f, lq = 0.f;
                #pragma unroll
                for (int u = 0; u < 8; u++) {
                    float v = __ldcg(trow + u * 128 + lt);
                    vb[u] = v; ls += v; lq += v * v;
                }
                #pragma unroll
                for (int o = 16; o > 0; o >>= 1) {
                    ls += __shfl_down_sync(0xffffffffu, ls, o);
                    lq += __shfl_down_sync(0xffffffffu, lq, o);
                }
                if (lane == 0) { redA[g * 4 + w4] = ls; redB[g * 4 + w4] = lq; }
                __syncthreads();
                float S = redA[g * 4] + redA[g * 4 + 1] + redA[g * 4 + 2] + redA[g * 4 + 3];
                float Q = redB[g * 4] + redB[g * 4 + 1] + redB[g * 4 + 2] + redB[g * 4 + 3];
                float mu = S * (1.f / 1024.f);
                float rstd = rsqrtf(Q * (1.f / 1024.f) - mu * mu + 1e-5f);
                #pragma unroll
                for (int u = 0; u < 8; u++) {
                    int i = u * 128 + lt;
                    float v = (vb[u] - mu) * rstd * __ldg(pln_w + i) + __ldg(pln_b + i);
                    pf[g * 1024 + i] = v * normcdff(v);
                }
                __syncthreads();
                const float* wrow = p2_w + (size_t)lt * HID;
                const float* gv = pf + g * 1024;
                float a = 0.f;
                #pragma unroll 4
                for (int k = 0; k < 1024; k += 4) {
                    float4 wv = *(const float4*)(wrow + k);
                    float4 g4 = *(const float4*)(gv + k);
                    a += g4.x * wv.x + g4.y * wv.y + g4.z * wv.z + g4.w * wv.w;
                }
                float y = a + __ldg(p2_b + lt);
                bf16 xh, xl; split1(y, xh, xl);
                size_t off = pk_off(row, lt);
                g_xp[0][off] = xh;
                g_xp[1][off] = xl;
                out[(size_t)row * SEQL * NOUT + s * NOUT + lt] = y;
                __syncthreads();
            }
        }
        gridbar(epoch);
    }
}

// ---------------- launch ----------------
extern "C" void kernel_launch(void* const* d_in, const int* in_sizes, int n_in,
                              void* d_out, int out_size) {
    (void)in_sizes; (void)n_in; (void)out_size;
    int nsm = 0;
    cudaDeviceGetAttribute(&nsm, cudaDevAttrMultiProcessorCount, 0);
    if (nsm <= 0) nsm = 148;
    if (nsm > 256) nsm = 256;
    cudaFuncSetAttribute(dec_kernel, cudaFuncAttributeMaxDynamicSharedMemorySize, SMEM_BYTES);

    const float* z      = (const float*)d_in[0];
    const float* lin1_w = (const float*)d_in[1];
    const float* lin1_b = (const float*)d_in[2];
    const float* ln1_w  = (const float*)d_in[3];
    const float* ln1_b  = (const float*)d_in[4];
    const float* w_ih0  = (const float*)d_in[5];
    const float* w_hh0  = (const float*)d_in[6];
    const float* b0     = (const float*)d_in[7];
    const float* w_ih1  = (const float*)d_in[8];
    const float* w_hh1  = (const float*)d_in[9];
    const float* b1     = (const float*)d_in[10];
    const float* p1_w   = (const float*)d_in[11];
    const float* p1_b   = (const float*)d_in[12];
    const float* pln_w  = (const float*)d_in[13];
    const float* pln_b  = (const float*)d_in[14];
    const float* p2_w   = (const float*)d_in[15];
    const float* p2_b   = (const float*)d_in[16];

    dec_kernel<<<nsm, NTHREADS, SMEM_BYTES>>>(
        z, lin1_w, lin1_b, ln1_w, ln1_b,
        w_ih0, w_hh0, b0, w_ih1, w_hh1, b1,
        p1_w, p1_b, pln_w, pln_b, p2_w, p2_b,
        (float*)d_out);
}

// round 7
// speedup vs baseline: 5.6702x; 1.2067x over previous
#include <cuda_runtime.h>
#include <cuda_bf16.h>
#include <mma.h>
#include <math.h>
#include <stdint.h>

using namespace nvcuda;
using bf16 = __nv_bfloat16;

#define LATENT 256
#define HID    1024
#define NOUT   128
#define SEQL   96

#define NTHREADS 256
#define LDA    72
#define ABLK   9216          // elems per 128x72 block
#define ABLKB  18432         // bytes per 128x72 bf16 block
#define NSTAGE 3
#define STGMAX 73728         // bytes per stage buffer (max: NFW=4)

// smem: 1024 align slack + 1024 hdr (mbars) + 3 stage buffers
#define SMEM_BYTES (1024 + 1024 + NSTAGE * STGMAX)

// ---------------- device scratch (packed layouts) ----------------
__device__ __align__(16) bf16 g_lin1p[2][32 * 4 * 4608];     // BN=64, K=256
__device__ __align__(16) bf16 g_wih0p[2][32 * 2 * 9216];     // BN=128 gated, K=128
__device__ __align__(16) bf16 g_whh0p[2][32 * 16 * 9216];    // BN=128 gated, K=1024
__device__ __align__(16) bf16 g_wih1p[2][32 * 16 * 9216];
__device__ __align__(16) bf16 g_whh1p[2][32 * 16 * 9216];
__device__ __align__(16) bf16 g_p1p[2][16 * 16 * 4608];      // BN=64, K=1024
__device__ __align__(16) float4 g_p2q[256 * 128];            // p2_w transposed k-quad major
// activations packed as [plane][kchunk][mgroup][128 x 72]
__device__ __align__(16) bf16 g_zp[2][4 * 4 * 9216];
__device__ __align__(16) bf16 g_xp[2][2 * 4 * 9216];
__device__ __align__(16) bf16 g_h1p[2][2][16 * 4 * 9216];    // [pingpong][plane]
__device__ __align__(16) bf16 g_h2p[2][2][16 * 4 * 9216];
__device__ float g_c1[2][512 * HID];
__device__ float g_c2[2][512 * HID];
__device__ float g_u[512 * 2 * HID];
__device__ float g_t[512 * HID];
__device__ volatile unsigned g_arrive[256];
__device__ volatile unsigned g_release;

typedef wmma::fragment<wmma::accumulator, 16, 16, 16, float> CFrag;
typedef wmma::fragment<wmma::matrix_a, 16, 16, 16, bf16, wmma::row_major> AFrag;
typedef wmma::fragment<wmma::matrix_b, 16, 16, 16, bf16, wmma::col_major> BFrag;

// ---------------- PTX helpers ----------------
__device__ __forceinline__ uint32_t smem_u32(const void* p) {
    uint32_t a;
    asm("{ .reg .u64 t; cvta.to.shared.u64 t, %1; cvt.u32.u64 %0, t; }" : "=r"(a) : "l"(p));
    return a;
}
#define MBAR_INIT(a, c) \
    asm volatile("mbarrier.init.shared.b64 [%0], %1;" :: "r"(a), "r"((uint32_t)(c)) : "memory")
#define MBAR_EXPECT(a, n) \
    asm volatile("mbarrier.arrive.expect_tx.shared.b64 _, [%0], %1;" :: "r"(a), "r"((uint32_t)(n)) : "memory")
#define MBAR_ARRIVE(a) \
    asm volatile("mbarrier.arrive.shared.b64 _, [%0];" :: "r"((uint32_t)(a)) : "memory")
#define MBAR_WAIT(a, par) do { \
    uint32_t _m = (a), _p = (par), _d; \
    asm volatile("{\n\t.reg .pred p;\n\t" \
        "mbarrier.try_wait.parity.acquire.cta.shared::cta.b64 p, [%1], %2;\n\t" \
        "selp.b32 %0, 1, 0, p;\n\t}" : "=r"(_d) : "r"(_m), "r"(_p) : "memory"); \
    if (!_d) { \
        asm volatile("{\n\t.reg .pred P1;\n\tWL_%=:\n\t" \
            "mbarrier.try_wait.parity.acquire.cta.shared::cta.b64 P1, [%0], %1, 0x989680;\n\t" \
            "@P1 bra.uni WD_%=;\n\tbra.uni WL_%=;\n\tWD_%=:\n\t}" \
            :: "r"(_m), "r"(_p) : "memory"); \
    } } while (0)
#define BULK_G2S(dst, src, sz, mbar) \
    asm volatile("cp.async.bulk.shared::cluster.global.mbarrier::complete_tx::bytes [%0], [%1], %2, [%3];" \
        :: "r"((uint32_t)(dst)), "l"(src), "r"((uint32_t)(sz)), "r"((uint32_t)(mbar)) : "memory")

// ---------------- grid barrier ----------------
__device__ __forceinline__ void gridbar(unsigned& epoch) {
    epoch++;
    __threadfence();
    __syncthreads();
    if (blockIdx.x == 0) {
        if (threadIdx.x == 0) g_arrive[0] = epoch;
        for (int b = threadIdx.x; b < (int)gridDim.x; b += blockDim.x) {
            while (g_arrive[b] < epoch) { __nanosleep(32); }
        }
        __syncthreads();
        if (threadIdx.x == 0) { __threadfence(); g_release = epoch; }
    } else {
        if (threadIdx.x == 0) {
            g_arrive[blockIdx.x] = epoch;
            while (g_release < epoch) { __nanosleep(32); }
        }
    }
    __syncthreads();
}

// fast activations (~1e-6 rel err)
__device__ __forceinline__ float sigm(float x) {
    return __fdividef(1.f, 1.f + __expf(-x));
}
__device__ __forceinline__ float tanh_f(float x) {
    float e = __expf(2.f * x);
    return 1.f - __fdividef(2.f, e + 1.f);
}
__device__ __forceinline__ void split1(float v, bf16& h, bf16& l) {
    h = __float2bfloat16_rn(v);
    l = __float2bfloat16_rn(v - __bfloat162float(h));
}

// pack activation offset: (row 0..511, col) -> packed elem index
__device__ __forceinline__ size_t pk_off(int row, int col) {
    return ((size_t)((col >> 6) * 4 + (row >> 7))) * ABLK + (size_t)(row & 127) * LDA + (col & 63);
}

// ---------------- S0 weight packer ----------------
__device__ void pack_w(const float* __restrict__ W, bf16* __restrict__ hi, bf16* __restrict__ lo,
                       int K, int BN, int ntiles, int gated, int gt, int gs)
{
    const int nch = K >> 6;
    const int tot = ntiles * nch * BN * 16;   // float4 units
    for (int i = gt; i < tot; i += gs) {
        int k4 = i & 15;
        int rest = i >> 4;
        int n = rest % BN; rest /= BN;
        int c = rest % nch;
        int nt = rest / nch;
        int row = gated ? ((n >> 5) * HID + nt * 32 + (n & 31)) : (nt * BN + n);
        float4 v = *(const float4*)(W + (size_t)row * K + c * 64 + k4 * 4);
        bf16 h[4], l[4];
        split1(v.x, h[0], l[0]); split1(v.y, h[1], l[1]);
        split1(v.z, h[2], l[2]); split1(v.w, h[3], l[3]);
        size_t d = ((size_t)(nt * nch + c) * BN + n) * LDA + k4 * 4;
        *(uint2*)(hi + d) = *(uint2*)h;
        *(uint2*)(lo + d) = *(uint2*)l;
    }
}

// ---------------- pipeline state ----------------
struct Pipe {
    int fullph[NSTAGE];
    int emptyph[NSTAGE];
    int pcnt, ccnt;
};
struct Seg { const bf16 *ah, *al, *bh, *bl; int nch, astr, bstr; };

// ---------------- 3-stage mbar-pipelined wmma GEMM ----------------
// 8 warps: wm = warp>>1 (4 row groups of 32), wn = warp&1 (2 col groups of 16*NFW).
// Block tile 128 x 32*NFW*... (BN = 32*NFW). Warp tile 32 x 16*NFW.
template <int NFW>
__device__ void gemm_pk(CFrag (&acc)[2][NFW], char* P, uint32_t pbase,
                        const Seg* segs, int nseg, Pipe& pp)
{
    constexpr int BB = 32 * NFW * 144;                // B plane bytes
    constexpr uint32_t TX = 2 * ABLKB + 2 * BB;
    const int tid = threadIdx.x;
    const int warp = tid >> 5, lane = tid & 31;
    const int wm = warp >> 1, wn = warp & 1;

    int nt = 0;
    for (int s = 0; s < nseg; s++) nt += segs[s].nch;

    auto do_fill = [&](int gidx) {
        int c = gidx, si = 0;
        while (c >= segs[si].nch) { c -= segs[si].nch; si++; }
        const Seg& S = segs[si];
        int st = pp.pcnt % NSTAGE;
        if (tid == 0) {
            MBAR_WAIT(pbase + 24 + (st << 3), (uint32_t)(pp.emptyph[st] & 1));
            uint32_t d = pbase + 1024 + st * STGMAX;
            uint32_t mb = pbase + (st << 3);
            MBAR_EXPECT(mb, TX);
            BULK_G2S(d,                  (const char*)(S.ah + (size_t)c * S.astr), ABLKB, mb);
            BULK_G2S(d + ABLKB,          (const char*)(S.al + (size_t)c * S.astr), ABLKB, mb);
            BULK_G2S(d + 2 * ABLKB,      (const char*)(S.bh + (size_t)c * S.bstr), BB, mb);
            BULK_G2S(d + 2 * ABLKB + BB, (const char*)(S.bl + (size_t)c * S.bstr), BB, mb);
        }
        pp.emptyph[st]++;
        pp.pcnt++;
    };

    const int pre = nt < 2 ? nt : 2;
    for (int g = 0; g < pre; g++) do_fill(g);

    for (int i = 0; i < nt; i++) {
        if (i + 2 < nt) do_fill(i + 2);
        const int st = pp.ccnt % NSTAGE;
        MBAR_WAIT(pbase + (st << 3), (uint32_t)(pp.fullph[st] & 1));
        pp.fullph[st]++;
        pp.ccnt++;

        const bf16* sAh = (const bf16*)(P + 1024 + st * STGMAX);
        const bf16* sAl = sAh + ABLK;
        const bf16* sBh = sAl + ABLK;
        const bf16* sBl = sBh + 32 * NFW * LDA;
        #pragma unroll
        for (int kk = 0; kk < 4; kk++) {
            AFrag ah0, ah1, al0, al1;
            wmma::load_matrix_sync(ah0, sAh + (wm * 32 + 0)  * LDA + kk * 16, LDA);
            wmma::load_matrix_sync(ah1, sAh + (wm * 32 + 16) * LDA + kk * 16, LDA);
            wmma::load_matrix_sync(al0, sAl + (wm * 32 + 0)  * LDA + kk * 16, LDA);
            wmma::load_matrix_sync(al1, sAl + (wm * 32 + 16) * LDA + kk * 16, LDA);
            #pragma unroll
            for (int nf = 0; nf < NFW; nf++) {
                BFrag bh, bl;
                int cb = wn * (16 * NFW) + nf * 16;
                wmma::load_matrix_sync(bh, sBh + cb * LDA + kk * 16, LDA);
                wmma::load_matrix_sync(bl, sBl + cb * LDA + kk * 16, LDA);
                wmma::mma_sync(acc[0][nf], ah0, bl, acc[0][nf]);
                wmma::mma_sync(acc[1][nf], ah1, bl, acc[1][nf]);
                wmma::mma_sync(acc[0][nf], al0, bh, acc[0][nf]);
                wmma::mma_sync(acc[1][nf], al1, bh, acc[1][nf]);
                wmma::mma_sync(acc[0][nf], ah0, bh, acc[0][nf]);
                wmma::mma_sync(acc[1][nf], ah1, bh, acc[1][nf]);
            }
        }
        if (lane == 0) MBAR_ARRIVE(pbase + 24 + (st << 3));
    }
}

// ---------------- epilogues (syncthreads at entry: patch aliases stage smem) ----------------
__device__ void lstm_epi(CFrag (&acc)[2][4], char* P, const float* __restrict__ bias,
                         const float* __restrict__ c_in, float* __restrict__ c_out,
                         bf16* __restrict__ hp_hi, bf16* __restrict__ hp_lo,
                         int mbase, int jbase)
{
    __syncthreads();                      // lagging warps may still read stages
    float* pf = (float*)(P + 1024);       // patch [128][132]
    const int tid = threadIdx.x, warp = tid >> 5;
    const int wm = warp >> 1, wn = warp & 1;
    #pragma unroll
    for (int i = 0; i < 2; i++)
        #pragma unroll
        for (int nf = 0; nf < 4; nf++)
            wmma::store_matrix_sync(pf + (wm * 32 + i * 16) * 132 + wn * 64 + nf * 16,
                                    acc[i][nf], 132, wmma::mem_row_major);
    __syncthreads();
    #pragma unroll 4
    for (int e = tid; e < 128 * 32; e += NTHREADS) {
        int r = e >> 5, j = e & 31;
        int row = mbase + r, col = jbase + j;
        float iv = pf[r * 132 + j]      + __ldg(bias + col);
        float fv = pf[r * 132 + 32 + j] + __ldg(bias + HID + col);
        float gv = pf[r * 132 + 64 + j] + __ldg(bias + 2 * HID + col);
        float ov = pf[r * 132 + 96 + j] + __ldg(bias + 3 * HID + col);
        float cold = __ldcg(c_in + (size_t)row * HID + col);
        float cn = sigm(fv) * cold + sigm(iv) * tanh_f(gv);
        float hn = sigm(ov) * tanh_f(cn);
        c_out[(size_t)row * HID + col] = cn;
        bf16 hh, hl; split1(hn, hh, hl);
        size_t off = pk_off(row, col);
        hp_hi[off] = hh;
        hp_lo[off] = hl;
    }
    __syncthreads();
}

template <int NFW>
__device__ void store_epi(CFrag (&acc)[2][NFW], char* P, const float* __restrict__ bias,
                          float* __restrict__ dst, int stride, int mbase, int nbase)
{
    __syncthreads();
    constexpr int BN = 32 * NFW, PS = BN + 4;
    float* pf = (float*)(P + 1024);
    const int tid = threadIdx.x, warp = tid >> 5;
    const int wm = warp >> 1, wn = warp & 1;
    #pragma unroll
    for (int i = 0; i < 2; i++)
        #pragma unroll
        for (int nf = 0; nf < NFW; nf++)
            wmma::store_matrix_sync(pf + (wm * 32 + i * 16) * PS + wn * (16 * NFW) + nf * 16,
                                    acc[i][nf], PS, wmma::mem_row_major);
    __syncthreads();
    for (int e = tid; e < 128 * BN; e += NTHREADS) {
        int r = e / BN, c = e % BN;
        dst[(size_t)(mbase + r) * stride + nbase + c] = pf[r * PS + c] + __ldg(bias + nbase + c);
    }
    __syncthreads();
}

// ---------------- the persistent decoder kernel ----------------
__global__ void __launch_bounds__(NTHREADS, 1) dec_kernel(
    const float* __restrict__ z,     const float* __restrict__ lin1_w, const float* __restrict__ lin1_b,
    const float* __restrict__ ln1_w, const float* __restrict__ ln1_b,
    const float* __restrict__ w_ih0, const float* __restrict__ w_hh0,  const float* __restrict__ b0,
    const float* __restrict__ w_ih1, const float* __restrict__ w_hh1,  const float* __restrict__ b1,
    const float* __restrict__ p1_w,  const float* __restrict__ p1_b,
    const float* __restrict__ pln_w, const float* __restrict__ pln_b,
    const float* __restrict__ p2_w,  const float* __restrict__ p2_b,
    float* __restrict__ out)
{
    extern __shared__ char pool[];
    __shared__ float redA[8], redB[8];
    const int bid = blockIdx.x, nb = gridDim.x, tid = threadIdx.x;
    const int lane = tid & 31;
    uint32_t raw = smem_u32(pool);
    uint32_t pbase = (raw + 1023) & ~1023u;
    char* P = pool + (pbase - raw);
    unsigned epoch = g_release;
    Pipe pp;
    #pragma unroll
    for (int s = 0; s < NSTAGE; s++) { pp.fullph[s] = 0; pp.emptyph[s] = 0; }
    pp.pcnt = 0; pp.ccnt = 0;

    if (tid == 0) {
        #pragma unroll
        for (int s = 0; s < NSTAGE; s++) {
            MBAR_INIT(pbase + (s << 3), 1);       // full: tx-based
            MBAR_INIT(pbase + 24 + (s << 3), 8);  // empty: one arrive per warp
        }
    }
    __syncthreads();
    if (lane == 0) {   // arm all empties (8 warps x lane0 = 8 arrivals each)
        MBAR_ARRIVE(pbase + 24);
        MBAR_ARRIVE(pbase + 32);
        MBAR_ARRIVE(pbase + 40);
    }
    __syncthreads();

    // ---- S0: pack weights; pack z; transpose p2; zero x
    {
        int gt = bid * NTHREADS + tid, gs = nb * NTHREADS;
        pack_w(lin1_w, g_lin1p[0], g_lin1p[1], LATENT, 64, 32, 0, gt, gs);
        pack_w(w_ih0,  g_wih0p[0], g_wih0p[1], NOUT, 128, 32, 1, gt, gs);
        pack_w(w_hh0,  g_whh0p[0], g_whh0p[1], HID, 128, 32, 1, gt, gs);
        pack_w(w_ih1,  g_wih1p[0], g_wih1p[1], HID, 128, 32, 1, gt, gs);
        pack_w(w_hh1,  g_whh1p[0], g_whh1p[1], HID, 128, 32, 1, gt, gs);
        pack_w(p1_w,   g_p1p[0],   g_p1p[1],   HID, 64, 16, 0, gt, gs);
        for (int i = gt; i < 4 * 4 * 128 * 16; i += gs) {
            int k4 = i & 15, r = (i >> 4) & 127, mg = (i >> 11) & 3, c = i >> 13;
            float4 v = *(const float4*)(z + (size_t)(mg * 128 + r) * LATENT + c * 64 + k4 * 4);
            bf16 h[4], l[4];
            split1(v.x, h[0], l[0]); split1(v.y, h[1], l[1]);
            split1(v.z, h[2], l[2]); split1(v.w, h[3], l[3]);
            size_t d = (size_t)(c * 4 + mg) * ABLK + (size_t)r * LDA + k4 * 4;
            *(uint2*)(g_zp[0] + d) = *(uint2*)h;
            *(uint2*)(g_zp[1] + d) = *(uint2*)l;
        }
        // p2 transposed quads: g_p2q[kq*128 + o] = p2_w[o][4kq..4kq+3]
        for (int i = gt; i < 256 * 128; i += gs) {
            int o = i & 127, kq = i >> 7;
            g_p2q[i] = *(const float4*)(p2_w + (size_t)o * HID + kq * 4);
        }
        for (int i = gt; i < 2 * 4 * ABLK; i += gs) {
            g_xp[0][i] = __float2bfloat16_rn(0.f);
            g_xp[1][i] = __float2bfloat16_rn(0.f);
        }
    }
    gridbar(epoch);

    // ---- S1: u = z @ lin1_w^T + lin1_b  (512 x 2048): 128 tiles of 128x64
    if (bid < 128) {
        int mg = bid >> 5, nt = bid & 31;
        CFrag acc[2][2];
        #pragma unroll
        for (int i = 0; i < 2; i++) { wmma::fill_fragment(acc[i][0], 0.f); wmma::fill_fragment(acc[i][1], 0.f); }
        Seg sg[1] = {{g_zp[0] + (size_t)mg * ABLK, g_zp[1] + (size_t)mg * ABLK,
                      g_lin1p[0] + (size_t)nt * 4 * 4608, g_lin1p[1] + (size_t)nt * 4 * 4608,
                      4, 4 * ABLK, 4608}};
        gemm_pk<2>(acc, P, pbase, sg, 1, pp);
        store_epi<2>(acc, P, lin1_b, g_u, 2 * HID, mg << 7, nt << 6);
    }
    gridbar(epoch);

    // ---- S2: LayerNorm(2048) + gelu -> h0/c0 (both cells), 2 rows per pass
    {
        float* pf = (float*)(P + 1024);
        const int g = tid >> 7, lt = tid & 127, w4 = (tid >> 5) & 3;
        for (int grp = bid; grp < 128; grp += nb) {
            for (int pass = 0; pass < 2; pass++) {
                int row = (grp << 2) + pass * 2 + g;
                const float* urow = g_u + (size_t)row * 2 * HID;
                float ls = 0.f, lq = 0.f;
                #pragma unroll
                for (int u = 0; u < 16; u++) {
                    float v = __ldcg(urow + u * 128 + lt);
                    pf[g * 2048 + u * 128 + lt] = v;
                    ls += v; lq += v * v;
                }
                #pragma unroll
                for (int o = 16; o > 0; o >>= 1) {
                    ls += __shfl_down_sync(0xffffffffu, ls, o);
                    lq += __shfl_down_sync(0xffffffffu, lq, o);
                }
                if (lane == 0) { redA[g * 4 + w4] = ls; redB[g * 4 + w4] = lq; }
                __syncthreads();
                float S = redA[g * 4] + redA[g * 4 + 1] + redA[g * 4 + 2] + redA[g * 4 + 3];
                float Q = redB[g * 4] + redB[g * 4 + 1] + redB[g * 4 + 2] + redB[g * 4 + 3];
                float mu = S * (1.f / 2048.f);
                float rstd = rsqrtf(Q * (1.f / 2048.f) - mu * mu + 1e-5f);
                #pragma unroll
                for (int u = 0; u < 16; u++) {
                    int i = u * 128 + lt;
                    float v = (pf[g * 2048 + i] - mu) * rstd * __ldg(ln1_w + i) + __ldg(ln1_b + i);
                    float ge = v * normcdff(v);
                    if (i < HID) {
                        bf16 hh, hl; split1(ge, hh, hl);
                        size_t off = pk_off(row, i);
                        g_h1p[0][0][off] = hh; g_h1p[0][1][off] = hl;
                        g_h2p[0][0][off] = hh; g_h2p[0][1][off] = hl;
                    } else {
                        g_c1[0][(size_t)row * HID + i - HID] = ge;
                        g_c2[0][(size_t)row * HID + i - HID] = ge;
                    }
                }
                __syncthreads();
            }
        }
    }
    gridbar(epoch);

    // ---- main sequential loop
    for (int s = 0; s < SEQL; s++) {
        const int pi = s & 1, po = pi ^ 1;
        const int mg = (bid >> 5) & 3, ntl = bid & 31;

        // P1: (h1,c1) = lstm0(x, h1, c1) : K = 128 + 1024 (18 chunks streamed)
        if (bid < 128) {
            CFrag acc[2][4];
            #pragma unroll
            for (int i = 0; i < 2; i++)
                #pragma unroll
                for (int j = 0; j < 4; j++) wmma::fill_fragment(acc[i][j], 0.f);
            Seg sg[2] = {
                {g_xp[0] + (size_t)mg * ABLK, g_xp[1] + (size_t)mg * ABLK,
                 g_wih0p[0] + (size_t)ntl * 2 * 9216, g_wih0p[1] + (size_t)ntl * 2 * 9216,
                 2, 4 * ABLK, 9216},
                {g_h1p[pi][0] + (size_t)mg * ABLK, g_h1p[pi][1] + (size_t)mg * ABLK,
                 g_whh0p[0] + (size_t)ntl * 16 * 9216, g_whh0p[1] + (size_t)ntl * 16 * 9216,
                 16, 4 * ABLK, 9216}};
            gemm_pk<4>(acc, P, pbase, sg, 2, pp);
            lstm_epi(acc, P, b0, g_c1[pi], g_c1[po], g_h1p[po][0], g_h1p[po][1], mg << 7, ntl << 5);
        }
        gridbar(epoch);

        // P2: (h2,c2) = lstm1(h1_new, h2, c2) : K = 1024 + 1024 (32 chunks)
        if (bid < 128) {
            CFrag acc[2][4];
            #pragma unroll
            for (int i = 0; i < 2; i++)
                #pragma unroll
                for (int j = 0; j < 4; j++) wmma::fill_fragment(acc[i][j], 0.f);
            Seg sg[2] = {
                {g_h1p[po][0] + (size_t)mg * ABLK, g_h1p[po][1] + (size_t)mg * ABLK,
                 g_wih1p[0] + (size_t)ntl * 16 * 9216, g_wih1p[1] + (size_t)ntl * 16 * 9216,
                 16, 4 * ABLK, 9216},
                {g_h2p[pi][0] + (size_t)mg * ABLK, g_h2p[pi][1] + (size_t)mg * ABLK,
                 g_whh1p[0] + (size_t)ntl * 16 * 9216, g_whh1p[1] + (size_t)ntl * 16 * 9216,
                 16, 4 * ABLK, 9216}};
            gemm_pk<4>(acc, P, pbase, sg, 2, pp);
            lstm_epi(acc, P, b1, g_c2[pi], g_c2[po], g_h2p[po][0], g_h2p[po][1], mg << 7, ntl << 5);
        }
        gridbar(epoch);

        // P3: t = h2_new @ p1_w^T + p1_b : 64 tiles of 128x64
        if (bid < 64) {
            int mg3 = bid >> 4, nt3 = bid & 15;
            CFrag acc[2][2];
            #pragma unroll
            for (int i = 0; i < 2; i++) { wmma::fill_fragment(acc[i][0], 0.f); wmma::fill_fragment(acc[i][1], 0.f); }
            Seg sg[1] = {{g_h2p[po][0] + (size_t)mg3 * ABLK, g_h2p[po][1] + (size_t)mg3 * ABLK,
                          g_p1p[0] + (size_t)nt3 * 16 * 4608, g_p1p[1] + (size_t)nt3 * 16 * 4608,
                          16, 4 * ABLK, 4608}};
            gemm_pk<2>(acc, P, pbase, sg, 1, pp);
            store_epi<2>(acc, P, p1_b, g_t, HID, mg3 << 7, nt3 << 6);
        }
        gridbar(epoch);

        // P4: LayerNorm + gelu (4 rows, 2 passes) then coalesced GEMV via g_p2q
        {
            float* pf = (float*)(P + 1024);        // [4][1024] gelu vals + [8][128] partials
            float* psum = pf + 4096;
            const int g = tid >> 7, lt = tid & 127, w4 = (tid >> 5) & 3;
            for (int grp = bid; grp < 128; grp += nb) {
                for (int pass = 0; pass < 2; pass++) {
                    int rr = pass * 2 + g;
                    int row = (grp << 2) + rr;
                    const float* trow = g_t + (size_t)row * HID;
                    float vb[8]; float ls = 0.f, lq = 0.f;
                    #pragma unroll
                    for (int u = 0; u < 8; u++) {
                        float v = __ldcg(trow + u * 128 + lt);
                        vb[u] = v; ls += v; lq += v * v;
                    }
                    #pragma unroll
                    for (int o = 16; o > 0; o >>= 1) {
                        ls += __shfl_down_sync(0xffffffffu, ls, o);
                        lq += __shfl_down_sync(0xffffffffu, lq, o);
                    }
                    if (lane == 0) { redA[g * 4 + w4] = ls; redB[g * 4 + w4] = lq; }
                    __syncthreads();
                    float S = redA[g * 4] + redA[g * 4 + 1] + redA[g * 4 + 2] + redA[g * 4 + 3];
                    float Q = redB[g * 4] + redB[g * 4 + 1] + redB[g * 4 + 2] + redB[g * 4 + 3];
                    float mu = S * (1.f / 1024.f);
                    float rstd = rsqrtf(Q * (1.f / 1024.f) - mu * mu + 1e-5f);
                    #pragma unroll
                    for (int u = 0; u < 8; u++) {
                        int i = u * 128 + lt;
                        float v = (vb[u] - mu) * rstd * __ldg(pln_w + i) + __ldg(pln_b + i);
                        pf[rr * 1024 + i] = v * normcdff(v);
                    }
                    __syncthreads();
                }
                // GEMV: thread (o=lt, half=g) does K-half 512 for all 4 rows, coalesced loads
                {
                    float a0 = 0.f, a1 = 0.f, a2 = 0.f, a3 = 0.f;
                    const int kq0 = g * 128;
                    #pragma unroll 2
                    for (int kq = 0; kq < 128; kq++) {
                        float4 wv = g_p2q[(size_t)(kq0 + kq) * 128 + lt];
                        float4 g0 = *(const float4*)(pf + 0 * 1024 + (kq0 + kq) * 4);
                        float4 g1 = *(const float4*)(pf + 1 * 1024 + (kq0 + kq) * 4);
                        float4 g2 = *(const float4*)(pf + 2 * 1024 + (kq0 + kq) * 4);
                        float4 g3 = *(const float4*)(pf + 3 * 1024 + (kq0 + kq) * 4);
                        a0 += g0.x * wv.x + g0.y * wv.y + g0.z * wv.z + g0.w * wv.w;
                        a1 += g1.x * wv.x + g1.y * wv.y + g1.z * wv.z + g1.w * wv.w;
                        a2 += g2.x * wv.x + g2.y * wv.y + g2.z * wv.z + g2.w * wv.w;
                        a3 += g3.x * wv.x + g3.y * wv.y + g3.z * wv.z + g3.w * wv.w;
                    }
                    psum[(0 * 2 + g) * 128 + lt] = a0;
                    psum[(1 * 2 + g) * 128 + lt] = a1;
                    psum[(2 * 2 + g) * 128 + lt] = a2;
                    psum[(3 * 2 + g) * 128 + lt] = a3;
                }
                __syncthreads();
                for (int idx = tid; idx < 512; idx += NTHREADS) {
                    int r = idx >> 7, o = idx & 127;
                    int row = (grp << 2) + r;
                    float y = psum[(r * 2) * 128 + o] + psum[(r * 2 + 1) * 128 + o] + __ldg(p2_b + o);
                    bf16 xh, xl; split1(y, xh, xl);
                    size_t off = pk_off(row, o);
                    g_xp[0][off] = xh;
                    g_xp[1][off] = xl;
                    out[(size_t)row * SEQL * NOUT + s * NOUT + o] = y;
                }
                __syncthreads();
            }
        }
        gridbar(epoch);
    }
}

// ---------------- launch ----------------
extern "C" void kernel_launch(void* const* d_in, const int* in_sizes, int n_in,
                              void* d_out, int out_size) {
    (void)in_sizes; (void)n_in; (void)out_size;
    int nsm = 0;
    cudaDeviceGetAttribute(&nsm, cudaDevAttrMultiProcessorCount, 0);
    if (nsm <= 0) nsm = 148;
    if (nsm > 256) nsm = 256;
    cudaFuncSetAttribute(dec_kernel, cudaFuncAttributeMaxDynamicSharedMemorySize, SMEM_BYTES);

    const float* z      = (const float*)d_in[0];
    const float* lin1_w = (const float*)d_in[1];
    const float* lin1_b = (const float*)d_in[2];
    const float* ln1_w  = (const float*)d_in[3];
    const float* ln1_b  = (const float*)d_in[4];
    const float* w_ih0  = (const float*)d_in[5];
    const float* w_hh0  = (const float*)d_in[6];
    const float* b0     = (const float*)d_in[7];
    const float* w_ih1  = (const float*)d_in[8];
    const float* w_hh1  = (const float*)d_in[9];
    const float* b1     = (const float*)d_in[10];
    const float* p1_w   = (const float*)d_in[11];
    const float* p1_b   = (const float*)d_in[12];
    const float* pln_w  = (const float*)d_in[13];
    const float* pln_b  = (const float*)d_in[14];
    const float* p2_w   = (const float*)d_in[15];
    const float* p2_b   = (const float*)d_in[16];

    dec_kernel<<<nsm, NTHREADS, SMEM_BYTES>>>(
        z, lin1_w, lin1_b, ln1_w, ln1_b,
        w_ih0, w_hh0, b0, w_ih1, w_hh1, b1,
        p1_w, p1_b, pln_w, pln_b, p2_w, p2_b,
        (float*)d_out);
}

// round 8
// speedup vs baseline: 5.8660x; 1.0345x over previous
#include <cuda_runtime.h>
#include <cuda_bf16.h>
#include <mma.h>
#include <math.h>
#include <stdint.h>

using namespace nvcuda;
using bf16 = __nv_bfloat16;

#define LATENT 256
#define HID    1024
#define NOUT   128
#define SEQL   96

#define NTHREADS 256
#define NBLOCKS  128
#define LDA    72
#define ABLK   9216          // elems per 128x72 block
#define ABLKB  18432         // bytes per 128x72 bf16 block
#define NSTAGE 3
#define STGMAX 73728         // bytes per stage buffer (max: NFW=4)

// smem: 1024 align slack + 1024 hdr (mbars) + 3 stage buffers
#define SMEM_BYTES (1024 + 1024 + NSTAGE * STGMAX)

// ---------------- device scratch (packed layouts) ----------------
__device__ __align__(16) bf16 g_lin1p[2][32 * 4 * 4608];     // BN=64, K=256
__device__ __align__(16) bf16 g_wih0p[2][32 * 2 * 9216];     // BN=128 gated, K=128
__device__ __align__(16) bf16 g_whh0p[2][32 * 16 * 9216];    // BN=128 gated, K=1024
__device__ __align__(16) bf16 g_wih1p[2][32 * 16 * 9216];
__device__ __align__(16) bf16 g_whh1p[2][32 * 16 * 9216];
__device__ __align__(16) bf16 g_p1p[2][32 * 16 * 2304];      // BN=32, K=1024
__device__ __align__(16) float4 g_p2q[256 * 128];            // p2_w transposed k-quad major
// activations packed as [plane][kchunk][mgroup][128 x 72]
__device__ __align__(16) bf16 g_zp[2][4 * 4 * 9216];
__device__ __align__(16) bf16 g_xp[2][2 * 4 * 9216];
__device__ __align__(16) bf16 g_h1p[2][2][16 * 4 * 9216];    // [pingpong][plane]
__device__ __align__(16) bf16 g_h2p[2][2][16 * 4 * 9216];
__device__ float g_c1[2][512 * HID];
__device__ float g_c2[2][512 * HID];
__device__ float g_u[512 * 2 * HID];
__device__ float g_t[512 * HID];
__device__ volatile unsigned g_arrive[256];
__device__ volatile unsigned g_release;

typedef wmma::fragment<wmma::accumulator, 16, 16, 16, float> CFrag;
typedef wmma::fragment<wmma::matrix_a, 16, 16, 16, bf16, wmma::row_major> AFrag;
typedef wmma::fragment<wmma::matrix_b, 16, 16, 16, bf16, wmma::col_major> BFrag;

// ---------------- PTX helpers ----------------
__device__ __forceinline__ uint32_t smem_u32(const void* p) {
    uint32_t a;
    asm("{ .reg .u64 t; cvta.to.shared.u64 t, %1; cvt.u32.u64 %0, t; }" : "=r"(a) : "l"(p));
    return a;
}
#define MBAR_INIT(a, c) \
    asm volatile("mbarrier.init.shared.b64 [%0], %1;" :: "r"(a), "r"((uint32_t)(c)) : "memory")
#define MBAR_EXPECT(a, n) \
    asm volatile("mbarrier.arrive.expect_tx.shared.b64 _, [%0], %1;" :: "r"(a), "r"((uint32_t)(n)) : "memory")
#define MBAR_ARRIVE(a) \
    asm volatile("mbarrier.arrive.shared.b64 _, [%0];" :: "r"((uint32_t)(a)) : "memory")
#define MBAR_WAIT(a, par) do { \
    uint32_t _m = (a), _p = (par), _d; \
    asm volatile("{\n\t.reg .pred p;\n\t" \
        "mbarrier.try_wait.parity.acquire.cta.shared::cta.b64 p, [%1], %2;\n\t" \
        "selp.b32 %0, 1, 0, p;\n\t}" : "=r"(_d) : "r"(_m), "r"(_p) : "memory"); \
    if (!_d) { \
        asm volatile("{\n\t.reg .pred P1;\n\tWL_%=:\n\t" \
            "mbarrier.try_wait.parity.acquire.cta.shared::cta.b64 P1, [%0], %1, 0x989680;\n\t" \
            "@P1 bra.uni WD_%=;\n\tbra.uni WL_%=;\n\tWD_%=:\n\t}" \
            :: "r"(_m), "r"(_p) : "memory"); \
    } } while (0)
#define BULK_G2S(dst, src, sz, mbar) \
    asm volatile("cp.async.bulk.shared::cluster.global.mbarrier::complete_tx::bytes [%0], [%1], %2, [%3];" \
        :: "r"((uint32_t)(dst)), "l"(src), "r"((uint32_t)(sz)), "r"((uint32_t)(mbar)) : "memory")

// ---------------- grid barrier ----------------
__device__ __forceinline__ void gridbar(unsigned& epoch) {
    epoch++;
    __threadfence();
    __syncthreads();
    if (blockIdx.x == 0) {
        if (threadIdx.x == 0) g_arrive[0] = epoch;
        for (int b = threadIdx.x; b < (int)gridDim.x; b += blockDim.x) {
            while (g_arrive[b] < epoch) { __nanosleep(16); }
        }
        __syncthreads();
        if (threadIdx.x == 0) { __threadfence(); g_release = epoch; }
    } else {
        if (threadIdx.x == 0) {
            g_arrive[blockIdx.x] = epoch;
            while (g_release < epoch) { __nanosleep(16); }
        }
    }
    __syncthreads();
}

// fast activations (~1e-6 rel err)
__device__ __forceinline__ float sigm(float x) {
    return __fdividef(1.f, 1.f + __expf(-x));
}
__device__ __forceinline__ float tanh_f(float x) {
    float e = __expf(2.f * x);
    return 1.f - __fdividef(2.f, e + 1.f);
}
__device__ __forceinline__ void split1(float v, bf16& h, bf16& l) {
    h = __float2bfloat16_rn(v);
    l = __float2bfloat16_rn(v - __bfloat162float(h));
}

// pack activation offset: (row 0..511, col) -> packed elem index
__device__ __forceinline__ size_t pk_off(int row, int col) {
    return ((size_t)((col >> 6) * 4 + (row >> 7))) * ABLK + (size_t)(row & 127) * LDA + (col & 63);
}

// ---------------- S0 weight packer ----------------
// gated: BN=128 (4 gates x 32 cols per ntile); plain: rows nt*BN..+BN
__device__ void pack_w(const float* __restrict__ W, bf16* __restrict__ hi, bf16* __restrict__ lo,
                       int K, int BN, int ntiles, int gated, int gt, int gs)
{
    const int nch = K >> 6;
    const int tot = ntiles * nch * BN * 16;   // float4 units
    for (int i = gt; i < tot; i += gs) {
        int k4 = i & 15;
        int rest = i >> 4;
        int n = rest % BN; rest /= BN;
        int c = rest % nch;
        int nt = rest / nch;
        int row = gated ? ((n >> 5) * HID + nt * 32 + (n & 31)) : (nt * BN + n);
        float4 v = *(const float4*)(W + (size_t)row * K + c * 64 + k4 * 4);
        bf16 h[4], l[4];
        split1(v.x, h[0], l[0]); split1(v.y, h[1], l[1]);
        split1(v.z, h[2], l[2]); split1(v.w, h[3], l[3]);
        size_t d = ((size_t)(nt * nch + c) * BN + n) * LDA + k4 * 4;
        *(uint2*)(hi + d) = *(uint2*)h;
        *(uint2*)(lo + d) = *(uint2*)l;
    }
}

// ---------------- pipeline state ----------------
struct Pipe {
    int fullph[NSTAGE];
    int emptyph[NSTAGE];
    int pcnt, ccnt;
};
struct Seg { const bf16 *ah, *al, *bh, *bl; int nch, astr, bstr; };

// ---------------- 3-stage mbar-pipelined wmma GEMM ----------------
// 8 warps: wm = warp>>1 (4 row groups of 32), wn = warp&1 (2 col groups of 16*NFW).
// Block tile 128 x 32*NFW. Warp tile 32 x 16*NFW.
// Term-major MMA ordering: dependent distance on each accumulator = 8 MMAs.
template <int NFW>
__device__ void gemm_pk(CFrag (&acc)[2][NFW], char* P, uint32_t pbase,
                        const Seg* segs, int nseg, Pipe& pp)
{
    constexpr int BB = 32 * NFW * 144;                // B plane bytes
    constexpr uint32_t TX = 2 * ABLKB + 2 * BB;
    const int tid = threadIdx.x;
    const int warp = tid >> 5, lane = tid & 31;
    const int wm = warp >> 1, wn = warp & 1;

    int nt = 0;
    for (int s = 0; s < nseg; s++) nt += segs[s].nch;

    auto do_fill = [&](int gidx) {
        int c = gidx, si = 0;
        while (c >= segs[si].nch) { c -= segs[si].nch; si++; }
        const Seg& S = segs[si];
        int st = pp.pcnt % NSTAGE;
        if (tid == 0) {
            MBAR_WAIT(pbase + 24 + (st << 3), (uint32_t)(pp.emptyph[st] & 1));
            uint32_t d = pbase + 1024 + st * STGMAX;
            uint32_t mb = pbase + (st << 3);
            MBAR_EXPECT(mb, TX);
            BULK_G2S(d,                  (const char*)(S.ah + (size_t)c * S.astr), ABLKB, mb);
            BULK_G2S(d + ABLKB,          (const char*)(S.al + (size_t)c * S.astr), ABLKB, mb);
            BULK_G2S(d + 2 * ABLKB,      (const char*)(S.bh + (size_t)c * S.bstr), BB, mb);
            BULK_G2S(d + 2 * ABLKB + BB, (const char*)(S.bl + (size_t)c * S.bstr), BB, mb);
        }
        pp.emptyph[st]++;
        pp.pcnt++;
    };

    const int pre = nt < 2 ? nt : 2;
    for (int g = 0; g < pre; g++) do_fill(g);

    for (int i = 0; i < nt; i++) {
        if (i + 2 < nt) do_fill(i + 2);
        const int st = pp.ccnt % NSTAGE;
        MBAR_WAIT(pbase + (st << 3), (uint32_t)(pp.fullph[st] & 1));
        pp.fullph[st]++;
        pp.ccnt++;

        const bf16* sAh = (const bf16*)(P + 1024 + st * STGMAX);
        const bf16* sAl = sAh + ABLK;
        const bf16* sBh = sAl + ABLK;
        const bf16* sBl = sBh + 32 * NFW * LDA;
        #pragma unroll
        for (int kk = 0; kk < 4; kk++) {
            AFrag ah0, ah1, al0, al1;
            wmma::load_matrix_sync(ah0, sAh + (wm * 32 + 0)  * LDA + kk * 16, LDA);
            wmma::load_matrix_sync(ah1, sAh + (wm * 32 + 16) * LDA + kk * 16, LDA);
            wmma::load_matrix_sync(al0, sAl + (wm * 32 + 0)  * LDA + kk * 16, LDA);
            wmma::load_matrix_sync(al1, sAl + (wm * 32 + 16) * LDA + kk * 16, LDA);
            BFrag bf[NFW];
            #pragma unroll
            for (int nf = 0; nf < NFW; nf++)
                wmma::load_matrix_sync(bf[nf], sBh + (wn * (16 * NFW) + nf * 16) * LDA + kk * 16, LDA);
            // term 1: ah * bh   (8 independent accumulators in flight)
            #pragma unroll
            for (int nf = 0; nf < NFW; nf++) {
                wmma::mma_sync(acc[0][nf], ah0, bf[nf], acc[0][nf]);
                wmma::mma_sync(acc[1][nf], ah1, bf[nf], acc[1][nf]);
            }
            // term 3: al * bh
            #pragma unroll
            for (int nf = 0; nf < NFW; nf++) {
                wmma::mma_sync(acc[0][nf], al0, bf[nf], acc[0][nf]);
                wmma::mma_sync(acc[1][nf], al1, bf[nf], acc[1][nf]);
            }
            // term 2: ah * bl
            #pragma unroll
            for (int nf = 0; nf < NFW; nf++)
                wmma::load_matrix_sync(bf[nf], sBl + (wn * (16 * NFW) + nf * 16) * LDA + kk * 16, LDA);
            #pragma unroll
            for (int nf = 0; nf < NFW; nf++) {
                wmma::mma_sync(acc[0][nf], ah0, bf[nf], acc[0][nf]);
                wmma::mma_sync(acc[1][nf], ah1, bf[nf], acc[1][nf]);
            }
        }
        if (lane == 0) MBAR_ARRIVE(pbase + 24 + (st << 3));
    }
}

// ---------------- epilogues (syncthreads at entry: patch aliases stage smem) ----------------
__device__ void lstm_epi(CFrag (&acc)[2][4], char* P, const float* __restrict__ bias,
                         const float* __restrict__ c_in, float* __restrict__ c_out,
                         bf16* __restrict__ hp_hi, bf16* __restrict__ hp_lo,
                         int mbase, int jbase)
{
    __syncthreads();                      // lagging warps may still read stages
    float* pf = (float*)(P + 1024);       // patch [128][132]
    const int tid = threadIdx.x, warp = tid >> 5;
    const int wm = warp >> 1, wn = warp & 1;
    #pragma unroll
    for (int i = 0; i < 2; i++)
        #pragma unroll
        for (int nf = 0; nf < 4; nf++)
            wmma::store_matrix_sync(pf + (wm * 32 + i * 16) * 132 + wn * 64 + nf * 16,
                                    acc[i][nf], 132, wmma::mem_row_major);
    __syncthreads();
    #pragma unroll 4
    for (int e = tid; e < 128 * 32; e += NTHREADS) {
        int r = e >> 5, j = e & 31;
        int row = mbase + r, col = jbase + j;
        float iv = pf[r * 132 + j]      + __ldg(bias + col);
        float fv = pf[r * 132 + 32 + j] + __ldg(bias + HID + col);
        float gv = pf[r * 132 + 64 + j] + __ldg(bias + 2 * HID + col);
        float ov = pf[r * 132 + 96 + j] + __ldg(bias + 3 * HID + col);
        float cold = __ldcg(c_in + (size_t)row * HID + col);
        float cn = sigm(fv) * cold + sigm(iv) * tanh_f(gv);
        float hn = sigm(ov) * tanh_f(cn);
        c_out[(size_t)row * HID + col] = cn;
        bf16 hh, hl; split1(hn, hh, hl);
        size_t off = pk_off(row, col);
        hp_hi[off] = hh;
        hp_lo[off] = hl;
    }
    __syncthreads();
}

template <int NFW>
__device__ void store_epi(CFrag (&acc)[2][NFW], char* P, const float* __restrict__ bias,
                          float* __restrict__ dst, int stride, int mbase, int nbase)
{
    __syncthreads();
    constexpr int BN = 32 * NFW, PS = BN + 4;
    float* pf = (float*)(P + 1024);
    const int tid = threadIdx.x, warp = tid >> 5;
    const int wm = warp >> 1, wn = warp & 1;
    #pragma unroll
    for (int i = 0; i < 2; i++)
        #pragma unroll
        for (int nf = 0; nf < NFW; nf++)
            wmma::store_matrix_sync(pf + (wm * 32 + i * 16) * PS + wn * (16 * NFW) + nf * 16,
                                    acc[i][nf], PS, wmma::mem_row_major);
    __syncthreads();
    for (int e = tid; e < 128 * BN; e += NTHREADS) {
        int r = e / BN, c = e % BN;
        dst[(size_t)(mbase + r) * stride + nbase + c] = pf[r * PS + c] + __ldg(bias + nbase + c);
    }
    __syncthreads();
}

// ---------------- the persistent decoder kernel ----------------
__global__ void __launch_bounds__(NTHREADS, 1) dec_kernel(
    const float* __restrict__ z,     const float* __restrict__ lin1_w, const float* __restrict__ lin1_b,
    const float* __restrict__ ln1_w, const float* __restrict__ ln1_b,
    const float* __restrict__ w_ih0, const float* __restrict__ w_hh0,  const float* __restrict__ b0,
    const float* __restrict__ w_ih1, const float* __restrict__ w_hh1,  const float* __restrict__ b1,
    const float* __restrict__ p1_w,  const float* __restrict__ p1_b,
    const float* __restrict__ pln_w, const float* __restrict__ pln_b,
    const float* __restrict__ p2_w,  const float* __restrict__ p2_b,
    float* __restrict__ out)
{
    extern __shared__ char pool[];
    __shared__ float redA[8], redB[8];
    const int bid = blockIdx.x, nb = gridDim.x, tid = threadIdx.x;
    const int lane = tid & 31;
    uint32_t raw = smem_u32(pool);
    uint32_t pbase = (raw + 1023) & ~1023u;
    char* P = pool + (pbase - raw);
    unsigned epoch = g_release;
    Pipe pp;
    #pragma unroll
    for (int s = 0; s < NSTAGE; s++) { pp.fullph[s] = 0; pp.emptyph[s] = 0; }
    pp.pcnt = 0; pp.ccnt = 0;

    if (tid == 0) {
        #pragma unroll
        for (int s = 0; s < NSTAGE; s++) {
            MBAR_INIT(pbase + (s << 3), 1);       // full: tx-based
            MBAR_INIT(pbase + 24 + (s << 3), 8);  // empty: one arrive per warp
        }
    }
    __syncthreads();
    if (lane == 0) {   // arm all empties (8 warps x lane0 = 8 arrivals each)
        MBAR_ARRIVE(pbase + 24);
        MBAR_ARRIVE(pbase + 32);
        MBAR_ARRIVE(pbase + 40);
    }
    __syncthreads();

    // ---- S0: pack weights; pack z; transpose p2; zero x
    {
        int gt = bid * NTHREADS + tid, gs = nb * NTHREADS;
        pack_w(lin1_w, g_lin1p[0], g_lin1p[1], LATENT, 64, 32, 0, gt, gs);
        pack_w(w_ih0,  g_wih0p[0], g_wih0p[1], NOUT, 128, 32, 1, gt, gs);
        pack_w(w_hh0,  g_whh0p[0], g_whh0p[1], HID, 128, 32, 1, gt, gs);
        pack_w(w_ih1,  g_wih1p[0], g_wih1p[1], HID, 128, 32, 1, gt, gs);
        pack_w(w_hh1,  g_whh1p[0], g_whh1p[1], HID, 128, 32, 1, gt, gs);
        pack_w(p1_w,   g_p1p[0],   g_p1p[1],   HID, 32, 32, 0, gt, gs);
        for (int i = gt; i < 4 * 4 * 128 * 16; i += gs) {
            int k4 = i & 15, r = (i >> 4) & 127, mg = (i >> 11) & 3, c = i >> 13;
            float4 v = *(const float4*)(z + (size_t)(mg * 128 + r) * LATENT + c * 64 + k4 * 4);
            bf16 h[4], l[4];
            split1(v.x, h[0], l[0]); split1(v.y, h[1], l[1]);
            split1(v.z, h[2], l[2]); split1(v.w, h[3], l[3]);
            size_t d = (size_t)(c * 4 + mg) * ABLK + (size_t)r * LDA + k4 * 4;
            *(uint2*)(g_zp[0] + d) = *(uint2*)h;
            *(uint2*)(g_zp[1] + d) = *(uint2*)l;
        }
        // p2 transposed quads: g_p2q[kq*128 + o] = p2_w[o][4kq..4kq+3]
        for (int i = gt; i < 256 * 128; i += gs) {
            int o = i & 127, kq = i >> 7;
            g_p2q[i] = *(const float4*)(p2_w + (size_t)o * HID + kq * 4);
        }
        for (int i = gt; i < 2 * 4 * ABLK; i += gs) {
            g_xp[0][i] = __float2bfloat16_rn(0.f);
            g_xp[1][i] = __float2bfloat16_rn(0.f);
        }
    }
    gridbar(epoch);

    // ---- S1: u = z @ lin1_w^T + lin1_b  (512 x 2048): 128 tiles of 128x64
    {
        int mg = bid >> 5, nt = bid & 31;
        CFrag acc[2][2];
        #pragma unroll
        for (int i = 0; i < 2; i++) { wmma::fill_fragment(acc[i][0], 0.f); wmma::fill_fragment(acc[i][1], 0.f); }
        Seg sg[1] = {{g_zp[0] + (size_t)mg * ABLK, g_zp[1] + (size_t)mg * ABLK,
                      g_lin1p[0] + (size_t)nt * 4 * 4608, g_lin1p[1] + (size_t)nt * 4 * 4608,
                      4, 4 * ABLK, 4608}};
        gemm_pk<2>(acc, P, pbase, sg, 1, pp);
        store_epi<2>(acc, P, lin1_b, g_u, 2 * HID, mg << 7, nt << 6);
    }
    gridbar(epoch);

    // ---- S2: LayerNorm(2048) + gelu -> h0/c0 (both cells), 2 rows per pass
    {
        float* pf = (float*)(P + 1024);
        const int g = tid >> 7, lt = tid & 127, w4 = (tid >> 5) & 3;
        for (int grp = bid; grp < 128; grp += nb) {
            for (int pass = 0; pass < 2; pass++) {
                int row = (grp << 2) + pass * 2 + g;
                const float* urow = g_u + (size_t)row * 2 * HID;
                float ls = 0.f, lq = 0.f;
                #pragma unroll
                for (int u = 0; u < 16; u++) {
                    float v = __ldcg(urow + u * 128 + lt);
                    pf[g * 2048 + u * 128 + lt] = v;
                    ls += v; lq += v * v;
                }
                #pragma unroll
                for (int o = 16; o > 0; o >>= 1) {
                    ls += __shfl_down_sync(0xffffffffu, ls, o);
                    lq += __shfl_down_sync(0xffffffffu, lq, o);
                }
                if (lane == 0) { redA[g * 4 + w4] = ls; redB[g * 4 + w4] = lq; }
                __syncthreads();
                float S = redA[g * 4] + redA[g * 4 + 1] + redA[g * 4 + 2] + redA[g * 4 + 3];
                float Q = redB[g * 4] + redB[g * 4 + 1] + redB[g * 4 + 2] + redB[g * 4 + 3];
                float mu = S * (1.f / 2048.f);
                float rstd = rsqrtf(Q * (1.f / 2048.f) - mu * mu + 1e-5f);
                #pragma unroll
                for (int u = 0; u < 16; u++) {
                    int i = u * 128 + lt;
                    float v = (pf[g * 2048 + i] - mu) * rstd * __ldg(ln1_w + i) + __ldg(ln1_b + i);
                    float ge = v * normcdff(v);
                    if (i < HID) {
                        bf16 hh, hl; split1(ge, hh, hl);
                        size_t off = pk_off(row, i);
                        g_h1p[0][0][off] = hh; g_h1p[0][1][off] = hl;
                        g_h2p[0][0][off] = hh; g_h2p[0][1][off] = hl;
                    } else {
                        g_c1[0][(size_t)row * HID + i - HID] = ge;
                        g_c2[0][(size_t)row * HID + i - HID] = ge;
                    }
                }
                __syncthreads();
            }
        }
    }
    gridbar(epoch);

    // ---- main sequential loop
    for (int s = 0; s < SEQL; s++) {
        const int pi = s & 1, po = pi ^ 1;
        const int mg = (bid >> 5) & 3, ntl = bid & 31;

        // P1: (h1,c1) = lstm0(x, h1, c1) : K = 128 + 1024 (18 chunks streamed)
        {
            CFrag acc[2][4];
            #pragma unroll
            for (int i = 0; i < 2; i++)
                #pragma unroll
                for (int j = 0; j < 4; j++) wmma::fill_fragment(acc[i][j], 0.f);
            Seg sg[2] = {
                {g_xp[0] + (size_t)mg * ABLK, g_xp[1] + (size_t)mg * ABLK,
                 g_wih0p[0] + (size_t)ntl * 2 * 9216, g_wih0p[1] + (size_t)ntl * 2 * 9216,
                 2, 4 * ABLK, 9216},
                {g_h1p[pi][0] + (size_t)mg * ABLK, g_h1p[pi][1] + (size_t)mg * ABLK,
                 g_whh0p[0] + (size_t)ntl * 16 * 9216, g_whh0p[1] + (size_t)ntl * 16 * 9216,
                 16, 4 * ABLK, 9216}};
            gemm_pk<4>(acc, P, pbase, sg, 2, pp);
            lstm_epi(acc, P, b0, g_c1[pi], g_c1[po], g_h1p[po][0], g_h1p[po][1], mg << 7, ntl << 5);
        }
        gridbar(epoch);

        // P2: (h2,c2) = lstm1(h1_new, h2, c2) : K = 1024 + 1024 (32 chunks)
        {
            CFrag acc[2][4];
            #pragma unroll
            for (int i = 0; i < 2; i++)
                #pragma unroll
                for (int j = 0; j < 4; j++) wmma::fill_fragment(acc[i][j], 0.f);
            Seg sg[2] = {
                {g_h1p[po][0] + (size_t)mg * ABLK, g_h1p[po][1] + (size_t)mg * ABLK,
                 g_wih1p[0] + (size_t)ntl * 16 * 9216, g_wih1p[1] + (size_t)ntl * 16 * 9216,
                 16, 4 * ABLK, 9216},
                {g_h2p[pi][0] + (size_t)mg * ABLK, g_h2p[pi][1] + (size_t)mg * ABLK,
                 g_whh1p[0] + (size_t)ntl * 16 * 9216, g_whh1p[1] + (size_t)ntl * 16 * 9216,
                 16, 4 * ABLK, 9216}};
            gemm_pk<4>(acc, P, pbase, sg, 2, pp);
            lstm_epi(acc, P, b1, g_c2[pi], g_c2[po], g_h2p[po][0], g_h2p[po][1], mg << 7, ntl << 5);
        }
        gridbar(epoch);

        // P3: t = h2_new @ p1_w^T + p1_b : 128 tiles of 128x32 (all blocks active)
        {
            CFrag acc[2][1];
            wmma::fill_fragment(acc[0][0], 0.f);
            wmma::fill_fragment(acc[1][0], 0.f);
            Seg sg[1] = {{g_h2p[po][0] + (size_t)mg * ABLK, g_h2p[po][1] + (size_t)mg * ABLK,
                          g_p1p[0] + (size_t)ntl * 16 * 2304, g_p1p[1] + (size_t)ntl * 16 * 2304,
                          16, 4 * ABLK, 2304}};
            gemm_pk<1>(acc, P, pbase, sg, 1, pp);
            store_epi<1>(acc, P, p1_b, g_t, HID, mg << 7, ntl << 5);
        }
        gridbar(epoch);

        // P4: LayerNorm + gelu (4 rows, 2 passes) then coalesced GEMV via g_p2q
        {
            float* pf = (float*)(P + 1024);        // [4][1024] gelu vals + [8][128] partials
            float* psum = pf + 4096;
            const int g = tid >> 7, lt = tid & 127, w4 = (tid >> 5) & 3;
            for (int grp = bid; grp < 128; grp += nb) {
                for (int pass = 0; pass < 2; pass++) {
                    int rr = pass * 2 + g;
                    int row = (grp << 2) + rr;
                    const float* trow = g_t + (size_t)row * HID;
                    float vb[8]; float ls = 0.f, lq = 0.f;
                    #pragma unroll
                    for (int u = 0; u < 8; u++) {
                        float v = __ldcg(trow + u * 128 + lt);
                        vb[u] = v; ls += v; lq += v * v;
                    }
                    #pragma unroll
                    for (int o = 16; o > 0; o >>= 1) {
                        ls += __shfl_down_sync(0xffffffffu, ls, o);
                        lq += __shfl_down_sync(0xffffffffu, lq, o);
                    }
                    if (lane == 0) { redA[g * 4 + w4] = ls; redB[g * 4 + w4] = lq; }
                    __syncthreads();
                    float S = redA[g * 4] + redA[g * 4 + 1] + redA[g * 4 + 2] + redA[g * 4 + 3];
                    float Q = redB[g * 4] + redB[g * 4 + 1] + redB[g * 4 + 2] + redB[g * 4 + 3];
                    float mu = S * (1.f / 1024.f);
                    float rstd = rsqrtf(Q * (1.f / 1024.f) - mu * mu + 1e-5f);
                    #pragma unroll
                    for (int u = 0; u < 8; u++) {
                        int i = u * 128 + lt;
                        float v = (vb[u] - mu) * rstd * __ldg(pln_w + i) + __ldg(pln_b + i);
                        pf[rr * 1024 + i] = v * normcdff(v);
                    }
                    __syncthreads();
                }
                // GEMV: thread (o=lt, half=g) does K-half 512 for all 4 rows, coalesced loads
                {
                    float a0 = 0.f, a1 = 0.f, a2 = 0.f, a3 = 0.f;
                    const int kq0 = g * 128;
                    #pragma unroll 2
                    for (int kq = 0; kq < 128; kq++) {
                        float4 wv = g_p2q[(size_t)(kq0 + kq) * 128 + lt];
                        float4 g0 = *(const float4*)(pf + 0 * 1024 + (kq0 + kq) * 4);
                        float4 g1 = *(const float4*)(pf + 1 * 1024 + (kq0 + kq) * 4);
                        float4 g2 = *(const float4*)(pf + 2 * 1024 + (kq0 + kq) * 4);
                        float4 g3 = *(const float4*)(pf + 3 * 1024 + (kq0 + kq) * 4);
                        a0 += g0.x * wv.x + g0.y * wv.y + g0.z * wv.z + g0.w * wv.w;
                        a1 += g1.x * wv.x + g1.y * wv.y + g1.z * wv.z + g1.w * wv.w;
                        a2 += g2.x * wv.x + g2.y * wv.y + g2.z * wv.z + g2.w * wv.w;
                        a3 += g3.x * wv.x + g3.y * wv.y + g3.z * wv.z + g3.w * wv.w;
                    }
                    psum[(0 * 2 + g) * 128 + lt] = a0;
                    psum[(1 * 2 + g) * 128 + lt] = a1;
                    psum[(2 * 2 + g) * 128 + lt] = a2;
                    psum[(3 * 2 + g) * 128 + lt] = a3;
                }
                __syncthreads();
                for (int idx = tid; idx < 512; idx += NTHREADS) {
                    int r = idx >> 7, o = idx & 127;
                    int row = (grp << 2) + r;
                    float y = psum[(r * 2) * 128 + o] + psum[(r * 2 + 1) * 128 + o] + __ldg(p2_b + o);
                    bf16 xh, xl; split1(y, xh, xl);
                    size_t off = pk_off(row, o);
                    g_xp[0][off] = xh;
                    g_xp[1][off] = xl;
                    out[(size_t)row * SEQL * NOUT + s * NOUT + o] = y;
                }
                __syncthreads();
            }
        }
        gridbar(epoch);
    }
}

// ---------------- launch ----------------
extern "C" void kernel_launch(void* const* d_in, const int* in_sizes, int n_in,
                              void* d_out, int out_size) {
    (void)in_sizes; (void)n_in; (void)out_size;
    cudaFuncSetAttribute(dec_kernel, cudaFuncAttributeMaxDynamicSharedMemorySize, SMEM_BYTES);

    const float* z      = (const float*)d_in[0];
    const float* lin1_w = (const float*)d_in[1];
    const float* lin1_b = (const float*)d_in[2];
    const float* ln1_w  = (const float*)d_in[3];
    const float* ln1_b  = (const float*)d_in[4];
    const float* w_ih0  = (const float*)d_in[5];
    const float* w_hh0  = (const float*)d_in[6];
    const float* b0     = (const float*)d_in[7];
    const float* w_ih1  = (const float*)d_in[8];
    const float* w_hh1  = (const float*)d_in[9];
    const float* b1     = (const float*)d_in[10];
    const float* p1_w   = (const float*)d_in[11];
    const float* p1_b   = (const float*)d_in[12];
    const float* pln_w  = (const float*)d_in[13];
    const float* pln_b  = (const float*)d_in[14];
    const float* p2_w   = (const float*)d_in[15];
    const float* p2_b   = (const float*)d_in[16];

    dec_kernel<<<NBLOCKS, NTHREADS, SMEM_BYTES>>>(
        z, lin1_w, lin1_b, ln1_w, ln1_b,
        w_ih0, w_hh0, b0, w_ih1, w_hh1, b1,
        p1_w, p1_b, pln_w, pln_b, p2_w, p2_b,
        (float*)d_out);
}

// round 9
// speedup vs baseline: 7.8991x; 1.3466x over previous
#include <cuda_runtime.h>
#include <cuda_fp16.h>
#include <mma.h>
#include <math.h>
#include <stdint.h>

using namespace nvcuda;
using fp16 = __half;

#define LATENT 256
#define HID    1024
#define NOUT   128
#define SEQL   96

#define NTHREADS 256
#define NBLOCKS  128
#define LDA    72
#define ABLK   9216          // elems per 128x72 block
#define ABLKB  18432         // bytes per 128x72 fp16 block
#define NSTAGE 4
#define STGMAX 55296         // bytes per stage buffer (A + Bh + Bl at NFW=4)

// smem: 1024 align slack + 1024 hdr (mbars) + 4 stage buffers = 223232
#define SMEM_BYTES (1024 + 1024 + NSTAGE * STGMAX)

// ---------------- device scratch (packed layouts) ----------------
// weights: hi/lo fp16 planes [plane][ntile][kchunk][BN x 72]
__device__ __align__(16) fp16 g_lin1p[2][32 * 4 * 4608];     // BN=64, K=256
__device__ __align__(16) fp16 g_wih0p[2][32 * 2 * 9216];     // BN=128 gated, K=128
__device__ __align__(16) fp16 g_whh0p[2][32 * 16 * 9216];    // BN=128 gated, K=1024
__device__ __align__(16) fp16 g_wih1p[2][32 * 16 * 9216];
__device__ __align__(16) fp16 g_whh1p[2][32 * 16 * 9216];
__device__ __align__(16) fp16 g_p1p[2][32 * 16 * 2304];      // BN=32, K=1024
__device__ __align__(16) float4 g_p2q[256 * 128];            // p2_w transposed k-quad major
// activations: SINGLE fp16 plane, packed [kchunk][mgroup][128 x 72]
__device__ __align__(16) fp16 g_zp[4 * 4 * 9216];
__device__ __align__(16) fp16 g_xp[2 * 4 * 9216];
__device__ __align__(16) fp16 g_h1p[2][16 * 4 * 9216];       // [pingpong]
__device__ __align__(16) fp16 g_h2p[2][16 * 4 * 9216];
__device__ float g_c1[2][512 * HID];
__device__ float g_c2[2][512 * HID];
__device__ float g_u[512 * 2 * HID];
__device__ float g_t[512 * HID];
__device__ volatile unsigned g_arrive[256];
__device__ volatile unsigned g_release;

typedef wmma::fragment<wmma::accumulator, 16, 16, 16, float> CFrag;
typedef wmma::fragment<wmma::matrix_a, 16, 16, 16, fp16, wmma::row_major> AFrag;
typedef wmma::fragment<wmma::matrix_b, 16, 16, 16, fp16, wmma::col_major> BFrag;

// ---------------- PTX helpers ----------------
__device__ __forceinline__ uint32_t smem_u32(const void* p) {
    uint32_t a;
    asm("{ .reg .u64 t; cvta.to.shared.u64 t, %1; cvt.u32.u64 %0, t; }" : "=r"(a) : "l"(p));
    return a;
}
#define MBAR_INIT(a, c) \
    asm volatile("mbarrier.init.shared.b64 [%0], %1;" :: "r"(a), "r"((uint32_t)(c)) : "memory")
#define MBAR_EXPECT(a, n) \
    asm volatile("mbarrier.arrive.expect_tx.shared.b64 _, [%0], %1;" :: "r"(a), "r"((uint32_t)(n)) : "memory")
#define MBAR_ARRIVE(a) \
    asm volatile("mbarrier.arrive.shared.b64 _, [%0];" :: "r"((uint32_t)(a)) : "memory")
#define MBAR_WAIT(a, par) do { \
    uint32_t _m = (a), _p = (par), _d; \
    asm volatile("{\n\t.reg .pred p;\n\t" \
        "mbarrier.try_wait.parity.acquire.cta.shared::cta.b64 p, [%1], %2;\n\t" \
        "selp.b32 %0, 1, 0, p;\n\t}" : "=r"(_d) : "r"(_m), "r"(_p) : "memory"); \
    if (!_d) { \
        asm volatile("{\n\t.reg .pred P1;\n\tWL_%=:\n\t" \
            "mbarrier.try_wait.parity.acquire.cta.shared::cta.b64 P1, [%0], %1, 0x989680;\n\t" \
            "@P1 bra.uni WD_%=;\n\tbra.uni WL_%=;\n\tWD_%=:\n\t}" \
            :: "r"(_m), "r"(_p) : "memory"); \
    } } while (0)
#define BULK_G2S(dst, src, sz, mbar) \
    asm volatile("cp.async.bulk.shared::cluster.global.mbarrier::complete_tx::bytes [%0], [%1], %2, [%3];" \
        :: "r"((uint32_t)(dst)), "l"(src), "r"((uint32_t)(sz)), "r"((uint32_t)(mbar)) : "memory")

// ---------------- grid barrier ----------------
__device__ __forceinline__ void gridbar(unsigned& epoch) {
    epoch++;
    __threadfence();
    __syncthreads();
    if (blockIdx.x == 0) {
        if (threadIdx.x == 0) g_arrive[0] = epoch;
        for (int b = threadIdx.x; b < (int)gridDim.x; b += blockDim.x) {
            while (g_arrive[b] < epoch) { __nanosleep(16); }
        }
        __syncthreads();
        if (threadIdx.x == 0) { __threadfence(); g_release = epoch; }
    } else {
        if (threadIdx.x == 0) {
            g_arrive[blockIdx.x] = epoch;
            while (g_release < epoch) { __nanosleep(16); }
        }
    }
    __syncthreads();
}

// fast activations (~1e-6 rel err)
__device__ __forceinline__ float sigm(float x) {
    return __fdividef(1.f, 1.f + __expf(-x));
}
__device__ __forceinline__ float tanh_f(float x) {
    float e = __expf(2.f * x);
    return 1.f - __fdividef(2.f, e + 1.f);
}
// fp16 hi/lo split (weights; lo may be subnormal -> abs err ~6e-8, fine)
__device__ __forceinline__ void split1(float v, fp16& h, fp16& l) {
    h = __float2half_rn(v);
    l = __float2half_rn(v - __half2float(h));
}

// pack activation offset: (row 0..511, col) -> packed elem index
__device__ __forceinline__ size_t pk_off(int row, int col) {
    return ((size_t)((col >> 6) * 4 + (row >> 7))) * ABLK + (size_t)(row & 127) * LDA + (col & 63);
}

// ---------------- S0 weight packer ----------------
__device__ void pack_w(const float* __restrict__ W, fp16* __restrict__ hi, fp16* __restrict__ lo,
                       int K, int BN, int ntiles, int gated, int gt, int gs)
{
    const int nch = K >> 6;
    const int tot = ntiles * nch * BN * 16;   // float4 units
    for (int i = gt; i < tot; i += gs) {
        int k4 = i & 15;
        int rest = i >> 4;
        int n = rest % BN; rest /= BN;
        int c = rest % nch;
        int nt = rest / nch;
        int row = gated ? ((n >> 5) * HID + nt * 32 + (n & 31)) : (nt * BN + n);
        float4 v = *(const float4*)(W + (size_t)row * K + c * 64 + k4 * 4);
        fp16 h[4], l[4];
        split1(v.x, h[0], l[0]); split1(v.y, h[1], l[1]);
        split1(v.z, h[2], l[2]); split1(v.w, h[3], l[3]);
        size_t d = ((size_t)(nt * nch + c) * BN + n) * LDA + k4 * 4;
        *(uint2*)(hi + d) = *(uint2*)h;
        *(uint2*)(lo + d) = *(uint2*)l;
    }
}

// ---------------- pipeline state ----------------
struct Pipe {
    int fullph[NSTAGE];
    int emptyph[NSTAGE];
    int pcnt, ccnt;
};
struct Seg { const fp16 *a, *bh, *bl; int nch, astr, bstr; };

// ---------------- 4-stage mbar-pipelined wmma GEMM ----------------
// 8 warps: wm = warp>>1 (4 row groups of 32), wn = warp&1 (2 col groups of 16*NFW).
// Block tile 128 x 32*NFW. Warp tile 32 x 16*NFW.
// fp16 2-term: a*bh + a*bl (weights split, activations single plane).
template <int NFW>
__device__ void gemm_pk(CFrag (&acc)[2][NFW], char* P, uint32_t pbase,
                        const Seg* segs, int nseg, Pipe& pp)
{
    constexpr int BB = 32 * NFW * 144;                // B plane bytes
    constexpr uint32_t TX = ABLKB + 2 * BB;
    const int tid = threadIdx.x;
    const int warp = tid >> 5, lane = tid & 31;
    const int wm = warp >> 1, wn = warp & 1;

    int nt = 0;
    for (int s = 0; s < nseg; s++) nt += segs[s].nch;

    auto do_fill = [&](int gidx) {
        int c = gidx, si = 0;
        while (c >= segs[si].nch) { c -= segs[si].nch; si++; }
        const Seg& S = segs[si];
        int st = pp.pcnt % NSTAGE;
        if (tid == 0) {
            MBAR_WAIT(pbase + 32 + (st << 3), (uint32_t)(pp.emptyph[st] & 1));
            uint32_t d = pbase + 1024 + st * STGMAX;
            uint32_t mb = pbase + (st << 3);
            MBAR_EXPECT(mb, TX);
            BULK_G2S(d,              (const char*)(S.a  + (size_t)c * S.astr), ABLKB, mb);
            BULK_G2S(d + ABLKB,      (const char*)(S.bh + (size_t)c * S.bstr), BB, mb);
            BULK_G2S(d + ABLKB + BB, (const char*)(S.bl + (size_t)c * S.bstr), BB, mb);
        }
        pp.emptyph[st]++;
        pp.pcnt++;
    };

    const int pre = nt < 3 ? nt : 3;
    for (int g = 0; g < pre; g++) do_fill(g);

    for (int i = 0; i < nt; i++) {
        if (i + 3 < nt) do_fill(i + 3);
        const int st = pp.ccnt % NSTAGE;
        MBAR_WAIT(pbase + (st << 3), (uint32_t)(pp.fullph[st] & 1));
        pp.fullph[st]++;
        pp.ccnt++;

        const fp16* sA  = (const fp16*)(P + 1024 + st * STGMAX);
        const fp16* sBh = sA + ABLK;
        const fp16* sBl = sBh + 32 * NFW * LDA;
        #pragma unroll
        for (int kk = 0; kk < 4; kk++) {
            AFrag a0, a1;
            wmma::load_matrix_sync(a0, sA + (wm * 32 + 0)  * LDA + kk * 16, LDA);
            wmma::load_matrix_sync(a1, sA + (wm * 32 + 16) * LDA + kk * 16, LDA);
            BFrag bf[NFW];
            #pragma unroll
            for (int nf = 0; nf < NFW; nf++)
                wmma::load_matrix_sync(bf[nf], sBh + (wn * (16 * NFW) + nf * 16) * LDA + kk * 16, LDA);
            // term 1: a * bh   (2*NFW independent accumulators in flight)
            #pragma unroll
            for (int nf = 0; nf < NFW; nf++) {
                wmma::mma_sync(acc[0][nf], a0, bf[nf], acc[0][nf]);
                wmma::mma_sync(acc[1][nf], a1, bf[nf], acc[1][nf]);
            }
            // term 2: a * bl
            #pragma unroll
            for (int nf = 0; nf < NFW; nf++)
                wmma::load_matrix_sync(bf[nf], sBl + (wn * (16 * NFW) + nf * 16) * LDA + kk * 16, LDA);
            #pragma unroll
            for (int nf = 0; nf < NFW; nf++) {
                wmma::mma_sync(acc[0][nf], a0, bf[nf], acc[0][nf]);
                wmma::mma_sync(acc[1][nf], a1, bf[nf], acc[1][nf]);
            }
        }
        if (lane == 0) MBAR_ARRIVE(pbase + 32 + (st << 3));
    }
}

// ---------------- epilogues (syncthreads at entry: patch aliases stage smem) ----------------
__device__ void lstm_epi(CFrag (&acc)[2][4], char* P, const float* __restrict__ bias,
                         const float* __restrict__ c_in, float* __restrict__ c_out,
                         fp16* __restrict__ hp,
                         int mbase, int jbase)
{
    __syncthreads();                      // lagging warps may still read stages
    float* pf = (float*)(P + 1024);       // patch [128][132]
    const int tid = threadIdx.x, warp = tid >> 5;
    const int wm = warp >> 1, wn = warp & 1;
    #pragma unroll
    for (int i = 0; i < 2; i++)
        #pragma unroll
        for (int nf = 0; nf < 4; nf++)
            wmma::store_matrix_sync(pf + (wm * 32 + i * 16) * 132 + wn * 64 + nf * 16,
                                    acc[i][nf], 132, wmma::mem_row_major);
    __syncthreads();
    #pragma unroll 4
    for (int e = tid; e < 128 * 32; e += NTHREADS) {
        int r = e >> 5, j = e & 31;
        int row = mbase + r, col = jbase + j;
        float iv = pf[r * 132 + j]      + __ldg(bias + col);
        float fv = pf[r * 132 + 32 + j] + __ldg(bias + HID + col);
        float gv = pf[r * 132 + 64 + j] + __ldg(bias + 2 * HID + col);
        float ov = pf[r * 132 + 96 + j] + __ldg(bias + 3 * HID + col);
        float cold = __ldcg(c_in + (size_t)row * HID + col);
        float cn = sigm(fv) * cold + sigm(iv) * tanh_f(gv);
        float hn = sigm(ov) * tanh_f(cn);
        c_out[(size_t)row * HID + col] = cn;
        hp[pk_off(row, col)] = __float2half_rn(hn);
    }
    __syncthreads();
}

template <int NFW>
__device__ void store_epi(CFrag (&acc)[2][NFW], char* P, const float* __restrict__ bias,
                          float* __restrict__ dst, int stride, int mbase, int nbase)
{
    __syncthreads();
    constexpr int BN = 32 * NFW, PS = BN + 4;
    float* pf = (float*)(P + 1024);
    const int tid = threadIdx.x, warp = tid >> 5;
    const int wm = warp >> 1, wn = warp & 1;
    #pragma unroll
    for (int i = 0; i < 2; i++)
        #pragma unroll
        for (int nf = 0; nf < NFW; nf++)
            wmma::store_matrix_sync(pf + (wm * 32 + i * 16) * PS + wn * (16 * NFW) + nf * 16,
                                    acc[i][nf], PS, wmma::mem_row_major);
    __syncthreads();
    for (int e = tid; e < 128 * BN; e += NTHREADS) {
        int r = e / BN, c = e % BN;
        dst[(size_t)(mbase + r) * stride + nbase + c] = pf[r * PS + c] + __ldg(bias + nbase + c);
    }
    __syncthreads();
}

// ---------------- the persistent decoder kernel ----------------
__global__ void __launch_bounds__(NTHREADS, 1) dec_kernel(
    const float* __restrict__ z,     const float* __restrict__ lin1_w, const float* __restrict__ lin1_b,
    const float* __restrict__ ln1_w, const float* __restrict__ ln1_b,
    const float* __restrict__ w_ih0, const float* __restrict__ w_hh0,  const float* __restrict__ b0,
    const float* __restrict__ w_ih1, const float* __restrict__ w_hh1,  const float* __restrict__ b1,
    const float* __restrict__ p1_w,  const float* __restrict__ p1_b,
    const float* __restrict__ pln_w, const float* __restrict__ pln_b,
    const float* __restrict__ p2_w,  const float* __restrict__ p2_b,
    float* __restrict__ out)
{
    extern __shared__ char pool[];
    __shared__ float redA[8], redB[8];
    const int bid = blockIdx.x, nb = gridDim.x, tid = threadIdx.x;
    const int lane = tid & 31;
    uint32_t raw = smem_u32(pool);
    uint32_t pbase = (raw + 1023) & ~1023u;
    char* P = pool + (pbase - raw);
    unsigned epoch = g_release;
    Pipe pp;
    #pragma unroll
    for (int s = 0; s < NSTAGE; s++) { pp.fullph[s] = 0; pp.emptyph[s] = 0; }
    pp.pcnt = 0; pp.ccnt = 0;

    if (tid == 0) {
        #pragma unroll
        for (int s = 0; s < NSTAGE; s++) {
            MBAR_INIT(pbase + (s << 3), 1);       // full: tx-based
            MBAR_INIT(pbase + 32 + (s << 3), 8);  // empty: one arrive per warp
        }
    }
    __syncthreads();
    if (lane == 0) {   // arm all empties (8 warps x lane0 = 8 arrivals each)
        MBAR_ARRIVE(pbase + 32);
        MBAR_ARRIVE(pbase + 40);
        MBAR_ARRIVE(pbase + 48);
        MBAR_ARRIVE(pbase + 56);
    }
    __syncthreads();

    // ---- S0: pack weights (fp16 hi/lo); pack z (single fp16); transpose p2; zero x
    {
        int gt = bid * NTHREADS + tid, gs = nb * NTHREADS;
        pack_w(lin1_w, g_lin1p[0], g_lin1p[1], LATENT, 64, 32, 0, gt, gs);
        pack_w(w_ih0,  g_wih0p[0], g_wih0p[1], NOUT, 128, 32, 1, gt, gs);
        pack_w(w_hh0,  g_whh0p[0], g_whh0p[1], HID, 128, 32, 1, gt, gs);
        pack_w(w_ih1,  g_wih1p[0], g_wih1p[1], HID, 128, 32, 1, gt, gs);
        pack_w(w_hh1,  g_whh1p[0], g_whh1p[1], HID, 128, 32, 1, gt, gs);
        pack_w(p1_w,   g_p1p[0],   g_p1p[1],   HID, 32, 32, 0, gt, gs);
        for (int i = gt; i < 4 * 4 * 128 * 16; i += gs) {
            int k4 = i & 15, r = (i >> 4) & 127, mg = (i >> 11) & 3, c = i >> 13;
            float4 v = *(const float4*)(z + (size_t)(mg * 128 + r) * LATENT + c * 64 + k4 * 4);
            fp16 h[4];
            h[0] = __float2half_rn(v.x); h[1] = __float2half_rn(v.y);
            h[2] = __float2half_rn(v.z); h[3] = __float2half_rn(v.w);
            size_t d = (size_t)(c * 4 + mg) * ABLK + (size_t)r * LDA + k4 * 4;
            *(uint2*)(g_zp + d) = *(uint2*)h;
        }
        // p2 transposed quads: g_p2q[kq*128 + o] = p2_w[o][4kq..4kq+3]
        for (int i = gt; i < 256 * 128; i += gs) {
            int o = i & 127, kq = i >> 7;
            g_p2q[i] = *(const float4*)(p2_w + (size_t)o * HID + kq * 4);
        }
        for (int i = gt; i < 2 * 4 * ABLK; i += gs) {
            g_xp[i] = __float2half_rn(0.f);
        }
    }
    gridbar(epoch);

    // ---- S1: u = z @ lin1_w^T + lin1_b  (512 x 2048): 128 tiles of 128x64
    {
        int mg = bid >> 5, nt = bid & 31;
        CFrag acc[2][2];
        #pragma unroll
        for (int i = 0; i < 2; i++) { wmma::fill_fragment(acc[i][0], 0.f); wmma::fill_fragment(acc[i][1], 0.f); }
        Seg sg[1] = {{g_zp + (size_t)mg * ABLK,
                      g_lin1p[0] + (size_t)nt * 4 * 4608, g_lin1p[1] + (size_t)nt * 4 * 4608,
                      4, 4 * ABLK, 4608}};
        gemm_pk<2>(acc, P, pbase, sg, 1, pp);
        store_epi<2>(acc, P, lin1_b, g_u, 2 * HID, mg << 7, nt << 6);
    }
    gridbar(epoch);

    // ---- S2: LayerNorm(2048) + gelu -> h0/c0 (both cells), 2 rows per pass
    {
        float* pf = (float*)(P + 1024);
        const int g = tid >> 7, lt = tid & 127, w4 = (tid >> 5) & 3;
        for (int grp = bid; grp < 128; grp += nb) {
            for (int pass = 0; pass < 2; pass++) {
                int row = (grp << 2) + pass * 2 + g;
                const float* urow = g_u + (size_t)row * 2 * HID;
                float ls = 0.f, lq = 0.f;
                #pragma unroll
                for (int u = 0; u < 16; u++) {
                    float v = __ldcg(urow + u * 128 + lt);
                    pf[g * 2048 + u * 128 + lt] = v;
                    ls += v; lq += v * v;
                }
                #pragma unroll
                for (int o = 16; o > 0; o >>= 1) {
                    ls += __shfl_down_sync(0xffffffffu, ls, o);
                    lq += __shfl_down_sync(0xffffffffu, lq, o);
                }
                if (lane == 0) { redA[g * 4 + w4] = ls; redB[g * 4 + w4] = lq; }
                __syncthreads();
                float S = redA[g * 4] + redA[g * 4 + 1] + redA[g * 4 + 2] + redA[g * 4 + 3];
                float Q = redB[g * 4] + redB[g * 4 + 1] + redB[g * 4 + 2] + redB[g * 4 + 3];
                float mu = S * (1.f / 2048.f);
                float rstd = rsqrtf(Q * (1.f / 2048.f) - mu * mu + 1e-5f);
                #pragma unroll
                for (int u = 0; u < 16; u++) {
                    int i = u * 128 + lt;
                    float v = (pf[g * 2048 + i] - mu) * rstd * __ldg(ln1_w + i) + __ldg(ln1_b + i);
                    float ge = v * normcdff(v);
                    if (i < HID) {
                        fp16 hv = __float2half_rn(ge);
                        size_t off = pk_off(row, i);
                        g_h1p[0][off] = hv;
                        g_h2p[0][off] = hv;
                    } else {
                        g_c1[0][(size_t)row * HID + i - HID] = ge;
                        g_c2[0][(size_t)row * HID + i - HID] = ge;
                    }
                }
                __syncthreads();
            }
        }
    }
    gridbar(epoch);

    // ---- main sequential loop
    for (int s = 0; s < SEQL; s++) {
        const int pi = s & 1, po = pi ^ 1;
        const int mg = (bid >> 5) & 3, ntl = bid & 31;

        // P1: (h1,c1) = lstm0(x, h1, c1) : K = 128 + 1024 (18 chunks streamed)
        {
            CFrag acc[2][4];
            #pragma unroll
            for (int i = 0; i < 2; i++)
                #pragma unroll
                for (int j = 0; j < 4; j++) wmma::fill_fragment(acc[i][j], 0.f);
            Seg sg[2] = {
                {g_xp + (size_t)mg * ABLK,
                 g_wih0p[0] + (size_t)ntl * 2 * 9216, g_wih0p[1] + (size_t)ntl * 2 * 9216,
                 2, 4 * ABLK, 9216},
                {g_h1p[pi] + (size_t)mg * ABLK,
                 g_whh0p[0] + (size_t)ntl * 16 * 9216, g_whh0p[1] + (size_t)ntl * 16 * 9216,
                 16, 4 * ABLK, 9216}};
            gemm_pk<4>(acc, P, pbase, sg, 2, pp);
            lstm_epi(acc, P, b0, g_c1[pi], g_c1[po], g_h1p[po], mg << 7, ntl << 5);
        }
        gridbar(epoch);

        // P2: (h2,c2) = lstm1(h1_new, h2, c2) : K = 1024 + 1024 (32 chunks)
        {
            CFrag acc[2][4];
            #pragma unroll
            for (int i = 0; i < 2; i++)
                #pragma unroll
                for (int j = 0; j < 4; j++) wmma::fill_fragment(acc[i][j], 0.f);
            Seg sg[2] = {
                {g_h1p[po] + (size_t)mg * ABLK,
                 g_wih1p[0] + (size_t)ntl * 16 * 9216, g_wih1p[1] + (size_t)ntl * 16 * 9216,
                 16, 4 * ABLK, 9216},
                {g_h2p[pi] + (size_t)mg * ABLK,
                 g_whh1p[0] + (size_t)ntl * 16 * 9216, g_whh1p[1] + (size_t)ntl * 16 * 9216,
                 16, 4 * ABLK, 9216}};
            gemm_pk<4>(acc, P, pbase, sg, 2, pp);
            lstm_epi(acc, P, b1, g_c2[pi], g_c2[po], g_h2p[po], mg << 7, ntl << 5);
        }
        gridbar(epoch);

        // P3: t = h2_new @ p1_w^T + p1_b : 128 tiles of 128x32 (all blocks active)
        {
            CFrag acc[2][1];
            wmma::fill_fragment(acc[0][0], 0.f);
            wmma::fill_fragment(acc[1][0], 0.f);
            Seg sg[1] = {{g_h2p[po] + (size_t)mg * ABLK,
                          g_p1p[0] + (size_t)ntl * 16 * 2304, g_p1p[1] + (size_t)ntl * 16 * 2304,
                          16, 4 * ABLK, 2304}};
            gemm_pk<1>(acc, P, pbase, sg, 1, pp);
            store_epi<1>(acc, P, p1_b, g_t, HID, mg << 7, ntl << 5);
        }
        gridbar(epoch);

        // P4: LayerNorm + gelu (4 rows, 2 passes) then coalesced GEMV via g_p2q
        {
            float* pf = (float*)(P + 1024);        // [4][1024] gelu vals + [8][128] partials
            float* psum = pf + 4096;
            const int g = tid >> 7, lt = tid & 127, w4 = (tid >> 5) & 3;
            for (int grp = bid; grp < 128; grp += nb) {
                for (int pass = 0; pass < 2; pass++) {
                    int rr = pass * 2 + g;
                    int row = (grp << 2) + rr;
                    const float* trow = g_t + (size_t)row * HID;
                    float vb[8]; float ls = 0.f, lq = 0.f;
                    #pragma unroll
                    for (int u = 0; u < 8; u++) {
                        float v = __ldcg(trow + u * 128 + lt);
                        vb[u] = v; ls += v; lq += v * v;
                    }
                    #pragma unroll
                    for (int o = 16; o > 0; o >>= 1) {
                        ls += __shfl_down_sync(0xffffffffu, ls, o);
                        lq += __shfl_down_sync(0xffffffffu, lq, o);
                    }
                    if (lane == 0) { redA[g * 4 + w4] = ls; redB[g * 4 + w4] = lq; }
                    __syncthreads();
                    float S = redA[g * 4] + redA[g * 4 + 1] + redA[g * 4 + 2] + redA[g * 4 + 3];
                    float Q = redB[g * 4] + redB[g * 4 + 1] + redB[g * 4 + 2] + redB[g * 4 + 3];
                    float mu = S * (1.f / 1024.f);
                    float rstd = rsqrtf(Q * (1.f / 1024.f) - mu * mu + 1e-5f);
                    #pragma unroll
                    for (int u = 0; u < 8; u++) {
                        int i = u * 128 + lt;
                        float v = (vb[u] - mu) * rstd * __ldg(pln_w + i) + __ldg(pln_b + i);
                        pf[rr * 1024 + i] = v * normcdff(v);
                    }
                    __syncthreads();
                }
                // GEMV: thread (o=lt, half=g) does K-half 512 for all 4 rows, coalesced loads
                {
                    float a0 = 0.f, a1 = 0.f, a2 = 0.f, a3 = 0.f;
                    const int kq0 = g * 128;
                    #pragma unroll 2
                    for (int kq = 0; kq < 128; kq++) {
                        float4 wv = g_p2q[(size_t)(kq0 + kq) * 128 + lt];
                        float4 g0 = *(const float4*)(pf + 0 * 1024 + (kq0 + kq) * 4);
                        float4 g1 = *(const float4*)(pf + 1 * 1024 + (kq0 + kq) * 4);
                        float4 g2 = *(const float4*)(pf + 2 * 1024 + (kq0 + kq) * 4);
                        float4 g3 = *(const float4*)(pf + 3 * 1024 + (kq0 + kq) * 4);
                        a0 += g0.x * wv.x + g0.y * wv.y + g0.z * wv.z + g0.w * wv.w;
                        a1 += g1.x * wv.x + g1.y * wv.y + g1.z * wv.z + g1.w * wv.w;
                        a2 += g2.x * wv.x + g2.y * wv.y + g2.z * wv.z + g2.w * wv.w;
                        a3 += g3.x * wv.x + g3.y * wv.y + g3.z * wv.z + g3.w * wv.w;
                    }
                    psum[(0 * 2 + g) * 128 + lt] = a0;
                    psum[(1 * 2 + g) * 128 + lt] = a1;
                    psum[(2 * 2 + g) * 128 + lt] = a2;
                    psum[(3 * 2 + g) * 128 + lt] = a3;
                }
                __syncthreads();
                for (int idx = tid; idx < 512; idx += NTHREADS) {
                    int r = idx >> 7, o = idx & 127;
                    int row = (grp << 2) + r;
                    float y = psum[(r * 2) * 128 + o] + psum[(r * 2 + 1) * 128 + o] + __ldg(p2_b + o);
                    g_xp[pk_off(row, o)] = __float2half_rn(y);
                    out[(size_t)row * SEQL * NOUT + s * NOUT + o] = y;
                }
                __syncthreads();
            }
        }
        gridbar(epoch);
    }
}

// ---------------- launch ----------------
extern "C" void kernel_launch(void* const* d_in, const int* in_sizes, int n_in,
                              void* d_out, int out_size) {
    (void)in_sizes; (void)n_in; (void)out_size;
    cudaFuncSetAttribute(dec_kernel, cudaFuncAttributeMaxDynamicSharedMemorySize, SMEM_BYTES);

    const float* z      = (const float*)d_in[0];
    const float* lin1_w = (const float*)d_in[1];
    const float* lin1_b = (const float*)d_in[2];
    const float* ln1_w  = (const float*)d_in[3];
    const float* ln1_b  = (const float*)d_in[4];
    const float* w_ih0  = (const float*)d_in[5];
    const float* w_hh0  = (const float*)d_in[6];
    const float* b0     = (const float*)d_in[7];
    const float* w_ih1  = (const float*)d_in[8];
    const float* w_hh1  = (const float*)d_in[9];
    const float* b1     = (const float*)d_in[10];
    const float* p1_w   = (const float*)d_in[11];
    const float* p1_b   = (const float*)d_in[12];
    const float* pln_w  = (const float*)d_in[13];
    const float* pln_b  = (const float*)d_in[14];
    const float* p2_w   = (const float*)d_in[15];
    const float* p2_b   = (const float*)d_in[16];

    dec_kernel<<<NBLOCKS, NTHREADS, SMEM_BYTES>>>(
        z, lin1_w, lin1_b, ln1_w, ln1_b,
        w_ih0, w_hh0, b0, w_ih1, w_hh1, b1,
        p1_w, p1_b, pln_w, pln_b, p2_w, p2_b,
        (float*)d_out);
}

// round 11
// speedup vs baseline: 12.2799x; 1.5546x over previous
#include <cuda_runtime.h>
#include <cuda_fp16.h>
#include <mma.h>
#include <math.h>
#include <stdint.h>

using namespace nvcuda;
using fp16 = __half;

#define LATENT 256
#define HID    1024
#define NOUT   128
#define SEQL   96

#define NTHREADS 256
#define NBLOCKS  128
#define LDA    72
#define ABLK   9216          // elems per 128x72 block
#define ABLKB  18432         // bytes per 128x72 fp16 block
#define NSTAGE 6
#define STGMAX 36864         // bytes per stage buffer (A + B at NFW=4)

// smem: 1024 align slack + 1024 hdr (mbars) + 6 stage buffers = 223232
#define SMEM_BYTES (1024 + 1024 + NSTAGE * STGMAX)

// ---------------- device scratch (packed layouts) ----------------
// weights: single fp16 plane [ntile][kchunk][BN x 72]
__device__ __align__(16) fp16 g_lin1p[32 * 4 * 4608];     // BN=64, K=256
__device__ __align__(16) fp16 g_wih0p[32 * 2 * 9216];     // BN=128 gated, K=128
__device__ __align__(16) fp16 g_whh0p[32 * 16 * 9216];    // BN=128 gated, K=1024
__device__ __align__(16) fp16 g_wih1p[32 * 16 * 9216];
__device__ __align__(16) fp16 g_whh1p[32 * 16 * 9216];
__device__ __align__(16) fp16 g_p1p[32 * 16 * 2304];      // BN=32, K=1024
__device__ __align__(16) float4 g_p2q[256 * 128];         // p2_w transposed k-quad major
// activations: single fp16 plane, packed [kchunk][mgroup][128 x 72]
__device__ __align__(16) fp16 g_zp[4 * 4 * 9216];
__device__ __align__(16) fp16 g_xp[2 * 4 * 9216];
__device__ __align__(16) fp16 g_h1p[2][16 * 4 * 9216];    // [pingpong]
__device__ __align__(16) fp16 g_h2p[2][16 * 4 * 9216];
__device__ float g_c1[2][512 * HID];
__device__ float g_c2[2][512 * HID];
__device__ float g_u[512 * 2 * HID];
__device__ float g_t[512 * HID];
__device__ volatile unsigned g_arrive[256];
__device__ volatile unsigned g_release;

typedef wmma::fragment<wmma::accumulator, 16, 16, 16, float> CFrag;
typedef wmma::fragment<wmma::matrix_a, 16, 16, 16, fp16, wmma::row_major> AFrag;
typedef wmma::fragment<wmma::matrix_b, 16, 16, 16, fp16, wmma::col_major> BFrag;

// ---------------- PTX helpers ----------------
__device__ __forceinline__ uint32_t smem_u32(const void* p) {
    uint32_t a;
    asm("{ .reg .u64 t; cvta.to.shared.u64 t, %1; cvt.u32.u64 %0, t; }" : "=r"(a) : "l"(p));
    return a;
}
#define MBAR_INIT(a, c) \
    asm volatile("mbarrier.init.shared.b64 [%0], %1;" :: "r"(a), "r"((uint32_t)(c)) : "memory")
#define MBAR_EXPECT(a, n) \
    asm volatile("mbarrier.arrive.expect_tx.shared.b64 _, [%0], %1;" :: "r"(a), "r"((uint32_t)(n)) : "memory")
#define MBAR_ARRIVE(a) \
    asm volatile("mbarrier.arrive.shared.b64 _, [%0];" :: "r"((uint32_t)(a)) : "memory")
#define MBAR_WAIT(a, par) do { \
    uint32_t _m = (a), _p = (par), _d; \
    asm volatile("{\n\t.reg .pred p;\n\t" \
        "mbarrier.try_wait.parity.acquire.cta.shared::cta.b64 p, [%1], %2;\n\t" \
        "selp.b32 %0, 1, 0, p;\n\t}" : "=r"(_d) : "r"(_m), "r"(_p) : "memory"); \
    if (!_d) { \
        asm volatile("{\n\t.reg .pred P1;\n\tWL_%=:\n\t" \
            "mbarrier.try_wait.parity.acquire.cta.shared::cta.b64 P1, [%0], %1, 0x989680;\n\t" \
            "@P1 bra.uni WD_%=;\n\tbra.uni WL_%=;\n\tWD_%=:\n\t}" \
            :: "r"(_m), "r"(_p) : "memory"); \
    } } while (0)
#define BULK_G2S(dst, src, sz, mbar) \
    asm volatile("cp.async.bulk.shared::cluster.global.mbarrier::complete_tx::bytes [%0], [%1], %2, [%3];" \
        :: "r"((uint32_t)(dst)), "l"(src), "r"((uint32_t)(sz)), "r"((uint32_t)(mbar)) : "memory")

// ---------------- grid barrier ----------------
__device__ __forceinline__ void gridbar(unsigned& epoch) {
    epoch++;
    __threadfence();
    __syncthreads();
    if (blockIdx.x == 0) {
        if (threadIdx.x == 0) g_arrive[0] = epoch;
        for (int b = threadIdx.x; b < (int)gridDim.x; b += blockDim.x) {
            while (g_arrive[b] < epoch) { __nanosleep(16); }
        }
        __syncthreads();
        if (threadIdx.x == 0) { __threadfence(); g_release = epoch; }
    } else {
        if (threadIdx.x == 0) {
            g_arrive[blockIdx.x] = epoch;
            while (g_release < epoch) { __nanosleep(16); }
        }
    }
    __syncthreads();
}

// fast activations (~1e-6 rel err)
__device__ __forceinline__ float sigm(float x) {
    return __fdividef(1.f, 1.f + __expf(-x));
}
__device__ __forceinline__ float tanh_f(float x) {
    float e = __expf(2.f * x);
    return 1.f - __fdividef(2.f, e + 1.f);
}

// pack activation offset: (row 0..511, col) -> packed elem index
__device__ __forceinline__ size_t pk_off(int row, int col) {
    return ((size_t)((col >> 6) * 4 + (row >> 7))) * ABLK + (size_t)(row & 127) * LDA + (col & 63);
}

// ---------------- S0 weight packer (single fp16 plane) ----------------
__device__ void pack_w(const float* __restrict__ W, fp16* __restrict__ dst,
                       int K, int BN, int ntiles, int gated, int gt, int gs)
{
    const int nch = K >> 6;
    const int tot = ntiles * nch * BN * 16;   // float4 units
    for (int i = gt; i < tot; i += gs) {
        int k4 = i & 15;
        int rest = i >> 4;
        int n = rest % BN; rest /= BN;
        int c = rest % nch;
        int nt = rest / nch;
        int row = gated ? ((n >> 5) * HID + nt * 32 + (n & 31)) : (nt * BN + n);
        float4 v = *(const float4*)(W + (size_t)row * K + c * 64 + k4 * 4);
        fp16 h[4];
        h[0] = __float2half_rn(v.x); h[1] = __float2half_rn(v.y);
        h[2] = __float2half_rn(v.z); h[3] = __float2half_rn(v.w);
        size_t d = ((size_t)(nt * nch + c) * BN + n) * LDA + k4 * 4;
        *(uint2*)(dst + d) = *(uint2*)h;
    }
}

// ---------------- pipeline state ----------------
struct Pipe {
    int fullph[NSTAGE];
    int emptyph[NSTAGE];
    int pcnt, ccnt;
};
struct Seg { const fp16 *a, *b; int nch, astr, bstr; };

// ---------------- 6-stage mbar-pipelined wmma GEMM (pure fp16, 1 term) ----------------
// 8 warps: wm = warp>>1 (4 row groups of 32), wn = warp&1 (2 col groups of 16*NFW).
// Block tile 128 x 32*NFW. Warp tile 32 x 16*NFW.
template <int NFW>
__device__ void gemm_pk(CFrag (&acc)[2][NFW], char* P, uint32_t pbase,
                        const Seg* segs, int nseg, Pipe& pp)
{
    constexpr int BB = 32 * NFW * 144;                // B plane bytes
    constexpr uint32_t TX = ABLKB + BB;
    const int tid = threadIdx.x;
    const int warp = tid >> 5, lane = tid & 31;
    const int wm = warp >> 1, wn = warp & 1;

    int nt = 0;
    for (int s = 0; s < nseg; s++) nt += segs[s].nch;

    auto do_fill = [&](int gidx) {
        int c = gidx, si = 0;
        while (c >= segs[si].nch) { c -= segs[si].nch; si++; }
        const Seg& S = segs[si];
        int st = pp.pcnt % NSTAGE;
        if (tid == 0) {
            MBAR_WAIT(pbase + 64 + (st << 3), (uint32_t)(pp.emptyph[st] & 1));
            uint32_t d = pbase + 1024 + st * STGMAX;
            uint32_t mb = pbase + (st << 3);
            MBAR_EXPECT(mb, TX);
            BULK_G2S(d,         (const char*)(S.a + (size_t)c * S.astr), ABLKB, mb);
            BULK_G2S(d + ABLKB, (const char*)(S.b + (size_t)c * S.bstr), BB, mb);
        }
        pp.emptyph[st]++;
        pp.pcnt++;
    };

    const int pre = nt < 4 ? nt : 4;
    for (int g = 0; g < pre; g++) do_fill(g);

    for (int i = 0; i < nt; i++) {
        if (i + 4 < nt) do_fill(i + 4);
        const int st = pp.ccnt % NSTAGE;
        MBAR_WAIT(pbase + (st << 3), (uint32_t)(pp.fullph[st] & 1));
        pp.fullph[st]++;
        pp.ccnt++;

        const fp16* sA = (const fp16*)(P + 1024 + st * STGMAX);
        const fp16* sB = sA + ABLK;
        #pragma unroll
        for (int kk = 0; kk < 4; kk++) {
            AFrag a0, a1;
            wmma::load_matrix_sync(a0, sA + (wm * 32 + 0)  * LDA + kk * 16, LDA);
            wmma::load_matrix_sync(a1, sA + (wm * 32 + 16) * LDA + kk * 16, LDA);
            BFrag bf[NFW];
            #pragma unroll
            for (int nf = 0; nf < NFW; nf++)
                wmma::load_matrix_sync(bf[nf], sB + (wn * (16 * NFW) + nf * 16) * LDA + kk * 16, LDA);
            #pragma unroll
            for (int nf = 0; nf < NFW; nf++) {
                wmma::mma_sync(acc[0][nf], a0, bf[nf], acc[0][nf]);
                wmma::mma_sync(acc[1][nf], a1, bf[nf], acc[1][nf]);
            }
        }
        if (lane == 0) MBAR_ARRIVE(pbase + 64 + (st << 3));
    }
}

// ---------------- epilogues (syncthreads at entry: patch aliases stage smem) ----------------
__device__ void lstm_epi(CFrag (&acc)[2][4], char* P, const float* __restrict__ bias,
                         const float* __restrict__ c_in, float* __restrict__ c_out,
                         fp16* __restrict__ hp,
                         int mbase, int jbase)
{
    __syncthreads();                      // lagging warps may still read stages
    float* pf = (float*)(P + 1024);       // patch [128][132]
    const int tid = threadIdx.x, warp = tid >> 5;
    const int wm = warp >> 1, wn = warp & 1;
    #pragma unroll
    for (int i = 0; i < 2; i++)
        #pragma unroll
        for (int nf = 0; nf < 4; nf++)
            wmma::store_matrix_sync(pf + (wm * 32 + i * 16) * 132 + wn * 64 + nf * 16,
                                    acc[i][nf], 132, wmma::mem_row_major);
    __syncthreads();
    #pragma unroll 4
    for (int e = tid; e < 128 * 32; e += NTHREADS) {
        int r = e >> 5, j = e & 31;
        int row = mbase + r, col = jbase + j;
        float iv = pf[r * 132 + j]      + __ldg(bias + col);
        float fv = pf[r * 132 + 32 + j] + __ldg(bias + HID + col);
        float gv = pf[r * 132 + 64 + j] + __ldg(bias + 2 * HID + col);
        float ov = pf[r * 132 + 96 + j] + __ldg(bias + 3 * HID + col);
        float cold = __ldcg(c_in + (size_t)row * HID + col);
        float cn = sigm(fv) * cold + sigm(iv) * tanh_f(gv);
        float hn = sigm(ov) * tanh_f(cn);
        c_out[(size_t)row * HID + col] = cn;
        hp[pk_off(row, col)] = __float2half_rn(hn);
    }
    __syncthreads();
}

template <int NFW>
__device__ void store_epi(CFrag (&acc)[2][NFW], char* P, const float* __restrict__ bias,
                          float* __restrict__ dst, int stride, int mbase, int nbase)
{
    __syncthreads();
    constexpr int BN = 32 * NFW, PS = BN + 4;
    float* pf = (float*)(P + 1024);
    const int tid = threadIdx.x, warp = tid >> 5;
    const int wm = warp >> 1, wn = warp & 1;
    #pragma unroll
    for (int i = 0; i < 2; i++)
        #pragma unroll
        for (int nf = 0; nf < NFW; nf++)
            wmma::store_matrix_sync(pf + (wm * 32 + i * 16) * PS + wn * (16 * NFW) + nf * 16,
                                    acc[i][nf], PS, wmma::mem_row_major);
    __syncthreads();
    for (int e = tid; e < 128 * BN; e += NTHREADS) {
        int r = e / BN, c = e % BN;
        dst[(size_t)(mbase + r) * stride + nbase + c] = pf[r * PS + c] + __ldg(bias + nbase + c);
    }
    __syncthreads();
}

// ---------------- the persistent decoder kernel ----------------
__global__ void __launch_bounds__(NTHREADS, 1) dec_kernel(
    const float* __restrict__ z,     const float* __restrict__ lin1_w, const float* __restrict__ lin1_b,
    const float* __restrict__ ln1_w, const float* __restrict__ ln1_b,
    const float* __restrict__ w_ih0, const float* __restrict__ w_hh0,  const float* __restrict__ b0,
    const float* __restrict__ w_ih1, const float* __restrict__ w_hh1,  const float* __restrict__ b1,
    const float* __restrict__ p1_w,  const float* __restrict__ p1_b,
    const float* __restrict__ pln_w, const float* __restrict__ pln_b,
    const float* __restrict__ p2_w,  const float* __restrict__ p2_b,
    float* __restrict__ out)
{
    extern __shared__ char pool[];
    __shared__ float redA[8], redB[8];
    const int bid = blockIdx.x, nb = gridDim.x, tid = threadIdx.x;
    const int lane = tid & 31;
    uint32_t raw = smem_u32(pool);
    uint32_t pbase = (raw + 1023) & ~1023u;
    char* P = pool + (pbase - raw);
    unsigned epoch = g_release;
    Pipe pp;
    #pragma unroll
    for (int s = 0; s < NSTAGE; s++) { pp.fullph[s] = 0; pp.emptyph[s] = 0; }
    pp.pcnt = 0; pp.ccnt = 0;

    if (tid == 0) {
        #pragma unroll
        for (int s = 0; s < NSTAGE; s++) {
            MBAR_INIT(pbase + (s << 3), 1);       // full: tx-based
            MBAR_INIT(pbase + 64 + (s << 3), 8);  // empty: one arrive per warp
        }
    }
    __syncthreads();
    if (lane == 0) {   // arm all empties (8 warps x lane0 = 8 arrivals each)
        #pragma unroll
        for (int s = 0; s < NSTAGE; s++) MBAR_ARRIVE(pbase + 64 + (s << 3));
    }
    __syncthreads();

    // ---- S0: pack weights (fp16); pack z; transpose p2; zero x
    {
        int gt = bid * NTHREADS + tid, gs = nb * NTHREADS;
        pack_w(lin1_w, g_lin1p, LATENT, 64, 32, 0, gt, gs);
        pack_w(w_ih0,  g_wih0p, NOUT, 128, 32, 1, gt, gs);
        pack_w(w_hh0,  g_whh0p, HID, 128, 32, 1, gt, gs);
        pack_w(w_ih1,  g_wih1p, HID, 128, 32, 1, gt, gs);
        pack_w(w_hh1,  g_whh1p, HID, 128, 32, 1, gt, gs);
        pack_w(p1_w,   g_p1p,   HID, 32, 32, 0, gt, gs);
        for (int i = gt; i < 4 * 4 * 128 * 16; i += gs) {
            int k4 = i & 15, r = (i >> 4) & 127, mg = (i >> 11) & 3, c = i >> 13;
            float4 v = *(const float4*)(z + (size_t)(mg * 128 + r) * LATENT + c * 64 + k4 * 4);
            fp16 h[4];
            h[0] = __float2half_rn(v.x); h[1] = __float2half_rn(v.y);
            h[2] = __float2half_rn(v.z); h[3] = __float2half_rn(v.w);
            size_t d = (size_t)(c * 4 + mg) * ABLK + (size_t)r * LDA + k4 * 4;
            *(uint2*)(g_zp + d) = *(uint2*)h;
        }
        // p2 transposed quads: g_p2q[kq*128 + o] = p2_w[o][4kq..4kq+3]
        for (int i = gt; i < 256 * 128; i += gs) {
            int o = i & 127, kq = i >> 7;
            g_p2q[i] = *(const float4*)(p2_w + (size_t)o * HID + kq * 4);
        }
        for (int i = gt; i < 2 * 4 * ABLK; i += gs) {
            g_xp[i] = __float2half_rn(0.f);
        }
    }
    gridbar(epoch);

    // ---- S1: u = z @ lin1_w^T + lin1_b  (512 x 2048): 128 tiles of 128x64
    {
        int mg = bid >> 5, nt = bid & 31;
        CFrag acc[2][2];
        #pragma unroll
        for (int i = 0; i < 2; i++) { wmma::fill_fragment(acc[i][0], 0.f); wmma::fill_fragment(acc[i][1], 0.f); }
        Seg sg[1] = {{g_zp + (size_t)mg * ABLK,
                      g_lin1p + (size_t)nt * 4 * 4608,
                      4, 4 * ABLK, 4608}};
        gemm_pk<2>(acc, P, pbase, sg, 1, pp);
        store_epi<2>(acc, P, lin1_b, g_u, 2 * HID, mg << 7, nt << 6);
    }
    gridbar(epoch);

    // ---- S2: LayerNorm(2048) + gelu -> h0/c0 (both cells), 2 rows per pass
    {
        float* pf = (float*)(P + 1024);
        const int g = tid >> 7, lt = tid & 127, w4 = (tid >> 5) & 3;
        for (int grp = bid; grp < 128; grp += nb) {
            for (int pass = 0; pass < 2; pass++) {
                int row = (grp << 2) + pass * 2 + g;
                const float* urow = g_u + (size_t)row * 2 * HID;
                float ls = 0.f, lq = 0.f;
                #pragma unroll
                for (int u = 0; u < 16; u++) {
                    float v = __ldcg(urow + u * 128 + lt);
                    pf[g * 2048 + u * 128 + lt] = v;
                    ls += v; lq += v * v;
                }
                #pragma unroll
                for (int o = 16; o > 0; o >>= 1) {
                    ls += __shfl_down_sync(0xffffffffu, ls, o);
                    lq += __shfl_down_sync(0xffffffffu, lq, o);
                }
                if (lane == 0) { redA[g * 4 + w4] = ls; redB[g * 4 + w4] = lq; }
                __syncthreads();
                float S = redA[g * 4] + redA[g * 4 + 1] + redA[g * 4 + 2] + redA[g * 4 + 3];
                float Q = redB[g * 4] + redB[g * 4 + 1] + redB[g * 4 + 2] + redB[g * 4 + 3];
                float mu = S * (1.f / 2048.f);
                float rstd = rsqrtf(Q * (1.f / 2048.f) - mu * mu + 1e-5f);
                #pragma unroll
                for (int u = 0; u < 16; u++) {
                    int i = u * 128 + lt;
                    float v = (pf[g * 2048 + i] - mu) * rstd * __ldg(ln1_w + i) + __ldg(ln1_b + i);
                    float ge = v * normcdff(v);
                    if (i < HID) {
                        fp16 hv = __float2half_rn(ge);
                        size_t off = pk_off(row, i);
                        g_h1p[0][off] = hv;
                        g_h2p[0][off] = hv;
                    } else {
                        g_c1[0][(size_t)row * HID + i - HID] = ge;
                        g_c2[0][(size_t)row * HID + i - HID] = ge;
                    }
                }
                __syncthreads();
            }
        }
    }
    gridbar(epoch);

    // ---- main sequential loop
    for (int s = 0; s < SEQL; s++) {
        const int pi = s & 1, po = pi ^ 1;
        const int mg = (bid >> 5) & 3, ntl = bid & 31;

        // P1: (h1,c1) = lstm0(x, h1, c1) : K = 128 + 1024 (18 chunks streamed)
        {
            CFrag acc[2][4];
            #pragma unroll
            for (int i = 0; i < 2; i++)
                #pragma unroll
                for (int j = 0; j < 4; j++) wmma::fill_fragment(acc[i][j], 0.f);
            Seg sg[2] = {
                {g_xp + (size_t)mg * ABLK,
                 g_wih0p + (size_t)ntl * 2 * 9216,
                 2, 4 * ABLK, 9216},
                {g_h1p[pi] + (size_t)mg * ABLK,
                 g_whh0p + (size_t)ntl * 16 * 9216,
                 16, 4 * ABLK, 9216}};
            gemm_pk<4>(acc, P, pbase, sg, 2, pp);
            lstm_epi(acc, P, b0, g_c1[pi], g_c1[po], g_h1p[po], mg << 7, ntl << 5);
        }
        gridbar(epoch);

        // P2: (h2,c2) = lstm1(h1_new, h2, c2) : K = 1024 + 1024 (32 chunks)
        {
            CFrag acc[2][4];
            #pragma unroll
            for (int i = 0; i < 2; i++)
                #pragma unroll
                for (int j = 0; j < 4; j++) wmma::fill_fragment(acc[i][j], 0.f);
            Seg sg[2] = {
                {g_h1p[po] + (size_t)mg * ABLK,
                 g_wih1p + (size_t)ntl * 16 * 9216,
                 16, 4 * ABLK, 9216},
                {g_h2p[pi] + (size_t)mg * ABLK,
                 g_whh1p + (size_t)ntl * 16 * 9216,
                 16, 4 * ABLK, 9216}};
            gemm_pk<4>(acc, P, pbase, sg, 2, pp);
            lstm_epi(acc, P, b1, g_c2[pi], g_c2[po], g_h2p[po], mg << 7, ntl << 5);
        }
        gridbar(epoch);

        // P3: t = h2_new @ p1_w^T + p1_b : 128 tiles of 128x32 (all blocks active)
        {
            CFrag acc[2][1];
            wmma::fill_fragment(acc[0][0], 0.f);
            wmma::fill_fragment(acc[1][0], 0.f);
            Seg sg[1] = {{g_h2p[po] + (size_t)mg * ABLK,
                          g_p1p + (size_t)ntl * 16 * 2304,
                          16, 4 * ABLK, 2304}};
            gemm_pk<1>(acc, P, pbase, sg, 1, pp);
            store_epi<1>(acc, P, p1_b, g_t, HID, mg << 7, ntl << 5);
        }
        gridbar(epoch);

        // P4: LayerNorm + gelu (4 rows, 2 passes) then coalesced GEMV via g_p2q
        {
            float* pf = (float*)(P + 1024);        // [4][1024] gelu vals + [8][128] partials
            float* psum = pf + 4096;
            const int g = tid >> 7, lt = tid & 127, w4 = (tid >> 5) & 3;
            for (int grp = bid; grp < 128; grp += nb) {
                for (int pass = 0; pass < 2; pass++) {
                    int rr = pass * 2 + g;
                    int row = (grp << 2) + rr;
                    const float* trow = g_t + (size_t)row * HID;
                    float vb[8]; float ls = 0.f, lq = 0.f;
                    #pragma unroll
                    for (int u = 0; u < 8; u++) {
                        float v = __ldcg(trow + u * 128 + lt);
                        vb[u] = v; ls += v; lq += v * v;
                    }
                    #pragma unroll
                    for (int o = 16; o > 0; o >>= 1) {
                        ls += __shfl_down_sync(0xffffffffu, ls, o);
                        lq += __shfl_down_sync(0xffffffffu, lq, o);
                    }
                    if (lane == 0) { redA[g * 4 + w4] = ls; redB[g * 4 + w4] = lq; }
                    __syncthreads();
                    float S = redA[g * 4] + redA[g * 4 + 1] + redA[g * 4 + 2] + redA[g * 4 + 3];
                    float Q = redB[g * 4] + redB[g * 4 + 1] + redB[g * 4 + 2] + redB[g * 4 + 3];
                    float mu = S * (1.f / 1024.f);
                    float rstd = rsqrtf(Q * (1.f / 1024.f) - mu * mu + 1e-5f);
                    #pragma unroll
                    for (int u = 0; u < 8; u++) {
                        int i = u * 128 + lt;
                        float v = (vb[u] - mu) * rstd * __ldg(pln_w + i) + __ldg(pln_b + i);
                        pf[rr * 1024 + i] = v * normcdff(v);
                    }
                    __syncthreads();
                }
                // GEMV: thread (o=lt, half=g) does K-half 512 for all 4 rows, coalesced loads
                {
                    float a0 = 0.f, a1 = 0.f, a2 = 0.f, a3 = 0.f;
                    const int kq0 = g * 128;
                    #pragma unroll 2
                    for (int kq = 0; kq < 128; kq++) {
                        float4 wv = g_p2q[(size_t)(kq0 + kq) * 128 + lt];
                        float4 g0 = *(const float4*)(pf + 0 * 1024 + (kq0 + kq) * 4);
                        float4 g1 = *(const float4*)(pf + 1 * 1024 + (kq0 + kq) * 4);
                        float4 g2 = *(const float4*)(pf + 2 * 1024 + (kq0 + kq) * 4);
                        float4 g3 = *(const float4*)(pf + 3 * 1024 + (kq0 + kq) * 4);
                        a0 += g0.x * wv.x + g0.y * wv.y + g0.z * wv.z + g0.w * wv.w;
                        a1 += g1.x * wv.x + g1.y * wv.y + g1.z * wv.z + g1.w * wv.w;
                        a2 += g2.x * wv.x + g2.y * wv.y + g2.z * wv.z + g2.w * wv.w;
                        a3 += g3.x * wv.x + g3.y * wv.y + g3.z * wv.z + g3.w * wv.w;
                    }
                    psum[(0 * 2 + g) * 128 + lt] = a0;
                    psum[(1 * 2 + g) * 128 + lt] = a1;
                    psum[(2 * 2 + g) * 128 + lt] = a2;
                    psum[(3 * 2 + g) * 128 + lt] = a3;
                }
                __syncthreads();
                for (int idx = tid; idx < 512; idx += NTHREADS) {
                    int r = idx >> 7, o = idx & 127;
                    int row = (grp << 2) + r;
                    float y = psum[(r * 2) * 128 + o] + psum[(r * 2 + 1) * 128 + o] + __ldg(p2_b + o);
                    g_xp[pk_off(row, o)] = __float2half_rn(y);
                    out[(size_t)row * SEQL * NOUT + s * NOUT + o] = y;
                }
                __syncthreads();
            }
        }
        gridbar(epoch);
    }
}

// ---------------- launch ----------------
extern "C" void kernel_launch(void* const* d_in, const int* in_sizes, int n_in,
                              void* d_out, int out_size) {
    (void)in_sizes; (void)n_in; (void)out_size;
    cudaFuncSetAttribute(dec_kernel, cudaFuncAttributeMaxDynamicSharedMemorySize, SMEM_BYTES);

    const float* z      = (const float*)d_in[0];
    const float* lin1_w = (const float*)d_in[1];
    const float* lin1_b = (const float*)d_in[2];
    const float* ln1_w  = (const float*)d_in[3];
    const float* ln1_b  = (const float*)d_in[4];
    const float* w_ih0  = (const float*)d_in[5];
    const float* w_hh0  = (const float*)d_in[6];
    const float* b0     = (const float*)d_in[7];
    const float* w_ih1  = (const float*)d_in[8];
    const float* w_hh1  = (const float*)d_in[9];
    const float* b1     = (const float*)d_in[10];
    const float* p1_w   = (const float*)d_in[11];
    const float* p1_b   = (const float*)d_in[12];
    const float* pln_w  = (const float*)d_in[13];
    const float* pln_b  = (const float*)d_in[14];
    const float* p2_w   = (const float*)d_in[15];
    const float* p2_b   = (const float*)d_in[16];

    dec_kernel<<<NBLOCKS, NTHREADS, SMEM_BYTES>>>(
        z, lin1_w, lin1_b, ln1_w, ln1_b,
        w_ih0, w_hh0, b0, w_ih1, w_hh1, b1,
        p1_w, p1_b, pln_w, pln_b, p2_w, p2_b,
        (float*)d_out);
}